// round 1
// baseline (speedup 1.0000x reference)
#include <cuda_runtime.h>
#include <cstdint>

#define EPSV 1e-5f

constexpr int Bsz = 16, D = 384, L = 1024, S = 64, C3 = 192, E = 8, HID = 768;
constexpr int NTOK = Bsz * L;                    // 16384
constexpr int MAXSLOTS = 2 * NTOK + E * 128;     // 33792 (expert-padded)

// ------------------------- scratch (static device globals) -------------------------
__device__ float g_x1[Bsz * D * L];
__device__ float g_xn[Bsz * D * L];
__device__ float g_bcdt[Bsz * C3 * L];
__device__ float g_bcdt2[Bsz * C3 * L];
__device__ float g_ab[Bsz * S * L];
__device__ float g_h[Bsz * D * S];
__device__ float g_x2[Bsz * D * L];
__device__ float g_xT[NTOK * D];
__device__ float g_he[(size_t)MAXSLOTS * HID];
__device__ int   g_cnt[E];
__device__ int   g_cnt2[E];
__device__ int   g_off[E + 1];
__device__ int   g_topk_idx[NTOK * 2];
__device__ float g_topk_w[NTOK * 2];
__device__ int   g_perm[MAXSLOTS];
__device__ float g_wgt[MAXSLOTS];

// ------------------------- init (zero counters / pads / split-K acc) ---------------
__global__ void k_init() {
    int i = blockIdx.x * 256 + threadIdx.x;
    if (i < MAXSLOTS) { g_wgt[i] = 0.f; g_perm[i] = 0; }
    if (i < E) g_cnt[i] = 0;
    if (i < Bsz * D * S) g_h[i] = 0.f;
}

// ------------------------- depthwise 3x3 (+optional BN, +optional residual) --------
__global__ void k_dwconv(const float* __restrict__ in, const float* __restrict__ w9,
                         const float* __restrict__ g, const float* __restrict__ bb,
                         const float* __restrict__ m, const float* __restrict__ v,
                         float* __restrict__ out, int C, int residual) {
    __shared__ float s[34 * 34];
    int b = blockIdx.x / C, c = blockIdx.x % C;
    const float* ip = in + (size_t)(b * C + c) * L;
    int tid = threadIdx.x;
    for (int idx = tid; idx < 34 * 34; idx += 256) {
        int r = idx / 34 - 1, cc = idx % 34 - 1;
        s[idx] = (r >= 0 && r < 32 && cc >= 0 && cc < 32) ? ip[r * 32 + cc] : 0.f;
    }
    __syncthreads();
    float w[9];
#pragma unroll
    for (int i = 0; i < 9; i++) w[i] = w9[c * 9 + i];
    float sc = 1.f, sh = 0.f;
    if (g) { sc = g[c] * rsqrtf(v[c] + EPSV); sh = bb[c] - m[c] * sc; }
    float* op = out + (size_t)(b * C + c) * L;
    for (int idx = tid; idx < 1024; idx += 256) {
        int r = idx >> 5, cc = idx & 31;
        float acc = 0.f;
#pragma unroll
        for (int kr = 0; kr < 3; kr++)
#pragma unroll
            for (int kc = 0; kc < 3; kc++)
                acc += w[kr * 3 + kc] * s[(r + kr) * 34 + cc + kc];
        float val = sc * acc + sh;
        if (residual) val += s[(r + 1) * 34 + cc + 1];
        op[idx] = val;
    }
}

// ------------------------- LayerNorm over channel dim ------------------------------
__global__ void k_ln(const float* __restrict__ lnw, const float* __restrict__ lnb) {
    int gi = blockIdx.x * 256 + threadIdx.x;        // one thread per (b,l)
    int b = gi >> 10, l = gi & 1023;
    const float* p = g_x1 + (size_t)b * D * L + l;
    float sum = 0.f, sq = 0.f;
    for (int d = 0; d < D; d++) { float x = p[(size_t)d * L]; sum += x; sq += x * x; }
    float mu = sum * (1.f / D);
    float var = sq * (1.f / D) - mu * mu;
    float inv = rsqrtf(var + EPSV);
    float* o = g_xn + (size_t)b * D * L + l;
    for (int d = 0; d < D; d++)
        o[(size_t)d * L] = (p[(size_t)d * L] - mu) * inv * lnw[d] + lnb[d];
}

// ------------------------- bcdt = bcdt_w @ xn_b : (192x384)x(384x1024) -------------
__global__ void k_gemm_bcdt(const float* __restrict__ Wm) {
    __shared__ float As[8][68], Bs[8][132];
    int b = blockIdx.x, m0 = blockIdx.y * 64, n0 = blockIdx.z * 128;
    int tid = threadIdx.x, tx = tid & 15, ty = tid >> 4;
    const float* Bp = g_xn + (size_t)b * D * L;
    float acc[4][8] = {};
    for (int k0 = 0; k0 < 384; k0 += 8) {
        for (int p = 0; p < 2; p++) {
            int idx = tid + p * 256; int mm = idx >> 3, kk = idx & 7;
            As[kk][mm] = Wm[(size_t)(m0 + mm) * 384 + k0 + kk];
        }
        for (int p = 0; p < 4; p++) {
            int idx = tid + p * 256; int kk = idx >> 7, nn = idx & 127;
            Bs[kk][nn] = Bp[(size_t)(k0 + kk) * L + n0 + nn];
        }
        __syncthreads();
#pragma unroll
        for (int k = 0; k < 8; k++) {
            float a[4], bv[8];
#pragma unroll
            for (int i = 0; i < 4; i++) a[i] = As[k][ty + i * 16];
#pragma unroll
            for (int j = 0; j < 8; j++) bv[j] = Bs[k][tx + j * 16];
#pragma unroll
            for (int i = 0; i < 4; i++)
#pragma unroll
                for (int j = 0; j < 8; j++) acc[i][j] += a[i] * bv[j];
        }
        __syncthreads();
    }
    float* Cp = g_bcdt + (size_t)b * C3 * L;
    for (int i = 0; i < 4; i++)
        for (int j = 0; j < 8; j++)
            Cp[(size_t)(m0 + ty + i * 16) * L + n0 + tx + j * 16] = acc[i][j];
}

// ------------------------- softmax over L (A[s] shift cancels) + *Bm ---------------
__global__ void k_softmax() {
    int b = blockIdx.x >> 6, s = blockIdx.x & 63;
    const float* dt = g_bcdt2 + ((size_t)b * C3 + 2 * S + s) * L;
    const float* Bm = g_bcdt2 + ((size_t)b * C3 + s) * L;
    float* ab = g_ab + ((size_t)b * S + s) * L;
    int tid = threadIdx.x;
    __shared__ float red[256];
    float vals[4]; float mx = -1e30f;
#pragma unroll
    for (int i = 0; i < 4; i++) { vals[i] = dt[tid + i * 256]; mx = fmaxf(mx, vals[i]); }
    red[tid] = mx; __syncthreads();
    for (int o = 128; o > 0; o >>= 1) { if (tid < o) red[tid] = fmaxf(red[tid], red[tid + o]); __syncthreads(); }
    mx = red[0]; __syncthreads();
    float e[4]; float sum = 0.f;
#pragma unroll
    for (int i = 0; i < 4; i++) { e[i] = __expf(vals[i] - mx); sum += e[i]; }
    red[tid] = sum; __syncthreads();
    for (int o = 128; o > 0; o >>= 1) { if (tid < o) red[tid] += red[tid + o]; __syncthreads(); }
    float inv = 1.f / red[0];
#pragma unroll
    for (int i = 0; i < 4; i++) ab[tid + i * 256] = e[i] * inv * Bm[tid + i * 256];
}

// ------------------------- h[b,d,s] = sum_l xn * ab  (split-K, atomic) -------------
__global__ void k_gemm_h() {
    __shared__ float As[8][68], Bs[8][68];
    int b = blockIdx.x, m0 = blockIdx.y * 64, kc = blockIdx.z;
    int tid = threadIdx.x, tx = tid & 15, ty = tid >> 4;
    const float* Ap = g_xn + (size_t)b * D * L;
    const float* Bp = g_ab + (size_t)b * S * L;
    float acc[4][4] = {};
    for (int k0 = kc * 256; k0 < kc * 256 + 256; k0 += 8) {
        for (int p = 0; p < 2; p++) {
            int idx = tid + p * 256; int mm = idx >> 3, kk = idx & 7;
            As[kk][mm] = Ap[(size_t)(m0 + mm) * L + k0 + kk];
        }
        for (int p = 0; p < 2; p++) {
            int idx = tid + p * 256; int nn = idx >> 3, kk = idx & 7;
            Bs[kk][nn] = Bp[(size_t)nn * L + k0 + kk];
        }
        __syncthreads();
#pragma unroll
        for (int k = 0; k < 8; k++) {
            float a[4], bv[4];
#pragma unroll
            for (int i = 0; i < 4; i++) a[i] = As[k][ty + i * 16];
#pragma unroll
            for (int j = 0; j < 4; j++) bv[j] = Bs[k][tx + j * 16];
#pragma unroll
            for (int i = 0; i < 4; i++)
#pragma unroll
                for (int j = 0; j < 4; j++) acc[i][j] += a[i] * bv[j];
        }
        __syncthreads();
    }
    float* Cp = g_h + (size_t)b * D * S;
    for (int i = 0; i < 4; i++)
        for (int j = 0; j < 4; j++)
            atomicAdd(&Cp[(size_t)(m0 + ty + i * 16) * S + tx + j * 16], acc[i][j]);
}

// ------------------------- h2 = silu(hproj @ h) -> out_h ---------------------------
__global__ void k_hproj(const float* __restrict__ Wp, float* __restrict__ outh) {
    __shared__ float As[8][68], Bs[8][68];
    int b = blockIdx.x, m0 = blockIdx.y * 64;
    int tid = threadIdx.x, tx = tid & 15, ty = tid >> 4;
    const float* Bp = g_h + (size_t)b * D * S;
    float acc[4][4] = {};
    for (int k0 = 0; k0 < 384; k0 += 8) {
        for (int p = 0; p < 2; p++) {
            int idx = tid + p * 256; int mm = idx >> 3, kk = idx & 7;
            As[kk][mm] = Wp[(size_t)(m0 + mm) * 384 + k0 + kk];
        }
        for (int p = 0; p < 2; p++) {
            int idx = tid + p * 256; int kk = idx >> 6, nn = idx & 63;
            Bs[kk][nn] = Bp[(size_t)(k0 + kk) * S + nn];
        }
        __syncthreads();
#pragma unroll
        for (int k = 0; k < 8; k++) {
            float a[4], bv[4];
#pragma unroll
            for (int i = 0; i < 4; i++) a[i] = As[k][ty + i * 16];
#pragma unroll
            for (int j = 0; j < 4; j++) bv[j] = Bs[k][tx + j * 16];
#pragma unroll
            for (int i = 0; i < 4; i++)
#pragma unroll
                for (int j = 0; j < 4; j++) acc[i][j] += a[i] * bv[j];
        }
        __syncthreads();
    }
    float* Cp = outh + (size_t)b * D * S;
    for (int i = 0; i < 4; i++)
        for (int j = 0; j < 4; j++) {
            float x = acc[i][j];
            Cp[(size_t)(m0 + ty + i * 16) * S + tx + j * 16] = x / (1.f + __expf(-x));
        }
}

// ------------------------- x2 = x1 + h2 @ Cm ---------------------------------------
__global__ void k_gemm_y(const float* __restrict__ outh) {
    __shared__ float As[8][68], Bs[8][132];
    int b = blockIdx.x, m0 = blockIdx.y * 64, n0 = blockIdx.z * 128;
    int tid = threadIdx.x, tx = tid & 15, ty = tid >> 4;
    const float* Ap = outh + (size_t)b * D * S;
    const float* Bp = g_bcdt2 + ((size_t)b * C3 + S) * L;   // Cm block
    float acc[4][8] = {};
    for (int k0 = 0; k0 < 64; k0 += 8) {
        for (int p = 0; p < 2; p++) {
            int idx = tid + p * 256; int mm = idx >> 3, kk = idx & 7;
            As[kk][mm] = Ap[(size_t)(m0 + mm) * S + k0 + kk];
        }
        for (int p = 0; p < 4; p++) {
            int idx = tid + p * 256; int kk = idx >> 7, nn = idx & 127;
            Bs[kk][nn] = Bp[(size_t)(k0 + kk) * L + n0 + nn];
        }
        __syncthreads();
#pragma unroll
        for (int k = 0; k < 8; k++) {
            float a[4], bv[8];
#pragma unroll
            for (int i = 0; i < 4; i++) a[i] = As[k][ty + i * 16];
#pragma unroll
            for (int j = 0; j < 8; j++) bv[j] = Bs[k][tx + j * 16];
#pragma unroll
            for (int i = 0; i < 4; i++)
#pragma unroll
                for (int j = 0; j < 8; j++) acc[i][j] += a[i] * bv[j];
        }
        __syncthreads();
    }
    for (int i = 0; i < 4; i++)
        for (int j = 0; j < 8; j++) {
            size_t o = (size_t)b * D * L + (size_t)(m0 + ty + i * 16) * L + n0 + tx + j * 16;
            g_x2[o] = g_x1[o] + acc[i][j];
        }
}

// ------------------------- NCHW -> token-major transpose ---------------------------
__global__ void k_transpose(const float* __restrict__ xin) {
    __shared__ float s[32][33];
    int b = blockIdx.x, d0 = blockIdx.y * 32, l0 = blockIdx.z * 32;
    int c = threadIdx.x & 31, r0 = threadIdx.x >> 5;
    for (int i = 0; i < 32; i += 8)
        s[r0 + i][c] = xin[((size_t)b * D + d0 + r0 + i) * L + l0 + c];
    __syncthreads();
    for (int i = 0; i < 32; i += 8)
        g_xT[((size_t)b * L + l0 + r0 + i) * D + d0 + c] = s[c][r0 + i];
}

// ------------------------- router: logits, top-2, softmax --------------------------
__global__ void k_route(const float* __restrict__ gw, const float* __restrict__ gb) {
    __shared__ float sg[E * D];
    int tid = threadIdx.x;
    for (int i = tid; i < E * D; i += 256) sg[i] = gw[i];
    __syncthreads();
    int n = blockIdx.x * 256 + tid;
    const float* t = g_xT + (size_t)n * D;
    float lg[E];
#pragma unroll
    for (int e = 0; e < E; e++) lg[e] = gb[e];
    for (int d = 0; d < D; d++) {
        float x = t[d];
#pragma unroll
        for (int e = 0; e < E; e++) lg[e] += sg[e * D + d] * x;
    }
    int i0 = 0; float v0 = lg[0];
#pragma unroll
    for (int e = 1; e < E; e++) if (lg[e] > v0) { v0 = lg[e]; i0 = e; }
    int i1 = -1; float v1 = -1e30f;
#pragma unroll
    for (int e = 0; e < E; e++) if (e != i0 && lg[e] > v1) { v1 = lg[e]; i1 = e; }
    float p0 = 1.f / (1.f + __expf(v1 - v0));
    g_topk_idx[n * 2] = i0; g_topk_idx[n * 2 + 1] = i1;
    g_topk_w[n * 2] = p0;   g_topk_w[n * 2 + 1] = 1.f - p0;
    atomicAdd(&g_cnt[i0], 1); atomicAdd(&g_cnt[i1], 1);
}

__global__ void k_offsets() {
    int off = 0;
    for (int e = 0; e < E; e++) {
        g_off[e] = off;
        off += (g_cnt[e] + 127) & ~127;
        g_cnt2[e] = 0;
    }
    g_off[E] = off;
}

__global__ void k_scatter() {
    int n = blockIdx.x * 256 + threadIdx.x;
#pragma unroll
    for (int k = 0; k < 2; k++) {
        int e = g_topk_idx[n * 2 + k];
        int pos = g_off[e] + atomicAdd(&g_cnt2[e], 1);
        g_perm[pos] = n;
        g_wgt[pos] = g_topk_w[n * 2 + k];
    }
}

// ------------------------- MoE GEMM1: he = silu(t@w1+b1)  then *= (t@w3+b3) --------
__global__ void k_moe1(const float* __restrict__ Wt, const float* __restrict__ bias, int mode) {
    int e = blockIdx.x;
    int cnt = g_cnt[e];
    int m0 = blockIdx.y * 128;
    if (m0 >= cnt) return;
    int base = g_off[e];
    int n0 = blockIdx.z * 128;
    __shared__ float As[8][132], Bs[8][132];
    __shared__ int sperm[128];
    int tid = threadIdx.x, tx = tid & 15, ty = tid >> 4;
    if (tid < 128) sperm[tid] = g_perm[base + m0 + tid];
    __syncthreads();
    const float* Wp = Wt + (size_t)e * HID * D;
    float acc[8][8] = {};
    for (int k0 = 0; k0 < D; k0 += 8) {
        for (int p = 0; p < 4; p++) {
            int idx = tid + p * 256; int mm = idx >> 3, kk = idx & 7;
            As[kk][mm] = g_xT[(size_t)sperm[mm] * D + k0 + kk];
        }
        for (int p = 0; p < 4; p++) {
            int idx = tid + p * 256; int nn = idx >> 3, kk = idx & 7;
            Bs[kk][nn] = Wp[(size_t)(n0 + nn) * D + k0 + kk];
        }
        __syncthreads();
#pragma unroll
        for (int k = 0; k < 8; k++) {
            float a[8], bv[8];
#pragma unroll
            for (int i = 0; i < 8; i++) a[i] = As[k][ty + i * 16];
#pragma unroll
            for (int j = 0; j < 8; j++) bv[j] = Bs[k][tx + j * 16];
#pragma unroll
            for (int i = 0; i < 8; i++)
#pragma unroll
                for (int j = 0; j < 8; j++) acc[i][j] += a[i] * bv[j];
        }
        __syncthreads();
    }
    for (int i = 0; i < 8; i++) {
        int row = m0 + ty + i * 16;
        size_t hbase = (size_t)(base + row) * HID + n0;
        for (int j = 0; j < 8; j++) {
            int col = tx + j * 16;
            float x = acc[i][j] + bias[e * HID + n0 + col];
            if (mode == 0) g_he[hbase + col] = x / (1.f + __expf(-x));
            else           g_he[hbase + col] *= x;
        }
    }
}

// ------------------------- MoE GEMM2: out += (he@w2+b2)*w  (scatter) ---------------
__global__ void k_moe2(const float* __restrict__ W2, const float* __restrict__ b2v,
                       float* __restrict__ outx) {
    int e = blockIdx.x;
    int cnt = g_cnt[e];
    int m0 = blockIdx.y * 128;
    if (m0 >= cnt) return;
    int base = g_off[e];
    int n0 = blockIdx.z * 128;
    __shared__ float As[8][132], Bs[8][132];
    int tid = threadIdx.x, tx = tid & 15, ty = tid >> 4;
    const float* Wp = W2 + (size_t)e * D * HID;
    float acc[8][8] = {};
    for (int k0 = 0; k0 < HID; k0 += 8) {
        for (int p = 0; p < 4; p++) {
            int idx = tid + p * 256; int mm = idx >> 3, kk = idx & 7;
            As[kk][mm] = g_he[(size_t)(base + m0 + mm) * HID + k0 + kk];
        }
        for (int p = 0; p < 4; p++) {
            int idx = tid + p * 256; int nn = idx >> 3, kk = idx & 7;
            Bs[kk][nn] = Wp[(size_t)(n0 + nn) * HID + k0 + kk];
        }
        __syncthreads();
#pragma unroll
        for (int k = 0; k < 8; k++) {
            float a[8], bv[8];
#pragma unroll
            for (int i = 0; i < 8; i++) a[i] = As[k][ty + i * 16];
#pragma unroll
            for (int j = 0; j < 8; j++) bv[j] = Bs[k][tx + j * 16];
#pragma unroll
            for (int i = 0; i < 8; i++)
#pragma unroll
                for (int j = 0; j < 8; j++) acc[i][j] += a[i] * bv[j];
        }
        __syncthreads();
    }
    for (int i = 0; i < 8; i++) {
        int row = m0 + ty + i * 16;
        float w = g_wgt[base + row];
        if (w != 0.f) {
            int n = g_perm[base + row];
            int b = n >> 10, l = n & 1023;
            for (int j = 0; j < 8; j++) {
                int col = n0 + tx + j * 16;
                atomicAdd(&outx[((size_t)b * D + col) * L + l],
                          (acc[i][j] + b2v[e * D + col]) * w);
            }
        }
    }
}

// ------------------------- launch ---------------------------------------------------
extern "C" void kernel_launch(void* const* d_in, const int* in_sizes, int n_in,
                              void* d_out, int out_size) {
    const float* x      = (const float*)d_in[0];
    const float* dw1_w  = (const float*)d_in[1];
    const float* bn1_g  = (const float*)d_in[2];
    const float* bn1_b  = (const float*)d_in[3];
    const float* bn1_m  = (const float*)d_in[4];
    const float* bn1_v  = (const float*)d_in[5];
    const float* dw2_w  = (const float*)d_in[6];
    const float* bn2_g  = (const float*)d_in[7];
    const float* bn2_b  = (const float*)d_in[8];
    const float* bn2_m  = (const float*)d_in[9];
    const float* bn2_v  = (const float*)d_in[10];
    const float* ln_w   = (const float*)d_in[11];
    const float* ln_b   = (const float*)d_in[12];
    const float* bcdt_w = (const float*)d_in[13];
    const float* dws_w  = (const float*)d_in[14];
    const float* hproj_w= (const float*)d_in[15];
    // d_in[16] = A (cancels inside softmax over L)
    const float* gate_w = (const float*)d_in[17];
    const float* gate_b = (const float*)d_in[18];
    const float* w1     = (const float*)d_in[19];
    const float* b1     = (const float*)d_in[20];
    const float* w2     = (const float*)d_in[21];
    const float* b2     = (const float*)d_in[22];
    const float* w3     = (const float*)d_in[23];
    const float* b3     = (const float*)d_in[24];

    float* out_x = (float*)d_out;
    float* out_h = out_x + (size_t)Bsz * D * L;

    float* px1;    cudaGetSymbolAddress((void**)&px1, g_x1);
    float* pbcdt;  cudaGetSymbolAddress((void**)&pbcdt, g_bcdt);
    float* pbcdt2; cudaGetSymbolAddress((void**)&pbcdt2, g_bcdt2);
    float* px2;    cudaGetSymbolAddress((void**)&px2, g_x2);

    k_init<<<1536, 256>>>();

    // x1 = x + bn1(dw1(x))
    k_dwconv<<<Bsz * D, 256>>>(x, dw1_w, bn1_g, bn1_b, bn1_m, bn1_v, px1, D, 1);
    // xn = LN(x1)
    k_ln<<<NTOK / 256, 256>>>(ln_w, ln_b);
    // bcdt
    k_gemm_bcdt<<<dim3(Bsz, 3, 8), 256>>>(bcdt_w);
    k_dwconv<<<Bsz * C3, 256>>>(pbcdt, dws_w, nullptr, nullptr, nullptr, nullptr, pbcdt2, C3, 0);
    k_softmax<<<Bsz * S, 256>>>();
    // h = xn @ (Am*Bm)^T  (split-K=4 with atomics)
    k_gemm_h<<<dim3(Bsz, 6, 4), 256>>>();
    // h2 = silu(hproj @ h) -> second output
    k_hproj<<<dim3(Bsz, 6, 1), 256>>>(hproj_w, out_h);
    // x2 = x1 + h2 @ Cm
    k_gemm_y<<<dim3(Bsz, 6, 8), 256>>>(out_h);
    // x3 = x2 + bn2(dw2(x2)) -> first output (MoE adds on top)
    k_dwconv<<<Bsz * D, 256>>>(px2, dw2_w, bn2_g, bn2_b, bn2_m, bn2_v, out_x, D, 1);
    // tokens
    k_transpose<<<dim3(Bsz, 12, 32), 256>>>(out_x);
    // routing
    k_route<<<NTOK / 256, 256>>>(gate_w, gate_b);
    k_offsets<<<1, 1>>>();
    k_scatter<<<NTOK / 256, 256>>>();
    // MoE
    k_moe1<<<dim3(E, 128, 6), 256>>>(w1, b1, 0);
    k_moe1<<<dim3(E, 128, 6), 256>>>(w3, b3, 1);
    k_moe2<<<dim3(E, 128, 3), 256>>>(w2, b2, out_x);
}

// round 2
// speedup vs baseline: 1.4369x; 1.4369x over previous
#include <cuda_runtime.h>
#include <cstdint>

#define EPSV 1e-5f

constexpr int Bsz = 16, D = 384, L = 1024, S = 64, C3 = 192, E = 8, HID = 768;
constexpr int NTOK = Bsz * L;                    // 16384
constexpr int MAXSLOTS = 2 * NTOK + E * 128;     // 33792 (expert-padded)

// ------------------------- scratch (static device globals) -------------------------
__device__ float g_x1[Bsz * D * L];
__device__ float g_xn[Bsz * D * L];
__device__ float g_bcdt[Bsz * C3 * L];
__device__ float g_bcdt2[Bsz * C3 * L];
__device__ float g_ab[Bsz * S * L];
__device__ float g_h[Bsz * D * S];
__device__ float g_x2[Bsz * D * L];
__device__ float g_xT[NTOK * D];
__device__ float g_he[(size_t)MAXSLOTS * HID];
__device__ int   g_cnt[E];
__device__ int   g_cnt2[E];
__device__ int   g_off[E + 1];
__device__ int   g_topk_idx[NTOK * 2];
__device__ float g_topk_w[NTOK * 2];
__device__ int   g_perm[MAXSLOTS];
__device__ float g_wgt[MAXSLOTS];

// ------------------------- tf32 mma helpers ----------------------------------------
__device__ __forceinline__ uint32_t f2tf32(float x) {
    uint32_t r;
    asm("cvt.rna.tf32.f32 %0, %1;" : "=r"(r) : "f"(x));
    return r;
}
__device__ __forceinline__ void mma_tf32(float c[4], uint32_t a0, uint32_t a1,
                                         uint32_t a2, uint32_t a3,
                                         uint32_t b0, uint32_t b1) {
    asm volatile(
        "mma.sync.aligned.m16n8k8.row.col.f32.tf32.tf32.f32 "
        "{%0,%1,%2,%3}, {%4,%5,%6,%7}, {%8,%9}, {%0,%1,%2,%3};"
        : "+f"(c[0]), "+f"(c[1]), "+f"(c[2]), "+f"(c[3])
        : "r"(a0), "r"(a1), "r"(a2), "r"(a3), "r"(b0), "r"(b1));
}

// ------------------------- init (zero counters / pads / split-K acc) ---------------
__global__ void k_init() {
    int i = blockIdx.x * 256 + threadIdx.x;
    if (i < MAXSLOTS) { g_wgt[i] = 0.f; g_perm[i] = 0; }
    if (i < E) g_cnt[i] = 0;
    if (i < Bsz * D * S) g_h[i] = 0.f;
}

// ------------------------- depthwise 3x3 (+optional BN, +optional residual) --------
__global__ void k_dwconv(const float* __restrict__ in, const float* __restrict__ w9,
                         const float* __restrict__ g, const float* __restrict__ bb,
                         const float* __restrict__ m, const float* __restrict__ v,
                         float* __restrict__ out, int C, int residual) {
    __shared__ float s[34 * 34];
    int b = blockIdx.x / C, c = blockIdx.x % C;
    const float* ip = in + (size_t)(b * C + c) * L;
    int tid = threadIdx.x;
    for (int idx = tid; idx < 34 * 34; idx += 256) {
        int r = idx / 34 - 1, cc = idx % 34 - 1;
        s[idx] = (r >= 0 && r < 32 && cc >= 0 && cc < 32) ? ip[r * 32 + cc] : 0.f;
    }
    __syncthreads();
    float w[9];
#pragma unroll
    for (int i = 0; i < 9; i++) w[i] = w9[c * 9 + i];
    float sc = 1.f, sh = 0.f;
    if (g) { sc = g[c] * rsqrtf(v[c] + EPSV); sh = bb[c] - m[c] * sc; }
    float* op = out + (size_t)(b * C + c) * L;
    for (int idx = tid; idx < 1024; idx += 256) {
        int r = idx >> 5, cc = idx & 31;
        float acc = 0.f;
#pragma unroll
        for (int kr = 0; kr < 3; kr++)
#pragma unroll
            for (int kc = 0; kc < 3; kc++)
                acc += w[kr * 3 + kc] * s[(r + kr) * 34 + cc + kc];
        float val = sc * acc + sh;
        if (residual) val += s[(r + 1) * 34 + cc + 1];
        op[idx] = val;
    }
}

// ------------------------- LayerNorm over channel dim ------------------------------
__global__ void k_ln(const float* __restrict__ lnw, const float* __restrict__ lnb) {
    int gi = blockIdx.x * 256 + threadIdx.x;        // one thread per (b,l)
    int b = gi >> 10, l = gi & 1023;
    const float* p = g_x1 + (size_t)b * D * L + l;
    float sum = 0.f, sq = 0.f;
    for (int d = 0; d < D; d++) { float x = p[(size_t)d * L]; sum += x; sq += x * x; }
    float mu = sum * (1.f / D);
    float var = sq * (1.f / D) - mu * mu;
    float inv = rsqrtf(var + EPSV);
    float* o = g_xn + (size_t)b * D * L + l;
    for (int d = 0; d < D; d++)
        o[(size_t)d * L] = (p[(size_t)d * L] - mu) * inv * lnw[d] + lnb[d];
}

// ------------------------- bcdt = bcdt_w @ xn_b : (192x384)x(384x1024) -------------
__global__ void k_gemm_bcdt(const float* __restrict__ Wm) {
    __shared__ float As[8][68], Bs[8][132];
    int b = blockIdx.x, m0 = blockIdx.y * 64, n0 = blockIdx.z * 128;
    int tid = threadIdx.x, tx = tid & 15, ty = tid >> 4;
    const float* Bp = g_xn + (size_t)b * D * L;
    float acc[4][8] = {};
    for (int k0 = 0; k0 < 384; k0 += 8) {
        for (int p = 0; p < 2; p++) {
            int idx = tid + p * 256; int mm = idx >> 3, kk = idx & 7;
            As[kk][mm] = Wm[(size_t)(m0 + mm) * 384 + k0 + kk];
        }
        for (int p = 0; p < 4; p++) {
            int idx = tid + p * 256; int kk = idx >> 7, nn = idx & 127;
            Bs[kk][nn] = Bp[(size_t)(k0 + kk) * L + n0 + nn];
        }
        __syncthreads();
#pragma unroll
        for (int k = 0; k < 8; k++) {
            float a[4], bv[8];
#pragma unroll
            for (int i = 0; i < 4; i++) a[i] = As[k][ty + i * 16];
#pragma unroll
            for (int j = 0; j < 8; j++) bv[j] = Bs[k][tx + j * 16];
#pragma unroll
            for (int i = 0; i < 4; i++)
#pragma unroll
                for (int j = 0; j < 8; j++) acc[i][j] += a[i] * bv[j];
        }
        __syncthreads();
    }
    float* Cp = g_bcdt + (size_t)b * C3 * L;
    for (int i = 0; i < 4; i++)
        for (int j = 0; j < 8; j++)
            Cp[(size_t)(m0 + ty + i * 16) * L + n0 + tx + j * 16] = acc[i][j];
}

// ------------------------- softmax over L (A[s] shift cancels) + *Bm ---------------
__global__ void k_softmax() {
    int b = blockIdx.x >> 6, s = blockIdx.x & 63;
    const float* dt = g_bcdt2 + ((size_t)b * C3 + 2 * S + s) * L;
    const float* Bm = g_bcdt2 + ((size_t)b * C3 + s) * L;
    float* ab = g_ab + ((size_t)b * S + s) * L;
    int tid = threadIdx.x;
    __shared__ float red[256];
    float vals[4]; float mx = -1e30f;
#pragma unroll
    for (int i = 0; i < 4; i++) { vals[i] = dt[tid + i * 256]; mx = fmaxf(mx, vals[i]); }
    red[tid] = mx; __syncthreads();
    for (int o = 128; o > 0; o >>= 1) { if (tid < o) red[tid] = fmaxf(red[tid], red[tid + o]); __syncthreads(); }
    mx = red[0]; __syncthreads();
    float e[4]; float sum = 0.f;
#pragma unroll
    for (int i = 0; i < 4; i++) { e[i] = __expf(vals[i] - mx); sum += e[i]; }
    red[tid] = sum; __syncthreads();
    for (int o = 128; o > 0; o >>= 1) { if (tid < o) red[tid] += red[tid + o]; __syncthreads(); }
    float inv = 1.f / red[0];
#pragma unroll
    for (int i = 0; i < 4; i++) ab[tid + i * 256] = e[i] * inv * Bm[tid + i * 256];
}

// ------------------------- h[b,d,s] = sum_l xn * ab  (split-K, atomic) -------------
__global__ void k_gemm_h() {
    __shared__ float As[8][68], Bs[8][68];
    int b = blockIdx.x, m0 = blockIdx.y * 64, kc = blockIdx.z;
    int tid = threadIdx.x, tx = tid & 15, ty = tid >> 4;
    const float* Ap = g_xn + (size_t)b * D * L;
    const float* Bp = g_ab + (size_t)b * S * L;
    float acc[4][4] = {};
    for (int k0 = kc * 256; k0 < kc * 256 + 256; k0 += 8) {
        for (int p = 0; p < 2; p++) {
            int idx = tid + p * 256; int mm = idx >> 3, kk = idx & 7;
            As[kk][mm] = Ap[(size_t)(m0 + mm) * L + k0 + kk];
        }
        for (int p = 0; p < 2; p++) {
            int idx = tid + p * 256; int nn = idx >> 3, kk = idx & 7;
            Bs[kk][nn] = Bp[(size_t)nn * L + k0 + kk];
        }
        __syncthreads();
#pragma unroll
        for (int k = 0; k < 8; k++) {
            float a[4], bv[4];
#pragma unroll
            for (int i = 0; i < 4; i++) a[i] = As[k][ty + i * 16];
#pragma unroll
            for (int j = 0; j < 4; j++) bv[j] = Bs[k][tx + j * 16];
#pragma unroll
            for (int i = 0; i < 4; i++)
#pragma unroll
                for (int j = 0; j < 4; j++) acc[i][j] += a[i] * bv[j];
        }
        __syncthreads();
    }
    float* Cp = g_h + (size_t)b * D * S;
    for (int i = 0; i < 4; i++)
        for (int j = 0; j < 4; j++)
            atomicAdd(&Cp[(size_t)(m0 + ty + i * 16) * S + tx + j * 16], acc[i][j]);
}

// ------------------------- h2 = silu(hproj @ h) -> out_h ---------------------------
__global__ void k_hproj(const float* __restrict__ Wp, float* __restrict__ outh) {
    __shared__ float As[8][68], Bs[8][68];
    int b = blockIdx.x, m0 = blockIdx.y * 64;
    int tid = threadIdx.x, tx = tid & 15, ty = tid >> 4;
    const float* Bp = g_h + (size_t)b * D * S;
    float acc[4][4] = {};
    for (int k0 = 0; k0 < 384; k0 += 8) {
        for (int p = 0; p < 2; p++) {
            int idx = tid + p * 256; int mm = idx >> 3, kk = idx & 7;
            As[kk][mm] = Wp[(size_t)(m0 + mm) * 384 + k0 + kk];
        }
        for (int p = 0; p < 2; p++) {
            int idx = tid + p * 256; int kk = idx >> 6, nn = idx & 63;
            Bs[kk][nn] = Bp[(size_t)(k0 + kk) * S + nn];
        }
        __syncthreads();
#pragma unroll
        for (int k = 0; k < 8; k++) {
            float a[4], bv[4];
#pragma unroll
            for (int i = 0; i < 4; i++) a[i] = As[k][ty + i * 16];
#pragma unroll
            for (int j = 0; j < 4; j++) bv[j] = Bs[k][tx + j * 16];
#pragma unroll
            for (int i = 0; i < 4; i++)
#pragma unroll
                for (int j = 0; j < 4; j++) acc[i][j] += a[i] * bv[j];
        }
        __syncthreads();
    }
    float* Cp = outh + (size_t)b * D * S;
    for (int i = 0; i < 4; i++)
        for (int j = 0; j < 4; j++) {
            float x = acc[i][j];
            Cp[(size_t)(m0 + ty + i * 16) * S + tx + j * 16] = x / (1.f + __expf(-x));
        }
}

// ------------------------- x2 = x1 + h2 @ Cm ---------------------------------------
__global__ void k_gemm_y(const float* __restrict__ outh) {
    __shared__ float As[8][68], Bs[8][132];
    int b = blockIdx.x, m0 = blockIdx.y * 64, n0 = blockIdx.z * 128;
    int tid = threadIdx.x, tx = tid & 15, ty = tid >> 4;
    const float* Ap = outh + (size_t)b * D * S;
    const float* Bp = g_bcdt2 + ((size_t)b * C3 + S) * L;   // Cm block
    float acc[4][8] = {};
    for (int k0 = 0; k0 < 64; k0 += 8) {
        for (int p = 0; p < 2; p++) {
            int idx = tid + p * 256; int mm = idx >> 3, kk = idx & 7;
            As[kk][mm] = Ap[(size_t)(m0 + mm) * S + k0 + kk];
        }
        for (int p = 0; p < 4; p++) {
            int idx = tid + p * 256; int kk = idx >> 7, nn = idx & 127;
            Bs[kk][nn] = Bp[(size_t)(k0 + kk) * L + n0 + nn];
        }
        __syncthreads();
#pragma unroll
        for (int k = 0; k < 8; k++) {
            float a[4], bv[8];
#pragma unroll
            for (int i = 0; i < 4; i++) a[i] = As[k][ty + i * 16];
#pragma unroll
            for (int j = 0; j < 8; j++) bv[j] = Bs[k][tx + j * 16];
#pragma unroll
            for (int i = 0; i < 4; i++)
#pragma unroll
                for (int j = 0; j < 8; j++) acc[i][j] += a[i] * bv[j];
        }
        __syncthreads();
    }
    for (int i = 0; i < 4; i++)
        for (int j = 0; j < 8; j++) {
            size_t o = (size_t)b * D * L + (size_t)(m0 + ty + i * 16) * L + n0 + tx + j * 16;
            g_x2[o] = g_x1[o] + acc[i][j];
        }
}

// ------------------------- NCHW -> token-major transpose ---------------------------
__global__ void k_transpose(const float* __restrict__ xin) {
    __shared__ float s[32][33];
    int b = blockIdx.x, d0 = blockIdx.y * 32, l0 = blockIdx.z * 32;
    int c = threadIdx.x & 31, r0 = threadIdx.x >> 5;
    for (int i = 0; i < 32; i += 8)
        s[r0 + i][c] = xin[((size_t)b * D + d0 + r0 + i) * L + l0 + c];
    __syncthreads();
    for (int i = 0; i < 32; i += 8)
        g_xT[((size_t)b * L + l0 + r0 + i) * D + d0 + c] = s[c][r0 + i];
}

// ------------------------- router: logits, top-2, softmax --------------------------
__global__ void k_route(const float* __restrict__ gw, const float* __restrict__ gb) {
    __shared__ float sg[E * D];
    int tid = threadIdx.x;
    for (int i = tid; i < E * D; i += 256) sg[i] = gw[i];
    __syncthreads();
    int n = blockIdx.x * 256 + tid;
    const float* t = g_xT + (size_t)n * D;
    float lg[E];
#pragma unroll
    for (int e = 0; e < E; e++) lg[e] = gb[e];
    for (int d = 0; d < D; d++) {
        float x = t[d];
#pragma unroll
        for (int e = 0; e < E; e++) lg[e] += sg[e * D + d] * x;
    }
    int i0 = 0; float v0 = lg[0];
#pragma unroll
    for (int e = 1; e < E; e++) if (lg[e] > v0) { v0 = lg[e]; i0 = e; }
    int i1 = -1; float v1 = -1e30f;
#pragma unroll
    for (int e = 0; e < E; e++) if (e != i0 && lg[e] > v1) { v1 = lg[e]; i1 = e; }
    float p0 = 1.f / (1.f + __expf(v1 - v0));
    g_topk_idx[n * 2] = i0; g_topk_idx[n * 2 + 1] = i1;
    g_topk_w[n * 2] = p0;   g_topk_w[n * 2 + 1] = 1.f - p0;
    atomicAdd(&g_cnt[i0], 1); atomicAdd(&g_cnt[i1], 1);
}

__global__ void k_offsets() {
    int off = 0;
    for (int e = 0; e < E; e++) {
        g_off[e] = off;
        off += (g_cnt[e] + 127) & ~127;
        g_cnt2[e] = 0;
    }
    g_off[E] = off;
}

__global__ void k_scatter() {
    int n = blockIdx.x * 256 + threadIdx.x;
#pragma unroll
    for (int k = 0; k < 2; k++) {
        int e = g_topk_idx[n * 2 + k];
        int pos = g_off[e] + atomicAdd(&g_cnt2[e], 1);
        g_perm[pos] = n;
        g_wgt[pos] = g_topk_w[n * 2 + k];
    }
}

// ------------------- MoE GEMM1 (fused): he = silu(t@w1+b1) * (t@w3+b3) --------------
// tf32 mma, 128x128x16 tiles, 8 warps of 64x32.
__global__ __launch_bounds__(256, 1) void k_moe1(
        const float* __restrict__ W1, const float* __restrict__ B1,
        const float* __restrict__ W3, const float* __restrict__ B3) {
    int e = blockIdx.x;
    int cnt = g_cnt[e];
    int m0 = blockIdx.y * 128;
    if (m0 >= cnt) return;
    int base = g_off[e];
    int n0 = blockIdx.z * 128;

    __shared__ uint32_t As[128][20];
    __shared__ uint32_t Bs1[128][20];
    __shared__ uint32_t Bs3[128][20];
    __shared__ int sperm[128];

    int tid = threadIdx.x, lane = tid & 31, wid = tid >> 5;
    int wm = (wid & 1) * 64, wn = (wid >> 1) * 32;
    int g = lane >> 2, tg = lane & 3;
    if (tid < 128) sperm[tid] = g_perm[base + m0 + tid];
    __syncthreads();

    const float* Wp1 = W1 + (size_t)e * HID * D + (size_t)n0 * D;
    const float* Wp3 = W3 + (size_t)e * HID * D + (size_t)n0 * D;

    float acc1[4][4][4] = {}, acc3[4][4][4] = {};

    int lr = tid >> 1;               // row 0..127
    int lc = (tid & 1) * 2;          // float4 index 0/2 (loads lc and lc+1)

    for (int k0 = 0; k0 < D; k0 += 16) {
        const float* arow = g_xT + (size_t)sperm[lr] * D + k0;
        const float* b1row = Wp1 + (size_t)lr * D + k0;
        const float* b3row = Wp3 + (size_t)lr * D + k0;
#pragma unroll
        for (int q = 0; q < 2; q++) {
            float4 av = *(const float4*)(arow + (lc + q) * 4);
            float4 bv1 = *(const float4*)(b1row + (lc + q) * 4);
            float4 bv3 = *(const float4*)(b3row + (lc + q) * 4);
            uint4 ua = make_uint4(f2tf32(av.x), f2tf32(av.y), f2tf32(av.z), f2tf32(av.w));
            uint4 ub1 = make_uint4(f2tf32(bv1.x), f2tf32(bv1.y), f2tf32(bv1.z), f2tf32(bv1.w));
            uint4 ub3 = make_uint4(f2tf32(bv3.x), f2tf32(bv3.y), f2tf32(bv3.z), f2tf32(bv3.w));
            *(uint4*)&As[lr][(lc + q) * 4] = ua;
            *(uint4*)&Bs1[lr][(lc + q) * 4] = ub1;
            *(uint4*)&Bs3[lr][(lc + q) * 4] = ub3;
        }
        __syncthreads();
#pragma unroll
        for (int ks = 0; ks < 16; ks += 8) {
            uint32_t af[4][4];
#pragma unroll
            for (int mt = 0; mt < 4; mt++) {
                int r = wm + mt * 16 + g;
                af[mt][0] = As[r][ks + tg];
                af[mt][1] = As[r + 8][ks + tg];
                af[mt][2] = As[r][ks + 4 + tg];
                af[mt][3] = As[r + 8][ks + 4 + tg];
            }
            uint32_t bf[4][2];
#pragma unroll
            for (int nt = 0; nt < 4; nt++) {
                int c = wn + nt * 8 + g;
                bf[nt][0] = Bs1[c][ks + tg];
                bf[nt][1] = Bs1[c][ks + 4 + tg];
            }
#pragma unroll
            for (int mt = 0; mt < 4; mt++)
#pragma unroll
                for (int nt = 0; nt < 4; nt++)
                    mma_tf32(acc1[mt][nt], af[mt][0], af[mt][1], af[mt][2], af[mt][3],
                             bf[nt][0], bf[nt][1]);
#pragma unroll
            for (int nt = 0; nt < 4; nt++) {
                int c = wn + nt * 8 + g;
                bf[nt][0] = Bs3[c][ks + tg];
                bf[nt][1] = Bs3[c][ks + 4 + tg];
            }
#pragma unroll
            for (int mt = 0; mt < 4; mt++)
#pragma unroll
                for (int nt = 0; nt < 4; nt++)
                    mma_tf32(acc3[mt][nt], af[mt][0], af[mt][1], af[mt][2], af[mt][3],
                             bf[nt][0], bf[nt][1]);
        }
        __syncthreads();
    }

    // epilogue: he = silu(acc1 + b1) * (acc3 + b3)
#pragma unroll
    for (int mt = 0; mt < 4; mt++) {
#pragma unroll
        for (int nt = 0; nt < 4; nt++) {
            int cl = n0 + wn + nt * 8 + tg * 2;
            float bb1a = B1[e * HID + cl], bb1b = B1[e * HID + cl + 1];
            float bb3a = B3[e * HID + cl], bb3b = B3[e * HID + cl + 1];
#pragma unroll
            for (int h = 0; h < 2; h++) {
                int rl = wm + mt * 16 + g + h * 8;
                float x1a = acc1[mt][nt][h * 2] + bb1a;
                float x1b = acc1[mt][nt][h * 2 + 1] + bb1b;
                float x3a = acc3[mt][nt][h * 2] + bb3a;
                float x3b = acc3[mt][nt][h * 2 + 1] + bb3b;
                float2 o;
                o.x = (x1a / (1.f + __expf(-x1a))) * x3a;
                o.y = (x1b / (1.f + __expf(-x1b))) * x3b;
                *(float2*)&g_he[(size_t)(base + m0 + rl) * HID + cl] = o;
            }
        }
    }
}

// ------------------------- MoE GEMM2: out += (he@w2+b2)*w (tf32 mma, scatter) ------
__global__ __launch_bounds__(256, 2) void k_moe2(
        const float* __restrict__ W2, const float* __restrict__ b2v,
        float* __restrict__ outx) {
    int e = blockIdx.x;
    int cnt = g_cnt[e];
    int m0 = blockIdx.y * 128;
    if (m0 >= cnt) return;
    int base = g_off[e];
    int n0 = blockIdx.z * 128;

    __shared__ uint32_t As[128][20];
    __shared__ uint32_t Bs[128][20];

    int tid = threadIdx.x, lane = tid & 31, wid = tid >> 5;
    int wm = (wid & 1) * 64, wn = (wid >> 1) * 32;
    int g = lane >> 2, tg = lane & 3;

    const float* Wp = W2 + (size_t)e * D * HID + (size_t)n0 * HID;
    float acc[4][4][4] = {};

    int lr = tid >> 1;
    int lc = (tid & 1) * 2;

    for (int k0 = 0; k0 < HID; k0 += 16) {
        const float* arow = g_he + (size_t)(base + m0 + lr) * HID + k0;
        const float* brow = Wp + (size_t)lr * HID + k0;
#pragma unroll
        for (int q = 0; q < 2; q++) {
            float4 av = *(const float4*)(arow + (lc + q) * 4);
            float4 bv = *(const float4*)(brow + (lc + q) * 4);
            uint4 ua = make_uint4(f2tf32(av.x), f2tf32(av.y), f2tf32(av.z), f2tf32(av.w));
            uint4 ub = make_uint4(f2tf32(bv.x), f2tf32(bv.y), f2tf32(bv.z), f2tf32(bv.w));
            *(uint4*)&As[lr][(lc + q) * 4] = ua;
            *(uint4*)&Bs[lr][(lc + q) * 4] = ub;
        }
        __syncthreads();
#pragma unroll
        for (int ks = 0; ks < 16; ks += 8) {
            uint32_t af[4][4];
#pragma unroll
            for (int mt = 0; mt < 4; mt++) {
                int r = wm + mt * 16 + g;
                af[mt][0] = As[r][ks + tg];
                af[mt][1] = As[r + 8][ks + tg];
                af[mt][2] = As[r][ks + 4 + tg];
                af[mt][3] = As[r + 8][ks + 4 + tg];
            }
            uint32_t bf[4][2];
#pragma unroll
            for (int nt = 0; nt < 4; nt++) {
                int c = wn + nt * 8 + g;
                bf[nt][0] = Bs[c][ks + tg];
                bf[nt][1] = Bs[c][ks + 4 + tg];
            }
#pragma unroll
            for (int mt = 0; mt < 4; mt++)
#pragma unroll
                for (int nt = 0; nt < 4; nt++)
                    mma_tf32(acc[mt][nt], af[mt][0], af[mt][1], af[mt][2], af[mt][3],
                             bf[nt][0], bf[nt][1]);
        }
        __syncthreads();
    }

    // epilogue: scatter-add (acc + b2) * weight into NCHW output
#pragma unroll
    for (int mt = 0; mt < 4; mt++) {
#pragma unroll
        for (int h = 0; h < 2; h++) {
            int rl = wm + mt * 16 + g + h * 8;
            float w = g_wgt[base + m0 + rl];
            if (w == 0.f) continue;
            int n = g_perm[base + m0 + rl];
            int b = n >> 10, l = n & 1023;
#pragma unroll
            for (int nt = 0; nt < 4; nt++) {
                int cl = n0 + wn + nt * 8 + tg * 2;
                float v0 = (acc[mt][nt][h * 2] + b2v[e * D + cl]) * w;
                float v1 = (acc[mt][nt][h * 2 + 1] + b2v[e * D + cl + 1]) * w;
                atomicAdd(&outx[((size_t)b * D + cl) * L + l], v0);
                atomicAdd(&outx[((size_t)b * D + cl + 1) * L + l], v1);
            }
        }
    }
}

// ------------------------- launch ---------------------------------------------------
extern "C" void kernel_launch(void* const* d_in, const int* in_sizes, int n_in,
                              void* d_out, int out_size) {
    const float* x      = (const float*)d_in[0];
    const float* dw1_w  = (const float*)d_in[1];
    const float* bn1_g  = (const float*)d_in[2];
    const float* bn1_b  = (const float*)d_in[3];
    const float* bn1_m  = (const float*)d_in[4];
    const float* bn1_v  = (const float*)d_in[5];
    const float* dw2_w  = (const float*)d_in[6];
    const float* bn2_g  = (const float*)d_in[7];
    const float* bn2_b  = (const float*)d_in[8];
    const float* bn2_m  = (const float*)d_in[9];
    const float* bn2_v  = (const float*)d_in[10];
    const float* ln_w   = (const float*)d_in[11];
    const float* ln_b   = (const float*)d_in[12];
    const float* bcdt_w = (const float*)d_in[13];
    const float* dws_w  = (const float*)d_in[14];
    const float* hproj_w= (const float*)d_in[15];
    // d_in[16] = A (cancels inside softmax over L)
    const float* gate_w = (const float*)d_in[17];
    const float* gate_b = (const float*)d_in[18];
    const float* w1     = (const float*)d_in[19];
    const float* b1     = (const float*)d_in[20];
    const float* w2     = (const float*)d_in[21];
    const float* b2     = (const float*)d_in[22];
    const float* w3     = (const float*)d_in[23];
    const float* b3     = (const float*)d_in[24];

    float* out_x = (float*)d_out;
    float* out_h = out_x + (size_t)Bsz * D * L;

    float* px1;    cudaGetSymbolAddress((void**)&px1, g_x1);
    float* pbcdt;  cudaGetSymbolAddress((void**)&pbcdt, g_bcdt);
    float* pbcdt2; cudaGetSymbolAddress((void**)&pbcdt2, g_bcdt2);
    float* px2;    cudaGetSymbolAddress((void**)&px2, g_x2);

    k_init<<<1536, 256>>>();

    // x1 = x + bn1(dw1(x))
    k_dwconv<<<Bsz * D, 256>>>(x, dw1_w, bn1_g, bn1_b, bn1_m, bn1_v, px1, D, 1);
    // xn = LN(x1)
    k_ln<<<NTOK / 256, 256>>>(ln_w, ln_b);
    // bcdt
    k_gemm_bcdt<<<dim3(Bsz, 3, 8), 256>>>(bcdt_w);
    k_dwconv<<<Bsz * C3, 256>>>(pbcdt, dws_w, nullptr, nullptr, nullptr, nullptr, pbcdt2, C3, 0);
    k_softmax<<<Bsz * S, 256>>>();
    // h = xn @ (Am*Bm)^T  (split-K=4 with atomics)
    k_gemm_h<<<dim3(Bsz, 6, 4), 256>>>();
    // h2 = silu(hproj @ h) -> second output
    k_hproj<<<dim3(Bsz, 6, 1), 256>>>(hproj_w, out_h);
    // x2 = x1 + h2 @ Cm
    k_gemm_y<<<dim3(Bsz, 6, 8), 256>>>(out_h);
    // x3 = x2 + bn2(dw2(x2)) -> first output (MoE adds on top)
    k_dwconv<<<Bsz * D, 256>>>(px2, dw2_w, bn2_g, bn2_b, bn2_m, bn2_v, out_x, D, 1);
    // tokens
    k_transpose<<<dim3(Bsz, 12, 32), 256>>>(out_x);
    // routing
    k_route<<<NTOK / 256, 256>>>(gate_w, gate_b);
    k_offsets<<<1, 1>>>();
    k_scatter<<<NTOK / 256, 256>>>();
    // MoE (tf32 tensor cores)
    k_moe1<<<dim3(E, 128, 6), 256>>>(w1, b1, w3, b3);
    k_moe2<<<dim3(E, 128, 3), 256>>>(w2, b2, out_x);
}

// round 3
// speedup vs baseline: 3.0079x; 2.0934x over previous
#include <cuda_runtime.h>
#include <cuda_bf16.h>
#include <cstdint>

#define EPSV 1e-5f

constexpr int Bsz = 16, D = 384, L = 1024, S = 64, C3 = 192, E = 8, HID = 768;
constexpr int NTOK = Bsz * L;                    // 16384
constexpr int MAXSLOTS = 2 * NTOK + E * 128;     // 33792 (expert-padded)

// ------------------------- scratch (static device globals) -------------------------
__device__ float g_x1[Bsz * D * L];
__device__ float g_xn[Bsz * D * L];
__device__ float g_bcdt[Bsz * C3 * L];
__device__ float g_bcdt2[Bsz * C3 * L];
__device__ float g_ab[Bsz * S * L];
__device__ float g_h[Bsz * D * S];
__device__ float g_x2[Bsz * D * L];
__device__ float g_xT[NTOK * D];
__device__ __nv_bfloat16 g_xTb[NTOK * D];
__device__ __nv_bfloat16 g_heb[(size_t)MAXSLOTS * HID];
__device__ __nv_bfloat16 g_w1b[E * HID * D];
__device__ __nv_bfloat16 g_w3b[E * HID * D];
__device__ __nv_bfloat16 g_w2b[E * D * HID];
__device__ int   g_cnt[E];
__device__ int   g_cnt2[E];
__device__ int   g_off[E + 1];
__device__ int   g_topk_idx[NTOK * 2];
__device__ float g_topk_w[NTOK * 2];
__device__ int   g_perm[MAXSLOTS];
__device__ float g_wgt[MAXSLOTS];

// ------------------------- mma helpers ----------------------------------------------
__device__ __forceinline__ void ldm_x4(uint32_t* r, uint32_t addr) {
    asm volatile("ldmatrix.sync.aligned.m8n8.x4.shared.b16 {%0,%1,%2,%3}, [%4];"
                 : "=r"(r[0]), "=r"(r[1]), "=r"(r[2]), "=r"(r[3]) : "r"(addr));
}
__device__ __forceinline__ void mma_bf16(float c[4], const uint32_t a[4],
                                         uint32_t b0, uint32_t b1) {
    asm volatile(
        "mma.sync.aligned.m16n8k16.row.col.f32.bf16.bf16.f32 "
        "{%0,%1,%2,%3}, {%4,%5,%6,%7}, {%8,%9}, {%0,%1,%2,%3};"
        : "+f"(c[0]), "+f"(c[1]), "+f"(c[2]), "+f"(c[3])
        : "r"(a[0]), "r"(a[1]), "r"(a[2]), "r"(a[3]), "r"(b0), "r"(b1));
}

// ------------------------- init ------------------------------------------------------
__global__ void k_init() {
    int i = blockIdx.x * 256 + threadIdx.x;
    if (i < MAXSLOTS) { g_wgt[i] = 0.f; g_perm[i] = 0; }
    if (i < E) g_cnt[i] = 0;
    if (i < Bsz * D * S) g_h[i] = 0.f;
}

// ------------------------- fp32 -> bf16 convert --------------------------------------
__global__ void k_cvt(const float* __restrict__ s, __nv_bfloat16* __restrict__ d, int n) {
    int i = (blockIdx.x * 256 + threadIdx.x) * 4;
    if (i < n) {
        float4 v = *(const float4*)(s + i);
        *(__nv_bfloat162*)(d + i)     = __float22bfloat162_rn(make_float2(v.x, v.y));
        *(__nv_bfloat162*)(d + i + 2) = __float22bfloat162_rn(make_float2(v.z, v.w));
    }
}

// ------------------------- depthwise 3x3 (+optional BN, +optional residual) ----------
__global__ void k_dwconv(const float* __restrict__ in, const float* __restrict__ w9,
                         const float* __restrict__ g, const float* __restrict__ bb,
                         const float* __restrict__ m, const float* __restrict__ v,
                         float* __restrict__ out, int C, int residual) {
    __shared__ float s[34 * 34];
    int b = blockIdx.x / C, c = blockIdx.x % C;
    const float* ip = in + (size_t)(b * C + c) * L;
    int tid = threadIdx.x;
    for (int idx = tid; idx < 34 * 34; idx += 256) {
        int r = idx / 34 - 1, cc = idx % 34 - 1;
        s[idx] = (r >= 0 && r < 32 && cc >= 0 && cc < 32) ? ip[r * 32 + cc] : 0.f;
    }
    __syncthreads();
    float w[9];
#pragma unroll
    for (int i = 0; i < 9; i++) w[i] = w9[c * 9 + i];
    float sc = 1.f, sh = 0.f;
    if (g) { sc = g[c] * rsqrtf(v[c] + EPSV); sh = bb[c] - m[c] * sc; }
    float* op = out + (size_t)(b * C + c) * L;
    for (int idx = tid; idx < 1024; idx += 256) {
        int r = idx >> 5, cc = idx & 31;
        float acc = 0.f;
#pragma unroll
        for (int kr = 0; kr < 3; kr++)
#pragma unroll
            for (int kc = 0; kc < 3; kc++)
                acc += w[kr * 3 + kc] * s[(r + kr) * 34 + cc + kc];
        float val = sc * acc + sh;
        if (residual) val += s[(r + 1) * 34 + cc + 1];
        op[idx] = val;
    }
}

// ------------------------- LayerNorm over channel dim --------------------------------
__global__ void k_ln(const float* __restrict__ lnw, const float* __restrict__ lnb) {
    int gi = blockIdx.x * 256 + threadIdx.x;
    int b = gi >> 10, l = gi & 1023;
    const float* p = g_x1 + (size_t)b * D * L + l;
    float sum = 0.f, sq = 0.f;
    for (int d = 0; d < D; d++) { float x = p[(size_t)d * L]; sum += x; sq += x * x; }
    float mu = sum * (1.f / D);
    float var = sq * (1.f / D) - mu * mu;
    float inv = rsqrtf(var + EPSV);
    float* o = g_xn + (size_t)b * D * L + l;
    for (int d = 0; d < D; d++)
        o[(size_t)d * L] = (p[(size_t)d * L] - mu) * inv * lnw[d] + lnb[d];
}

// ------------------------- bcdt = bcdt_w @ xn_b --------------------------------------
__global__ void k_gemm_bcdt(const float* __restrict__ Wm) {
    __shared__ float As[8][68], Bs[8][132];
    int b = blockIdx.x, m0 = blockIdx.y * 64, n0 = blockIdx.z * 128;
    int tid = threadIdx.x, tx = tid & 15, ty = tid >> 4;
    const float* Bp = g_xn + (size_t)b * D * L;
    float acc[4][8] = {};
    for (int k0 = 0; k0 < 384; k0 += 8) {
        for (int p = 0; p < 2; p++) {
            int idx = tid + p * 256; int mm = idx >> 3, kk = idx & 7;
            As[kk][mm] = Wm[(size_t)(m0 + mm) * 384 + k0 + kk];
        }
        for (int p = 0; p < 4; p++) {
            int idx = tid + p * 256; int kk = idx >> 7, nn = idx & 127;
            Bs[kk][nn] = Bp[(size_t)(k0 + kk) * L + n0 + nn];
        }
        __syncthreads();
#pragma unroll
        for (int k = 0; k < 8; k++) {
            float a[4], bv[8];
#pragma unroll
            for (int i = 0; i < 4; i++) a[i] = As[k][ty + i * 16];
#pragma unroll
            for (int j = 0; j < 8; j++) bv[j] = Bs[k][tx + j * 16];
#pragma unroll
            for (int i = 0; i < 4; i++)
#pragma unroll
                for (int j = 0; j < 8; j++) acc[i][j] += a[i] * bv[j];
        }
        __syncthreads();
    }
    float* Cp = g_bcdt + (size_t)b * C3 * L;
    for (int i = 0; i < 4; i++)
        for (int j = 0; j < 8; j++)
            Cp[(size_t)(m0 + ty + i * 16) * L + n0 + tx + j * 16] = acc[i][j];
}

// ------------------------- softmax over L + *Bm --------------------------------------
__global__ void k_softmax() {
    int b = blockIdx.x >> 6, s = blockIdx.x & 63;
    const float* dt = g_bcdt2 + ((size_t)b * C3 + 2 * S + s) * L;
    const float* Bm = g_bcdt2 + ((size_t)b * C3 + s) * L;
    float* ab = g_ab + ((size_t)b * S + s) * L;
    int tid = threadIdx.x;
    __shared__ float red[256];
    float vals[4]; float mx = -1e30f;
#pragma unroll
    for (int i = 0; i < 4; i++) { vals[i] = dt[tid + i * 256]; mx = fmaxf(mx, vals[i]); }
    red[tid] = mx; __syncthreads();
    for (int o = 128; o > 0; o >>= 1) { if (tid < o) red[tid] = fmaxf(red[tid], red[tid + o]); __syncthreads(); }
    mx = red[0]; __syncthreads();
    float e[4]; float sum = 0.f;
#pragma unroll
    for (int i = 0; i < 4; i++) { e[i] = __expf(vals[i] - mx); sum += e[i]; }
    red[tid] = sum; __syncthreads();
    for (int o = 128; o > 0; o >>= 1) { if (tid < o) red[tid] += red[tid + o]; __syncthreads(); }
    float inv = 1.f / red[0];
#pragma unroll
    for (int i = 0; i < 4; i++) ab[tid + i * 256] = e[i] * inv * Bm[tid + i * 256];
}

// ------------------------- h[b,d,s] = sum_l xn * ab (split-K, atomic) ----------------
__global__ void k_gemm_h() {
    __shared__ float As[8][68], Bs[8][68];
    int b = blockIdx.x, m0 = blockIdx.y * 64, kc = blockIdx.z;
    int tid = threadIdx.x, tx = tid & 15, ty = tid >> 4;
    const float* Ap = g_xn + (size_t)b * D * L;
    const float* Bp = g_ab + (size_t)b * S * L;
    float acc[4][4] = {};
    for (int k0 = kc * 256; k0 < kc * 256 + 256; k0 += 8) {
        for (int p = 0; p < 2; p++) {
            int idx = tid + p * 256; int mm = idx >> 3, kk = idx & 7;
            As[kk][mm] = Ap[(size_t)(m0 + mm) * L + k0 + kk];
        }
        for (int p = 0; p < 2; p++) {
            int idx = tid + p * 256; int nn = idx >> 3, kk = idx & 7;
            Bs[kk][nn] = Bp[(size_t)nn * L + k0 + kk];
        }
        __syncthreads();
#pragma unroll
        for (int k = 0; k < 8; k++) {
            float a[4], bv[4];
#pragma unroll
            for (int i = 0; i < 4; i++) a[i] = As[k][ty + i * 16];
#pragma unroll
            for (int j = 0; j < 4; j++) bv[j] = Bs[k][tx + j * 16];
#pragma unroll
            for (int i = 0; i < 4; i++)
#pragma unroll
                for (int j = 0; j < 4; j++) acc[i][j] += a[i] * bv[j];
        }
        __syncthreads();
    }
    float* Cp = g_h + (size_t)b * D * S;
    for (int i = 0; i < 4; i++)
        for (int j = 0; j < 4; j++)
            atomicAdd(&Cp[(size_t)(m0 + ty + i * 16) * S + tx + j * 16], acc[i][j]);
}

// ------------------------- h2 = silu(hproj @ h) -> out_h -----------------------------
__global__ void k_hproj(const float* __restrict__ Wp, float* __restrict__ outh) {
    __shared__ float As[8][68], Bs[8][68];
    int b = blockIdx.x, m0 = blockIdx.y * 64;
    int tid = threadIdx.x, tx = tid & 15, ty = tid >> 4;
    const float* Bp = g_h + (size_t)b * D * S;
    float acc[4][4] = {};
    for (int k0 = 0; k0 < 384; k0 += 8) {
        for (int p = 0; p < 2; p++) {
            int idx = tid + p * 256; int mm = idx >> 3, kk = idx & 7;
            As[kk][mm] = Wp[(size_t)(m0 + mm) * 384 + k0 + kk];
        }
        for (int p = 0; p < 2; p++) {
            int idx = tid + p * 256; int kk = idx >> 6, nn = idx & 63;
            Bs[kk][nn] = Bp[(size_t)(k0 + kk) * S + nn];
        }
        __syncthreads();
#pragma unroll
        for (int k = 0; k < 8; k++) {
            float a[4], bv[4];
#pragma unroll
            for (int i = 0; i < 4; i++) a[i] = As[k][ty + i * 16];
#pragma unroll
            for (int j = 0; j < 4; j++) bv[j] = Bs[k][tx + j * 16];
#pragma unroll
            for (int i = 0; i < 4; i++)
#pragma unroll
                for (int j = 0; j < 4; j++) acc[i][j] += a[i] * bv[j];
        }
        __syncthreads();
    }
    float* Cp = outh + (size_t)b * D * S;
    for (int i = 0; i < 4; i++)
        for (int j = 0; j < 4; j++) {
            float x = acc[i][j];
            Cp[(size_t)(m0 + ty + i * 16) * S + tx + j * 16] = x / (1.f + __expf(-x));
        }
}

// ------------------------- x2 = x1 + h2 @ Cm -----------------------------------------
__global__ void k_gemm_y(const float* __restrict__ outh) {
    __shared__ float As[8][68], Bs[8][132];
    int b = blockIdx.x, m0 = blockIdx.y * 64, n0 = blockIdx.z * 128;
    int tid = threadIdx.x, tx = tid & 15, ty = tid >> 4;
    const float* Ap = outh + (size_t)b * D * S;
    const float* Bp = g_bcdt2 + ((size_t)b * C3 + S) * L;
    float acc[4][8] = {};
    for (int k0 = 0; k0 < 64; k0 += 8) {
        for (int p = 0; p < 2; p++) {
            int idx = tid + p * 256; int mm = idx >> 3, kk = idx & 7;
            As[kk][mm] = Ap[(size_t)(m0 + mm) * S + k0 + kk];
        }
        for (int p = 0; p < 4; p++) {
            int idx = tid + p * 256; int kk = idx >> 7, nn = idx & 127;
            Bs[kk][nn] = Bp[(size_t)(k0 + kk) * L + n0 + nn];
        }
        __syncthreads();
#pragma unroll
        for (int k = 0; k < 8; k++) {
            float a[4], bv[8];
#pragma unroll
            for (int i = 0; i < 4; i++) a[i] = As[k][ty + i * 16];
#pragma unroll
            for (int j = 0; j < 8; j++) bv[j] = Bs[k][tx + j * 16];
#pragma unroll
            for (int i = 0; i < 4; i++)
#pragma unroll
                for (int j = 0; j < 8; j++) acc[i][j] += a[i] * bv[j];
        }
        __syncthreads();
    }
    for (int i = 0; i < 4; i++)
        for (int j = 0; j < 8; j++) {
            size_t o = (size_t)b * D * L + (size_t)(m0 + ty + i * 16) * L + n0 + tx + j * 16;
            g_x2[o] = g_x1[o] + acc[i][j];
        }
}

// ------------------------- NCHW -> token-major transpose (fp32 + bf16) ---------------
__global__ void k_transpose(const float* __restrict__ xin) {
    __shared__ float s[32][33];
    int b = blockIdx.x, d0 = blockIdx.y * 32, l0 = blockIdx.z * 32;
    int c = threadIdx.x & 31, r0 = threadIdx.x >> 5;
    for (int i = 0; i < 32; i += 8)
        s[r0 + i][c] = xin[((size_t)b * D + d0 + r0 + i) * L + l0 + c];
    __syncthreads();
    for (int i = 0; i < 32; i += 8) {
        float v = s[c][r0 + i];
        size_t o = ((size_t)b * L + l0 + r0 + i) * D + d0 + c;
        g_xT[o] = v;
        g_xTb[o] = __float2bfloat16(v);
    }
}

// ------------------------- router --------------------------------------------------
__global__ void k_route(const float* __restrict__ gw, const float* __restrict__ gb) {
    __shared__ float sg[E * D];
    int tid = threadIdx.x;
    for (int i = tid; i < E * D; i += 256) sg[i] = gw[i];
    __syncthreads();
    int n = blockIdx.x * 256 + tid;
    const float* t = g_xT + (size_t)n * D;
    float lg[E];
#pragma unroll
    for (int e = 0; e < E; e++) lg[e] = gb[e];
    for (int d = 0; d < D; d++) {
        float x = t[d];
#pragma unroll
        for (int e = 0; e < E; e++) lg[e] += sg[e * D + d] * x;
    }
    int i0 = 0; float v0 = lg[0];
#pragma unroll
    for (int e = 1; e < E; e++) if (lg[e] > v0) { v0 = lg[e]; i0 = e; }
    int i1 = -1; float v1 = -1e30f;
#pragma unroll
    for (int e = 0; e < E; e++) if (e != i0 && lg[e] > v1) { v1 = lg[e]; i1 = e; }
    float p0 = 1.f / (1.f + __expf(v1 - v0));
    g_topk_idx[n * 2] = i0; g_topk_idx[n * 2 + 1] = i1;
    g_topk_w[n * 2] = p0;   g_topk_w[n * 2 + 1] = 1.f - p0;
    atomicAdd(&g_cnt[i0], 1); atomicAdd(&g_cnt[i1], 1);
}

__global__ void k_offsets() {
    int off = 0;
    for (int e = 0; e < E; e++) {
        g_off[e] = off;
        off += (g_cnt[e] + 127) & ~127;
        g_cnt2[e] = 0;
    }
    g_off[E] = off;
}

__global__ void k_scatter() {
    int n = blockIdx.x * 256 + threadIdx.x;
#pragma unroll
    for (int k = 0; k < 2; k++) {
        int e = g_topk_idx[n * 2 + k];
        int pos = g_off[e] + atomicAdd(&g_cnt2[e], 1);
        g_perm[pos] = n;
        g_wgt[pos] = g_topk_w[n * 2 + k];
    }
}

// ------------------- MoE GEMM1 (bf16 mma): he = silu(t@w1+b1)*(t@w3+b3) --------------
// CTA tile 128x128, k-tile 32, double-buffered smem, ldmatrix fragments.
// smem layout (bytes): A[2][10240] @0, B1[2][10240] @20480, B3 @40960, perm @61440
__global__ __launch_bounds__(256) void k_moe1(
        const float* __restrict__ B1, const float* __restrict__ B3) {
    extern __shared__ char sm[];
    __nv_bfloat16* sA  = (__nv_bfloat16*)sm;
    __nv_bfloat16* sB1 = (__nv_bfloat16*)(sm + 20480);
    __nv_bfloat16* sB3 = (__nv_bfloat16*)(sm + 40960);
    int* sperm = (int*)(sm + 61440);

    int e = blockIdx.x;
    int cnt = g_cnt[e];
    int m0 = blockIdx.y * 128;
    if (m0 >= cnt) return;
    int base = g_off[e];
    int n0 = blockIdx.z * 128;

    int tid = threadIdx.x, lane = tid & 31, wid = tid >> 5;
    int wm = (wid & 1) * 64, wn = (wid >> 1) * 32;
    int g = lane >> 2, tg = lane & 3;

    if (tid < 128) sperm[tid] = g_perm[base + m0 + tid];
    __syncthreads();

    int lr = tid >> 1, lh = tid & 1;
    const __nv_bfloat16* aRow  = g_xTb + (size_t)sperm[lr] * D + lh * 16;
    const __nv_bfloat16* b1Row = g_w1b + ((size_t)e * HID + n0 + lr) * D + lh * 16;
    const __nv_bfloat16* b3Row = g_w3b + ((size_t)e * HID + n0 + lr) * D + lh * 16;
    int sStore = lr * 40 + lh * 16;          // elements

    uint32_t aSm  = (uint32_t)__cvta_generic_to_shared(sA);
    uint32_t b1Sm = (uint32_t)__cvta_generic_to_shared(sB1);
    uint32_t b3Sm = (uint32_t)__cvta_generic_to_shared(sB3);
    uint32_t aFrag = (wm + (lane & 15)) * 80 + (lane >> 4) * 16;
    uint32_t bFrag = (wn + (lane >> 4) * 8 + (lane & 7)) * 80 + ((lane >> 3) & 1) * 16;

    float acc1[4][4][4] = {}, acc3[4][4][4] = {};
    uint4 pa0, pa1, pb10, pb11, pb30, pb31;

    pa0  = *(const uint4*)(aRow);      pa1  = *(const uint4*)(aRow + 8);
    pb10 = *(const uint4*)(b1Row);     pb11 = *(const uint4*)(b1Row + 8);
    pb30 = *(const uint4*)(b3Row);     pb31 = *(const uint4*)(b3Row + 8);

    constexpr int KT = D / 32;   // 12
    for (int it = 0; it < KT; it++) {
        int buf = it & 1;
        __nv_bfloat16* dA  = sA  + buf * 5120 + sStore;
        __nv_bfloat16* dB1 = sB1 + buf * 5120 + sStore;
        __nv_bfloat16* dB3 = sB3 + buf * 5120 + sStore;
        *(uint4*)dA = pa0;        *(uint4*)(dA + 8) = pa1;
        *(uint4*)dB1 = pb10;      *(uint4*)(dB1 + 8) = pb11;
        *(uint4*)dB3 = pb30;      *(uint4*)(dB3 + 8) = pb31;
        __syncthreads();
        if (it + 1 < KT) {
            int k0 = (it + 1) * 32;
            pa0  = *(const uint4*)(aRow + k0);      pa1  = *(const uint4*)(aRow + k0 + 8);
            pb10 = *(const uint4*)(b1Row + k0);     pb11 = *(const uint4*)(b1Row + k0 + 8);
            pb30 = *(const uint4*)(b3Row + k0);     pb31 = *(const uint4*)(b3Row + k0 + 8);
        }
        uint32_t bufOff = buf * 10240;
#pragma unroll
        for (int ks = 0; ks < 2; ks++) {
            uint32_t af[4][4], bf1[2][4], bf3[2][4];
#pragma unroll
            for (int mt = 0; mt < 4; mt++)
                ldm_x4(af[mt], aSm + bufOff + aFrag + mt * 1280 + ks * 32);
#pragma unroll
            for (int np = 0; np < 2; np++) {
                ldm_x4(bf1[np], b1Sm + bufOff + bFrag + np * 1280 + ks * 32);
                ldm_x4(bf3[np], b3Sm + bufOff + bFrag + np * 1280 + ks * 32);
            }
#pragma unroll
            for (int mt = 0; mt < 4; mt++)
#pragma unroll
                for (int nt = 0; nt < 4; nt++) {
                    int np = nt >> 1, hf = (nt & 1) * 2;
                    mma_bf16(acc1[mt][nt], af[mt], bf1[np][hf], bf1[np][hf + 1]);
                    mma_bf16(acc3[mt][nt], af[mt], bf3[np][hf], bf3[np][hf + 1]);
                }
        }
        __syncthreads();
    }

    // epilogue: he = silu(acc1 + b1) * (acc3 + b3), write bf16
#pragma unroll
    for (int mt = 0; mt < 4; mt++) {
#pragma unroll
        for (int nt = 0; nt < 4; nt++) {
            int cl = n0 + wn + nt * 8 + tg * 2;
            float bb1a = B1[e * HID + cl], bb1b = B1[e * HID + cl + 1];
            float bb3a = B3[e * HID + cl], bb3b = B3[e * HID + cl + 1];
#pragma unroll
            for (int h = 0; h < 2; h++) {
                int rl = wm + mt * 16 + g + h * 8;
                float x1a = acc1[mt][nt][h * 2] + bb1a;
                float x1b = acc1[mt][nt][h * 2 + 1] + bb1b;
                float x3a = acc3[mt][nt][h * 2] + bb3a;
                float x3b = acc3[mt][nt][h * 2 + 1] + bb3b;
                float oa = (x1a / (1.f + __expf(-x1a))) * x3a;
                float ob = (x1b / (1.f + __expf(-x1b))) * x3b;
                *(__nv_bfloat162*)&g_heb[(size_t)(base + m0 + rl) * HID + cl] =
                    __float22bfloat162_rn(make_float2(oa, ob));
            }
        }
    }
}

// ------------------- MoE GEMM2 (bf16 mma): out += (he@w2+b2)*w (scatter) -------------
// smem: A[2][10240] @0, B[2][10240] @20480
__global__ __launch_bounds__(256) void k_moe2(
        const float* __restrict__ b2v, float* __restrict__ outx) {
    extern __shared__ char sm[];
    __nv_bfloat16* sA = (__nv_bfloat16*)sm;
    __nv_bfloat16* sB = (__nv_bfloat16*)(sm + 20480);

    int e = blockIdx.x;
    int cnt = g_cnt[e];
    int m0 = blockIdx.y * 128;
    if (m0 >= cnt) return;
    int base = g_off[e];
    int n0 = blockIdx.z * 128;

    int tid = threadIdx.x, lane = tid & 31, wid = tid >> 5;
    int wm = (wid & 1) * 64, wn = (wid >> 1) * 32;
    int g = lane >> 2, tg = lane & 3;

    int lr = tid >> 1, lh = tid & 1;
    const __nv_bfloat16* aRow = g_heb + (size_t)(base + m0 + lr) * HID + lh * 16;
    const __nv_bfloat16* bRow = g_w2b + ((size_t)e * D + n0 + lr) * HID + lh * 16;
    int sStore = lr * 40 + lh * 16;

    uint32_t aSm = (uint32_t)__cvta_generic_to_shared(sA);
    uint32_t bSm = (uint32_t)__cvta_generic_to_shared(sB);
    uint32_t aFrag = (wm + (lane & 15)) * 80 + (lane >> 4) * 16;
    uint32_t bFrag = (wn + (lane >> 4) * 8 + (lane & 7)) * 80 + ((lane >> 3) & 1) * 16;

    float acc[4][4][4] = {};
    uint4 pa0, pa1, pb0, pb1;
    pa0 = *(const uint4*)(aRow);  pa1 = *(const uint4*)(aRow + 8);
    pb0 = *(const uint4*)(bRow);  pb1 = *(const uint4*)(bRow + 8);

    constexpr int KT = HID / 32;  // 24
    for (int it = 0; it < KT; it++) {
        int buf = it & 1;
        __nv_bfloat16* dA = sA + buf * 5120 + sStore;
        __nv_bfloat16* dB = sB + buf * 5120 + sStore;
        *(uint4*)dA = pa0;  *(uint4*)(dA + 8) = pa1;
        *(uint4*)dB = pb0;  *(uint4*)(dB + 8) = pb1;
        __syncthreads();
        if (it + 1 < KT) {
            int k0 = (it + 1) * 32;
            pa0 = *(const uint4*)(aRow + k0);  pa1 = *(const uint4*)(aRow + k0 + 8);
            pb0 = *(const uint4*)(bRow + k0);  pb1 = *(const uint4*)(bRow + k0 + 8);
        }
        uint32_t bufOff = buf * 10240;
#pragma unroll
        for (int ks = 0; ks < 2; ks++) {
            uint32_t af[4][4], bf[2][4];
#pragma unroll
            for (int mt = 0; mt < 4; mt++)
                ldm_x4(af[mt], aSm + bufOff + aFrag + mt * 1280 + ks * 32);
#pragma unroll
            for (int np = 0; np < 2; np++)
                ldm_x4(bf[np], bSm + bufOff + bFrag + np * 1280 + ks * 32);
#pragma unroll
            for (int mt = 0; mt < 4; mt++)
#pragma unroll
                for (int nt = 0; nt < 4; nt++) {
                    int np = nt >> 1, hf = (nt & 1) * 2;
                    mma_bf16(acc[mt][nt], af[mt], bf[np][hf], bf[np][hf + 1]);
                }
        }
        __syncthreads();
    }

    // epilogue: scatter-add (acc + b2) * weight into NCHW output
#pragma unroll
    for (int mt = 0; mt < 4; mt++) {
#pragma unroll
        for (int h = 0; h < 2; h++) {
            int rl = wm + mt * 16 + g + h * 8;
            float w = g_wgt[base + m0 + rl];
            if (w == 0.f) continue;
            int n = g_perm[base + m0 + rl];
            int b = n >> 10, l = n & 1023;
#pragma unroll
            for (int nt = 0; nt < 4; nt++) {
                int cl = n0 + wn + nt * 8 + tg * 2;
                float v0 = (acc[mt][nt][h * 2] + b2v[e * D + cl]) * w;
                float v1 = (acc[mt][nt][h * 2 + 1] + b2v[e * D + cl + 1]) * w;
                atomicAdd(&outx[((size_t)b * D + cl) * L + l], v0);
                atomicAdd(&outx[((size_t)b * D + cl + 1) * L + l], v1);
            }
        }
    }
}

// ------------------------- launch ---------------------------------------------------
extern "C" void kernel_launch(void* const* d_in, const int* in_sizes, int n_in,
                              void* d_out, int out_size) {
    const float* x      = (const float*)d_in[0];
    const float* dw1_w  = (const float*)d_in[1];
    const float* bn1_g  = (const float*)d_in[2];
    const float* bn1_b  = (const float*)d_in[3];
    const float* bn1_m  = (const float*)d_in[4];
    const float* bn1_v  = (const float*)d_in[5];
    const float* dw2_w  = (const float*)d_in[6];
    const float* bn2_g  = (const float*)d_in[7];
    const float* bn2_b  = (const float*)d_in[8];
    const float* bn2_m  = (const float*)d_in[9];
    const float* bn2_v  = (const float*)d_in[10];
    const float* ln_w   = (const float*)d_in[11];
    const float* ln_b   = (const float*)d_in[12];
    const float* bcdt_w = (const float*)d_in[13];
    const float* dws_w  = (const float*)d_in[14];
    const float* hproj_w= (const float*)d_in[15];
    // d_in[16] = A (cancels inside softmax over L)
    const float* gate_w = (const float*)d_in[17];
    const float* gate_b = (const float*)d_in[18];
    const float* w1     = (const float*)d_in[19];
    const float* b1     = (const float*)d_in[20];
    const float* w2     = (const float*)d_in[21];
    const float* b2     = (const float*)d_in[22];
    const float* w3     = (const float*)d_in[23];
    const float* b3     = (const float*)d_in[24];

    float* out_x = (float*)d_out;
    float* out_h = out_x + (size_t)Bsz * D * L;

    float* px1;    cudaGetSymbolAddress((void**)&px1, g_x1);
    float* pbcdt;  cudaGetSymbolAddress((void**)&pbcdt, g_bcdt);
    float* pbcdt2; cudaGetSymbolAddress((void**)&pbcdt2, g_bcdt2);
    float* px2;    cudaGetSymbolAddress((void**)&px2, g_x2);
    __nv_bfloat16 *pw1b, *pw3b, *pw2b;
    cudaGetSymbolAddress((void**)&pw1b, g_w1b);
    cudaGetSymbolAddress((void**)&pw3b, g_w3b);
    cudaGetSymbolAddress((void**)&pw2b, g_w2b);

    static bool attr_set = false;
    if (!attr_set) {
        cudaFuncSetAttribute(k_moe1, cudaFuncAttributeMaxDynamicSharedMemorySize, 61952);
        cudaFuncSetAttribute(k_moe2, cudaFuncAttributeMaxDynamicSharedMemorySize, 40960);
        attr_set = true;
    }

    k_init<<<1536, 256>>>();
    // weight conversions (independent of data path)
    constexpr int WN = E * HID * D;   // 2359296
    k_cvt<<<WN / 1024, 256>>>(w1, pw1b, WN);
    k_cvt<<<WN / 1024, 256>>>(w3, pw3b, WN);
    k_cvt<<<WN / 1024, 256>>>(w2, pw2b, WN);

    // x1 = x + bn1(dw1(x))
    k_dwconv<<<Bsz * D, 256>>>(x, dw1_w, bn1_g, bn1_b, bn1_m, bn1_v, px1, D, 1);
    // xn = LN(x1)
    k_ln<<<NTOK / 256, 256>>>(ln_w, ln_b);
    // bcdt
    k_gemm_bcdt<<<dim3(Bsz, 3, 8), 256>>>(bcdt_w);
    k_dwconv<<<Bsz * C3, 256>>>(pbcdt, dws_w, nullptr, nullptr, nullptr, nullptr, pbcdt2, C3, 0);
    k_softmax<<<Bsz * S, 256>>>();
    // h = xn @ (Am*Bm)^T
    k_gemm_h<<<dim3(Bsz, 6, 4), 256>>>();
    // h2 = silu(hproj @ h) -> second output
    k_hproj<<<dim3(Bsz, 6, 1), 256>>>(hproj_w, out_h);
    // x2 = x1 + h2 @ Cm
    k_gemm_y<<<dim3(Bsz, 6, 8), 256>>>(out_h);
    // x3 = x2 + bn2(dw2(x2)) -> first output (MoE adds on top)
    k_dwconv<<<Bsz * D, 256>>>(px2, dw2_w, bn2_g, bn2_b, bn2_m, bn2_v, out_x, D, 1);
    // tokens (fp32 + bf16)
    k_transpose<<<dim3(Bsz, 12, 32), 256>>>(out_x);
    // routing
    k_route<<<NTOK / 256, 256>>>(gate_w, gate_b);
    k_offsets<<<1, 1>>>();
    k_scatter<<<NTOK / 256, 256>>>();
    // MoE (bf16 tensor cores)
    k_moe1<<<dim3(E, 128, 6), 256, 61952>>>(b1, b3);
    k_moe2<<<dim3(E, 128, 3), 256, 40960>>>(b2, out_x);
}

// round 4
// speedup vs baseline: 3.4399x; 1.1436x over previous
#include <cuda_runtime.h>
#include <cuda_bf16.h>
#include <cstdint>

#define EPSV 1e-5f

constexpr int Bsz = 16, D = 384, L = 1024, S = 64, C3 = 192, E = 8, HID = 768;
constexpr int NTOK = Bsz * L;                    // 16384
constexpr int MAXSLOTS = 2 * NTOK + E * 128;     // 33792 (expert-padded)

// ------------------------- scratch (static device globals) -------------------------
__device__ float g_x1[Bsz * D * L];
__device__ float g_xn[Bsz * D * L];
__device__ float g_bcdt[Bsz * C3 * L];
__device__ float g_bcdt2[Bsz * C3 * L];
__device__ float g_ab[Bsz * S * L];
__device__ float g_h[Bsz * D * S];
__device__ float g_x2[Bsz * D * L];
__device__ float g_xT[NTOK * D];
__device__ __nv_bfloat16 g_xTb[NTOK * D];
__device__ __nv_bfloat16 g_heb[(size_t)MAXSLOTS * HID];
__device__ __nv_bfloat16 g_w1b[E * HID * D];
__device__ __nv_bfloat16 g_w3b[E * HID * D];
__device__ __nv_bfloat16 g_w2b[E * D * HID];
__device__ int   g_cnt[E];
__device__ int   g_cnt2[E];
__device__ int   g_off[E + 1];
__device__ int   g_topk_idx[NTOK * 2];
__device__ float g_topk_w[NTOK * 2];
__device__ int   g_perm[MAXSLOTS];
__device__ float g_wgt[MAXSLOTS];

// ------------------------- mma helpers ----------------------------------------------
__device__ __forceinline__ uint32_t f2tf32(float x) {
    uint32_t r;
    asm("cvt.rna.tf32.f32 %0, %1;" : "=r"(r) : "f"(x));
    return r;
}
__device__ __forceinline__ void mma_tf32(float c[4], uint32_t a0, uint32_t a1,
                                         uint32_t a2, uint32_t a3,
                                         uint32_t b0, uint32_t b1) {
    asm volatile(
        "mma.sync.aligned.m16n8k8.row.col.f32.tf32.tf32.f32 "
        "{%0,%1,%2,%3}, {%4,%5,%6,%7}, {%8,%9}, {%0,%1,%2,%3};"
        : "+f"(c[0]), "+f"(c[1]), "+f"(c[2]), "+f"(c[3])
        : "r"(a0), "r"(a1), "r"(a2), "r"(a3), "r"(b0), "r"(b1));
}
__device__ __forceinline__ void ldm_x4(uint32_t* r, uint32_t addr) {
    asm volatile("ldmatrix.sync.aligned.m8n8.x4.shared.b16 {%0,%1,%2,%3}, [%4];"
                 : "=r"(r[0]), "=r"(r[1]), "=r"(r[2]), "=r"(r[3]) : "r"(addr));
}
__device__ __forceinline__ void mma_bf16(float c[4], const uint32_t a[4],
                                         uint32_t b0, uint32_t b1) {
    asm volatile(
        "mma.sync.aligned.m16n8k16.row.col.f32.bf16.bf16.f32 "
        "{%0,%1,%2,%3}, {%4,%5,%6,%7}, {%8,%9}, {%0,%1,%2,%3};"
        : "+f"(c[0]), "+f"(c[1]), "+f"(c[2]), "+f"(c[3])
        : "r"(a[0]), "r"(a[1]), "r"(a[2]), "r"(a[3]), "r"(b0), "r"(b1));
}

// ------------------------- init ------------------------------------------------------
__global__ void k_init() {
    int i = blockIdx.x * 256 + threadIdx.x;
    if (i < MAXSLOTS) { g_wgt[i] = 0.f; g_perm[i] = 0; }
    if (i < E) g_cnt[i] = 0;
    if (i < Bsz * D * S) g_h[i] = 0.f;
}

// ------------------------- fp32 -> bf16 convert --------------------------------------
__global__ void k_cvt(const float* __restrict__ s, __nv_bfloat16* __restrict__ d, int n) {
    int i = (blockIdx.x * 256 + threadIdx.x) * 4;
    if (i < n) {
        float4 v = *(const float4*)(s + i);
        *(__nv_bfloat162*)(d + i)     = __float22bfloat162_rn(make_float2(v.x, v.y));
        *(__nv_bfloat162*)(d + i + 2) = __float22bfloat162_rn(make_float2(v.z, v.w));
    }
}

// ------------------------- depthwise 3x3 (+optional BN, +optional residual) ----------
__global__ void k_dwconv(const float* __restrict__ in, const float* __restrict__ w9,
                         const float* __restrict__ g, const float* __restrict__ bb,
                         const float* __restrict__ m, const float* __restrict__ v,
                         float* __restrict__ out, int C, int residual) {
    __shared__ float s[34 * 34];
    int b = blockIdx.x / C, c = blockIdx.x % C;
    const float* ip = in + (size_t)(b * C + c) * L;
    int tid = threadIdx.x;
    for (int idx = tid; idx < 34 * 34; idx += 256) {
        int r = idx / 34 - 1, cc = idx % 34 - 1;
        s[idx] = (r >= 0 && r < 32 && cc >= 0 && cc < 32) ? ip[r * 32 + cc] : 0.f;
    }
    __syncthreads();
    float w[9];
#pragma unroll
    for (int i = 0; i < 9; i++) w[i] = w9[c * 9 + i];
    float sc = 1.f, sh = 0.f;
    if (g) { sc = g[c] * rsqrtf(v[c] + EPSV); sh = bb[c] - m[c] * sc; }
    float* op = out + (size_t)(b * C + c) * L;
    for (int idx = tid; idx < 1024; idx += 256) {
        int r = idx >> 5, cc = idx & 31;
        float acc = 0.f;
#pragma unroll
        for (int kr = 0; kr < 3; kr++)
#pragma unroll
            for (int kc = 0; kc < 3; kc++)
                acc += w[kr * 3 + kc] * s[(r + kr) * 34 + cc + kc];
        float val = sc * acc + sh;
        if (residual) val += s[(r + 1) * 34 + cc + 1];
        op[idx] = val;
    }
}

// ------------------------- LayerNorm over channel dim --------------------------------
__global__ void k_ln(const float* __restrict__ lnw, const float* __restrict__ lnb) {
    int gi = blockIdx.x * 256 + threadIdx.x;
    int b = gi >> 10, l = gi & 1023;
    const float* p = g_x1 + (size_t)b * D * L + l;
    float sum = 0.f, sq = 0.f;
    for (int d = 0; d < D; d++) { float x = p[(size_t)d * L]; sum += x; sq += x * x; }
    float mu = sum * (1.f / D);
    float var = sq * (1.f / D) - mu * mu;
    float inv = rsqrtf(var + EPSV);
    float* o = g_xn + (size_t)b * D * L + l;
    for (int d = 0; d < D; d++)
        o[(size_t)d * L] = (p[(size_t)d * L] - mu) * inv * lnw[d] + lnb[d];
}

// --------------- bcdt = bcdt_w @ xn_b  (tf32 mma, 64x128 tiles, K=384) ---------------
__global__ __launch_bounds__(256) void k_gemm_bcdt(const float* __restrict__ Wm) {
    __shared__ uint32_t As[64][17];
    __shared__ uint32_t Bs[128][17];
    int b = blockIdx.x, m0 = blockIdx.y * 64, n0 = blockIdx.z * 128;
    int tid = threadIdx.x, lane = tid & 31, wid = tid >> 5;
    int wm = (wid & 1) * 32, wn = (wid >> 1) * 32;
    int g = lane >> 2, tg = lane & 3;
    const float* Bp = g_xn + (size_t)b * D * L;

    int mA = tid >> 2, kqA = tid & 3;            // A: 64 rows x 4 float4
    int nB = (tid & 31) * 4, kB = tid >> 5;      // B: per pass, k = kB + p*8

    float acc[2][4][4] = {};
    float4 ra, rb0, rb1;
    ra  = *(const float4*)&Wm[(size_t)(m0 + mA) * 384 + kqA * 4];
    rb0 = *(const float4*)&Bp[(size_t)kB * L + n0 + nB];
    rb1 = *(const float4*)&Bp[(size_t)(kB + 8) * L + n0 + nB];

    for (int it = 0; it < 24; it++) {
        As[mA][kqA * 4 + 0] = f2tf32(ra.x); As[mA][kqA * 4 + 1] = f2tf32(ra.y);
        As[mA][kqA * 4 + 2] = f2tf32(ra.z); As[mA][kqA * 4 + 3] = f2tf32(ra.w);
        Bs[nB + 0][kB] = f2tf32(rb0.x); Bs[nB + 1][kB] = f2tf32(rb0.y);
        Bs[nB + 2][kB] = f2tf32(rb0.z); Bs[nB + 3][kB] = f2tf32(rb0.w);
        Bs[nB + 0][kB + 8] = f2tf32(rb1.x); Bs[nB + 1][kB + 8] = f2tf32(rb1.y);
        Bs[nB + 2][kB + 8] = f2tf32(rb1.z); Bs[nB + 3][kB + 8] = f2tf32(rb1.w);
        __syncthreads();
        if (it + 1 < 24) {
            int k0 = (it + 1) * 16;
            ra  = *(const float4*)&Wm[(size_t)(m0 + mA) * 384 + k0 + kqA * 4];
            rb0 = *(const float4*)&Bp[(size_t)(k0 + kB) * L + n0 + nB];
            rb1 = *(const float4*)&Bp[(size_t)(k0 + kB + 8) * L + n0 + nB];
        }
#pragma unroll
        for (int ks = 0; ks < 16; ks += 8) {
            uint32_t af[2][4], bf[4][2];
#pragma unroll
            for (int mt = 0; mt < 2; mt++) {
                int r = wm + mt * 16 + g;
                af[mt][0] = As[r][ks + tg];     af[mt][1] = As[r + 8][ks + tg];
                af[mt][2] = As[r][ks + 4 + tg]; af[mt][3] = As[r + 8][ks + 4 + tg];
            }
#pragma unroll
            for (int nt = 0; nt < 4; nt++) {
                int c = wn + nt * 8 + g;
                bf[nt][0] = Bs[c][ks + tg]; bf[nt][1] = Bs[c][ks + 4 + tg];
            }
#pragma unroll
            for (int mt = 0; mt < 2; mt++)
#pragma unroll
                for (int nt = 0; nt < 4; nt++)
                    mma_tf32(acc[mt][nt], af[mt][0], af[mt][1], af[mt][2], af[mt][3],
                             bf[nt][0], bf[nt][1]);
        }
        __syncthreads();
    }
    float* Cp = g_bcdt + (size_t)b * C3 * L;
#pragma unroll
    for (int mt = 0; mt < 2; mt++)
#pragma unroll
        for (int h = 0; h < 2; h++) {
            int row = m0 + wm + mt * 16 + g + h * 8;
#pragma unroll
            for (int nt = 0; nt < 4; nt++) {
                int col = n0 + wn + nt * 8 + tg * 2;
                Cp[(size_t)row * L + col]     = acc[mt][nt][h * 2];
                Cp[(size_t)row * L + col + 1] = acc[mt][nt][h * 2 + 1];
            }
        }
}

// ------------------------- softmax over L + *Bm --------------------------------------
__global__ void k_softmax() {
    int b = blockIdx.x >> 6, s = blockIdx.x & 63;
    const float* dt = g_bcdt2 + ((size_t)b * C3 + 2 * S + s) * L;
    const float* Bm = g_bcdt2 + ((size_t)b * C3 + s) * L;
    float* ab = g_ab + ((size_t)b * S + s) * L;
    int tid = threadIdx.x;
    __shared__ float red[256];
    float vals[4]; float mx = -1e30f;
#pragma unroll
    for (int i = 0; i < 4; i++) { vals[i] = dt[tid + i * 256]; mx = fmaxf(mx, vals[i]); }
    red[tid] = mx; __syncthreads();
    for (int o = 128; o > 0; o >>= 1) { if (tid < o) red[tid] = fmaxf(red[tid], red[tid + o]); __syncthreads(); }
    mx = red[0]; __syncthreads();
    float e[4]; float sum = 0.f;
#pragma unroll
    for (int i = 0; i < 4; i++) { e[i] = __expf(vals[i] - mx); sum += e[i]; }
    red[tid] = sum; __syncthreads();
    for (int o = 128; o > 0; o >>= 1) { if (tid < o) red[tid] += red[tid + o]; __syncthreads(); }
    float inv = 1.f / red[0];
#pragma unroll
    for (int i = 0; i < 4; i++) ab[tid + i * 256] = e[i] * inv * Bm[tid + i * 256];
}

// ----------- h[b,d,s] = sum_l xn*ab  (tf32 mma, 128x64 tile, split-K=4) --------------
__global__ __launch_bounds__(256) void k_gemm_h() {
    __shared__ uint32_t As[128][17];
    __shared__ uint32_t Bs[64][17];
    int b = blockIdx.x, m0 = blockIdx.y * 128, kc = blockIdx.z;
    int tid = threadIdx.x, lane = tid & 31, wid = tid >> 5;
    int wm = (wid & 3) * 32, wn = (wid >> 2) * 32;
    int g = lane >> 2, tg = lane & 3;
    const float* Ap = g_xn + (size_t)b * D * L;
    const float* Bp = g_ab + (size_t)b * S * L;

    int mA = tid >> 1, kqA = (tid & 1) * 2;      // 2 float4 per thread
    int nB = tid >> 2, kqB = tid & 3;

    float acc[2][4][4] = {};
    float4 ra0, ra1, rb;
    int kbase = kc * 256;
    ra0 = *(const float4*)&Ap[(size_t)(m0 + mA) * L + kbase + kqA * 4];
    ra1 = *(const float4*)&Ap[(size_t)(m0 + mA) * L + kbase + kqA * 4 + 4];
    rb  = *(const float4*)&Bp[(size_t)nB * L + kbase + kqB * 4];

    for (int it = 0; it < 16; it++) {
        As[mA][kqA * 4 + 0] = f2tf32(ra0.x); As[mA][kqA * 4 + 1] = f2tf32(ra0.y);
        As[mA][kqA * 4 + 2] = f2tf32(ra0.z); As[mA][kqA * 4 + 3] = f2tf32(ra0.w);
        As[mA][kqA * 4 + 4] = f2tf32(ra1.x); As[mA][kqA * 4 + 5] = f2tf32(ra1.y);
        As[mA][kqA * 4 + 6] = f2tf32(ra1.z); As[mA][kqA * 4 + 7] = f2tf32(ra1.w);
        Bs[nB][kqB * 4 + 0] = f2tf32(rb.x); Bs[nB][kqB * 4 + 1] = f2tf32(rb.y);
        Bs[nB][kqB * 4 + 2] = f2tf32(rb.z); Bs[nB][kqB * 4 + 3] = f2tf32(rb.w);
        __syncthreads();
        if (it + 1 < 16) {
            int k0 = kbase + (it + 1) * 16;
            ra0 = *(const float4*)&Ap[(size_t)(m0 + mA) * L + k0 + kqA * 4];
            ra1 = *(const float4*)&Ap[(size_t)(m0 + mA) * L + k0 + kqA * 4 + 4];
            rb  = *(const float4*)&Bp[(size_t)nB * L + k0 + kqB * 4];
        }
#pragma unroll
        for (int ks = 0; ks < 16; ks += 8) {
            uint32_t af[2][4], bf[4][2];
#pragma unroll
            for (int mt = 0; mt < 2; mt++) {
                int r = wm + mt * 16 + g;
                af[mt][0] = As[r][ks + tg];     af[mt][1] = As[r + 8][ks + tg];
                af[mt][2] = As[r][ks + 4 + tg]; af[mt][3] = As[r + 8][ks + 4 + tg];
            }
#pragma unroll
            for (int nt = 0; nt < 4; nt++) {
                int c = wn + nt * 8 + g;
                bf[nt][0] = Bs[c][ks + tg]; bf[nt][1] = Bs[c][ks + 4 + tg];
            }
#pragma unroll
            for (int mt = 0; mt < 2; mt++)
#pragma unroll
                for (int nt = 0; nt < 4; nt++)
                    mma_tf32(acc[mt][nt], af[mt][0], af[mt][1], af[mt][2], af[mt][3],
                             bf[nt][0], bf[nt][1]);
        }
        __syncthreads();
    }
    float* Cp = g_h + (size_t)b * D * S;
#pragma unroll
    for (int mt = 0; mt < 2; mt++)
#pragma unroll
        for (int h = 0; h < 2; h++) {
            int row = m0 + wm + mt * 16 + g + h * 8;
#pragma unroll
            for (int nt = 0; nt < 4; nt++) {
                int col = wn + nt * 8 + tg * 2;
                atomicAdd(&Cp[(size_t)row * S + col],     acc[mt][nt][h * 2]);
                atomicAdd(&Cp[(size_t)row * S + col + 1], acc[mt][nt][h * 2 + 1]);
            }
        }
}

// ------------------------- h2 = silu(hproj @ h) -> out_h -----------------------------
__global__ void k_hproj(const float* __restrict__ Wp, float* __restrict__ outh) {
    __shared__ float As[8][68], Bs[8][68];
    int b = blockIdx.x, m0 = blockIdx.y * 64;
    int tid = threadIdx.x, tx = tid & 15, ty = tid >> 4;
    const float* Bp = g_h + (size_t)b * D * S;
    float acc[4][4] = {};
    for (int k0 = 0; k0 < 384; k0 += 8) {
        for (int p = 0; p < 2; p++) {
            int idx = tid + p * 256; int mm = idx >> 3, kk = idx & 7;
            As[kk][mm] = Wp[(size_t)(m0 + mm) * 384 + k0 + kk];
        }
        for (int p = 0; p < 2; p++) {
            int idx = tid + p * 256; int kk = idx >> 6, nn = idx & 63;
            Bs[kk][nn] = Bp[(size_t)(k0 + kk) * S + nn];
        }
        __syncthreads();
#pragma unroll
        for (int k = 0; k < 8; k++) {
            float a[4], bv[4];
#pragma unroll
            for (int i = 0; i < 4; i++) a[i] = As[k][ty + i * 16];
#pragma unroll
            for (int j = 0; j < 4; j++) bv[j] = Bs[k][tx + j * 16];
#pragma unroll
            for (int i = 0; i < 4; i++)
#pragma unroll
                for (int j = 0; j < 4; j++) acc[i][j] += a[i] * bv[j];
        }
        __syncthreads();
    }
    float* Cp = outh + (size_t)b * D * S;
    for (int i = 0; i < 4; i++)
        for (int j = 0; j < 4; j++) {
            float x = acc[i][j];
            Cp[(size_t)(m0 + ty + i * 16) * S + tx + j * 16] = x / (1.f + __expf(-x));
        }
}

// ------------- x2 = x1 + h2 @ Cm  (tf32 mma, 128x128 tiles, K=64) --------------------
__global__ __launch_bounds__(256) void k_gemm_y(const float* __restrict__ outh) {
    __shared__ uint32_t As[128][17];
    __shared__ uint32_t Bs[128][17];
    int b = blockIdx.x, m0 = blockIdx.y * 128, n0 = blockIdx.z * 128;
    int tid = threadIdx.x, lane = tid & 31, wid = tid >> 5;
    int wm = (wid & 1) * 64, wn = (wid >> 1) * 32;
    int g = lane >> 2, tg = lane & 3;
    const float* Ap = outh + (size_t)b * D * S;
    const float* Bp = g_bcdt2 + ((size_t)b * C3 + S) * L;    // Cm

    int mA = tid >> 1, kqA = (tid & 1) * 2;
    int nB = (tid & 31) * 4, kB = tid >> 5;

    float acc[4][4][4] = {};
    float4 ra0, ra1, rb0, rb1;
    ra0 = *(const float4*)&Ap[(size_t)(m0 + mA) * S + kqA * 4];
    ra1 = *(const float4*)&Ap[(size_t)(m0 + mA) * S + kqA * 4 + 4];
    rb0 = *(const float4*)&Bp[(size_t)kB * L + n0 + nB];
    rb1 = *(const float4*)&Bp[(size_t)(kB + 8) * L + n0 + nB];

    for (int it = 0; it < 4; it++) {
        As[mA][kqA * 4 + 0] = f2tf32(ra0.x); As[mA][kqA * 4 + 1] = f2tf32(ra0.y);
        As[mA][kqA * 4 + 2] = f2tf32(ra0.z); As[mA][kqA * 4 + 3] = f2tf32(ra0.w);
        As[mA][kqA * 4 + 4] = f2tf32(ra1.x); As[mA][kqA * 4 + 5] = f2tf32(ra1.y);
        As[mA][kqA * 4 + 6] = f2tf32(ra1.z); As[mA][kqA * 4 + 7] = f2tf32(ra1.w);
        Bs[nB + 0][kB] = f2tf32(rb0.x); Bs[nB + 1][kB] = f2tf32(rb0.y);
        Bs[nB + 2][kB] = f2tf32(rb0.z); Bs[nB + 3][kB] = f2tf32(rb0.w);
        Bs[nB + 0][kB + 8] = f2tf32(rb1.x); Bs[nB + 1][kB + 8] = f2tf32(rb1.y);
        Bs[nB + 2][kB + 8] = f2tf32(rb1.z); Bs[nB + 3][kB + 8] = f2tf32(rb1.w);
        __syncthreads();
        if (it + 1 < 4) {
            int k0 = (it + 1) * 16;
            ra0 = *(const float4*)&Ap[(size_t)(m0 + mA) * S + k0 + kqA * 4];
            ra1 = *(const float4*)&Ap[(size_t)(m0 + mA) * S + k0 + kqA * 4 + 4];
            rb0 = *(const float4*)&Bp[(size_t)(k0 + kB) * L + n0 + nB];
            rb1 = *(const float4*)&Bp[(size_t)(k0 + kB + 8) * L + n0 + nB];
        }
#pragma unroll
        for (int ks = 0; ks < 16; ks += 8) {
            uint32_t af[4][4], bf[4][2];
#pragma unroll
            for (int mt = 0; mt < 4; mt++) {
                int r = wm + mt * 16 + g;
                af[mt][0] = As[r][ks + tg];     af[mt][1] = As[r + 8][ks + tg];
                af[mt][2] = As[r][ks + 4 + tg]; af[mt][3] = As[r + 8][ks + 4 + tg];
            }
#pragma unroll
            for (int nt = 0; nt < 4; nt++) {
                int c = wn + nt * 8 + g;
                bf[nt][0] = Bs[c][ks + tg]; bf[nt][1] = Bs[c][ks + 4 + tg];
            }
#pragma unroll
            for (int mt = 0; mt < 4; mt++)
#pragma unroll
                for (int nt = 0; nt < 4; nt++)
                    mma_tf32(acc[mt][nt], af[mt][0], af[mt][1], af[mt][2], af[mt][3],
                             bf[nt][0], bf[nt][1]);
        }
        __syncthreads();
    }
#pragma unroll
    for (int mt = 0; mt < 4; mt++)
#pragma unroll
        for (int h = 0; h < 2; h++) {
            int row = m0 + wm + mt * 16 + g + h * 8;
#pragma unroll
            for (int nt = 0; nt < 4; nt++) {
                int col = n0 + wn + nt * 8 + tg * 2;
                size_t o = (size_t)b * D * L + (size_t)row * L + col;
                g_x2[o]     = g_x1[o]     + acc[mt][nt][h * 2];
                g_x2[o + 1] = g_x1[o + 1] + acc[mt][nt][h * 2 + 1];
            }
        }
}

// ------------------------- NCHW -> token-major transpose (fp32 + bf16) ---------------
__global__ void k_transpose(const float* __restrict__ xin) {
    __shared__ float s[32][33];
    int b = blockIdx.x, d0 = blockIdx.y * 32, l0 = blockIdx.z * 32;
    int c = threadIdx.x & 31, r0 = threadIdx.x >> 5;
    for (int i = 0; i < 32; i += 8)
        s[r0 + i][c] = xin[((size_t)b * D + d0 + r0 + i) * L + l0 + c];
    __syncthreads();
    for (int i = 0; i < 32; i += 8) {
        float v = s[c][r0 + i];
        size_t o = ((size_t)b * L + l0 + r0 + i) * D + d0 + c;
        g_xT[o] = v;
        g_xTb[o] = __float2bfloat16(v);
    }
}

// ------------------------- router (warp per token, coalesced) ------------------------
__global__ void k_route(const float* __restrict__ gw, const float* __restrict__ gb) {
    __shared__ float sg[E * D];
    int tid = threadIdx.x, lane = tid & 31, wid = tid >> 5;
    for (int i = tid; i < E * D; i += 256) sg[i] = gw[i];
    __syncthreads();
    int n = blockIdx.x * 8 + wid;
    const float* t = g_xT + (size_t)n * D;
    float lg[E] = {};
#pragma unroll
    for (int j = 0; j < 12; j++) {
        float x = t[lane + j * 32];
        int d = lane + j * 32;
#pragma unroll
        for (int e = 0; e < E; e++) lg[e] += sg[e * D + d] * x;
    }
#pragma unroll
    for (int e = 0; e < E; e++) {
        float v = lg[e];
#pragma unroll
        for (int o = 16; o > 0; o >>= 1) v += __shfl_xor_sync(0xffffffff, v, o);
        lg[e] = v;
    }
    if (lane == 0) {
#pragma unroll
        for (int e = 0; e < E; e++) lg[e] += gb[e];
        int i0 = 0; float v0 = lg[0];
#pragma unroll
        for (int e = 1; e < E; e++) if (lg[e] > v0) { v0 = lg[e]; i0 = e; }
        int i1 = -1; float v1 = -1e30f;
#pragma unroll
        for (int e = 0; e < E; e++) if (e != i0 && lg[e] > v1) { v1 = lg[e]; i1 = e; }
        float p0 = 1.f / (1.f + __expf(v1 - v0));
        g_topk_idx[n * 2] = i0; g_topk_idx[n * 2 + 1] = i1;
        g_topk_w[n * 2] = p0;   g_topk_w[n * 2 + 1] = 1.f - p0;
        atomicAdd(&g_cnt[i0], 1); atomicAdd(&g_cnt[i1], 1);
    }
}

__global__ void k_offsets() {
    int off = 0;
    for (int e = 0; e < E; e++) {
        g_off[e] = off;
        off += (g_cnt[e] + 127) & ~127;
        g_cnt2[e] = 0;
    }
    g_off[E] = off;
}

__global__ void k_scatter() {
    int n = blockIdx.x * 256 + threadIdx.x;
#pragma unroll
    for (int k = 0; k < 2; k++) {
        int e = g_topk_idx[n * 2 + k];
        int pos = g_off[e] + atomicAdd(&g_cnt2[e], 1);
        g_perm[pos] = n;
        g_wgt[pos] = g_topk_w[n * 2 + k];
    }
}

// ------------------- MoE GEMM1 (bf16 mma): he = silu(t@w1+b1)*(t@w3+b3) --------------
__global__ __launch_bounds__(256) void k_moe1(
        const float* __restrict__ B1, const float* __restrict__ B3) {
    extern __shared__ char sm[];
    __nv_bfloat16* sA  = (__nv_bfloat16*)sm;
    __nv_bfloat16* sB1 = (__nv_bfloat16*)(sm + 20480);
    __nv_bfloat16* sB3 = (__nv_bfloat16*)(sm + 40960);
    int* sperm = (int*)(sm + 61440);

    int e = blockIdx.x;
    int cnt = g_cnt[e];
    int m0 = blockIdx.y * 128;
    if (m0 >= cnt) return;
    int base = g_off[e];
    int n0 = blockIdx.z * 128;

    int tid = threadIdx.x, lane = tid & 31, wid = tid >> 5;
    int wm = (wid & 1) * 64, wn = (wid >> 1) * 32;
    int g = lane >> 2, tg = lane & 3;

    if (tid < 128) sperm[tid] = g_perm[base + m0 + tid];
    __syncthreads();

    int lr = tid >> 1, lh = tid & 1;
    const __nv_bfloat16* aRow  = g_xTb + (size_t)sperm[lr] * D + lh * 16;
    const __nv_bfloat16* b1Row = g_w1b + ((size_t)e * HID + n0 + lr) * D + lh * 16;
    const __nv_bfloat16* b3Row = g_w3b + ((size_t)e * HID + n0 + lr) * D + lh * 16;
    int sStore = lr * 40 + lh * 16;

    uint32_t aSm  = (uint32_t)__cvta_generic_to_shared(sA);
    uint32_t b1Sm = (uint32_t)__cvta_generic_to_shared(sB1);
    uint32_t b3Sm = (uint32_t)__cvta_generic_to_shared(sB3);
    uint32_t aFrag = (wm + (lane & 15)) * 80 + (lane >> 4) * 16;
    uint32_t bFrag = (wn + (lane >> 4) * 8 + (lane & 7)) * 80 + ((lane >> 3) & 1) * 16;

    float acc1[4][4][4] = {}, acc3[4][4][4] = {};
    uint4 pa0, pa1, pb10, pb11, pb30, pb31;
    pa0  = *(const uint4*)(aRow);      pa1  = *(const uint4*)(aRow + 8);
    pb10 = *(const uint4*)(b1Row);     pb11 = *(const uint4*)(b1Row + 8);
    pb30 = *(const uint4*)(b3Row);     pb31 = *(const uint4*)(b3Row + 8);

    constexpr int KT = D / 32;
    for (int it = 0; it < KT; it++) {
        int buf = it & 1;
        __nv_bfloat16* dA  = sA  + buf * 5120 + sStore;
        __nv_bfloat16* dB1 = sB1 + buf * 5120 + sStore;
        __nv_bfloat16* dB3 = sB3 + buf * 5120 + sStore;
        *(uint4*)dA = pa0;        *(uint4*)(dA + 8) = pa1;
        *(uint4*)dB1 = pb10;      *(uint4*)(dB1 + 8) = pb11;
        *(uint4*)dB3 = pb30;      *(uint4*)(dB3 + 8) = pb31;
        __syncthreads();
        if (it + 1 < KT) {
            int k0 = (it + 1) * 32;
            pa0  = *(const uint4*)(aRow + k0);      pa1  = *(const uint4*)(aRow + k0 + 8);
            pb10 = *(const uint4*)(b1Row + k0);     pb11 = *(const uint4*)(b1Row + k0 + 8);
            pb30 = *(const uint4*)(b3Row + k0);     pb31 = *(const uint4*)(b3Row + k0 + 8);
        }
        uint32_t bufOff = buf * 10240;
#pragma unroll
        for (int ks = 0; ks < 2; ks++) {
            uint32_t af[4][4], bf1[2][4], bf3[2][4];
#pragma unroll
            for (int mt = 0; mt < 4; mt++)
                ldm_x4(af[mt], aSm + bufOff + aFrag + mt * 1280 + ks * 32);
#pragma unroll
            for (int np = 0; np < 2; np++) {
                ldm_x4(bf1[np], b1Sm + bufOff + bFrag + np * 1280 + ks * 32);
                ldm_x4(bf3[np], b3Sm + bufOff + bFrag + np * 1280 + ks * 32);
            }
#pragma unroll
            for (int mt = 0; mt < 4; mt++)
#pragma unroll
                for (int nt = 0; nt < 4; nt++) {
                    int np = nt >> 1, hf = (nt & 1) * 2;
                    mma_bf16(acc1[mt][nt], af[mt], bf1[np][hf], bf1[np][hf + 1]);
                    mma_bf16(acc3[mt][nt], af[mt], bf3[np][hf], bf3[np][hf + 1]);
                }
        }
        __syncthreads();
    }

#pragma unroll
    for (int mt = 0; mt < 4; mt++) {
#pragma unroll
        for (int nt = 0; nt < 4; nt++) {
            int cl = n0 + wn + nt * 8 + tg * 2;
            float bb1a = B1[e * HID + cl], bb1b = B1[e * HID + cl + 1];
            float bb3a = B3[e * HID + cl], bb3b = B3[e * HID + cl + 1];
#pragma unroll
            for (int h = 0; h < 2; h++) {
                int rl = wm + mt * 16 + g + h * 8;
                float x1a = acc1[mt][nt][h * 2] + bb1a;
                float x1b = acc1[mt][nt][h * 2 + 1] + bb1b;
                float x3a = acc3[mt][nt][h * 2] + bb3a;
                float x3b = acc3[mt][nt][h * 2 + 1] + bb3b;
                float oa = (x1a / (1.f + __expf(-x1a))) * x3a;
                float ob = (x1b / (1.f + __expf(-x1b))) * x3b;
                *(__nv_bfloat162*)&g_heb[(size_t)(base + m0 + rl) * HID + cl] =
                    __float22bfloat162_rn(make_float2(oa, ob));
            }
        }
    }
}

// ------------------- MoE GEMM2 (bf16 mma): out += (he@w2+b2)*w (scatter) -------------
__global__ __launch_bounds__(256) void k_moe2(
        const float* __restrict__ b2v, float* __restrict__ outx) {
    extern __shared__ char sm[];
    __nv_bfloat16* sA = (__nv_bfloat16*)sm;
    __nv_bfloat16* sB = (__nv_bfloat16*)(sm + 20480);

    int e = blockIdx.x;
    int cnt = g_cnt[e];
    int m0 = blockIdx.y * 128;
    if (m0 >= cnt) return;
    int base = g_off[e];
    int n0 = blockIdx.z * 128;

    int tid = threadIdx.x, lane = tid & 31, wid = tid >> 5;
    int wm = (wid & 1) * 64, wn = (wid >> 1) * 32;
    int g = lane >> 2, tg = lane & 3;

    int lr = tid >> 1, lh = tid & 1;
    const __nv_bfloat16* aRow = g_heb + (size_t)(base + m0 + lr) * HID + lh * 16;
    const __nv_bfloat16* bRow = g_w2b + ((size_t)e * D + n0 + lr) * HID + lh * 16;
    int sStore = lr * 40 + lh * 16;

    uint32_t aSm = (uint32_t)__cvta_generic_to_shared(sA);
    uint32_t bSm = (uint32_t)__cvta_generic_to_shared(sB);
    uint32_t aFrag = (wm + (lane & 15)) * 80 + (lane >> 4) * 16;
    uint32_t bFrag = (wn + (lane >> 4) * 8 + (lane & 7)) * 80 + ((lane >> 3) & 1) * 16;

    float acc[4][4][4] = {};
    uint4 pa0, pa1, pb0, pb1;
    pa0 = *(const uint4*)(aRow);  pa1 = *(const uint4*)(aRow + 8);
    pb0 = *(const uint4*)(bRow);  pb1 = *(const uint4*)(bRow + 8);

    constexpr int KT = HID / 32;
    for (int it = 0; it < KT; it++) {
        int buf = it & 1;
        __nv_bfloat16* dA = sA + buf * 5120 + sStore;
        __nv_bfloat16* dB = sB + buf * 5120 + sStore;
        *(uint4*)dA = pa0;  *(uint4*)(dA + 8) = pa1;
        *(uint4*)dB = pb0;  *(uint4*)(dB + 8) = pb1;
        __syncthreads();
        if (it + 1 < KT) {
            int k0 = (it + 1) * 32;
            pa0 = *(const uint4*)(aRow + k0);  pa1 = *(const uint4*)(aRow + k0 + 8);
            pb0 = *(const uint4*)(bRow + k0);  pb1 = *(const uint4*)(bRow + k0 + 8);
        }
        uint32_t bufOff = buf * 10240;
#pragma unroll
        for (int ks = 0; ks < 2; ks++) {
            uint32_t af[4][4], bf[2][4];
#pragma unroll
            for (int mt = 0; mt < 4; mt++)
                ldm_x4(af[mt], aSm + bufOff + aFrag + mt * 1280 + ks * 32);
#pragma unroll
            for (int np = 0; np < 2; np++)
                ldm_x4(bf[np], bSm + bufOff + bFrag + np * 1280 + ks * 32);
#pragma unroll
            for (int mt = 0; mt < 4; mt++)
#pragma unroll
                for (int nt = 0; nt < 4; nt++) {
                    int np = nt >> 1, hf = (nt & 1) * 2;
                    mma_bf16(acc[mt][nt], af[mt], bf[np][hf], bf[np][hf + 1]);
                }
        }
        __syncthreads();
    }

#pragma unroll
    for (int mt = 0; mt < 4; mt++) {
#pragma unroll
        for (int h = 0; h < 2; h++) {
            int rl = wm + mt * 16 + g + h * 8;
            float w = g_wgt[base + m0 + rl];
            if (w == 0.f) continue;
            int n = g_perm[base + m0 + rl];
            int b = n >> 10, l = n & 1023;
#pragma unroll
            for (int nt = 0; nt < 4; nt++) {
                int cl = n0 + wn + nt * 8 + tg * 2;
                float v0 = (acc[mt][nt][h * 2] + b2v[e * D + cl]) * w;
                float v1 = (acc[mt][nt][h * 2 + 1] + b2v[e * D + cl + 1]) * w;
                atomicAdd(&outx[((size_t)b * D + cl) * L + l], v0);
                atomicAdd(&outx[((size_t)b * D + cl + 1) * L + l], v1);
            }
        }
    }
}

// ------------------------- launch ---------------------------------------------------
extern "C" void kernel_launch(void* const* d_in, const int* in_sizes, int n_in,
                              void* d_out, int out_size) {
    const float* x      = (const float*)d_in[0];
    const float* dw1_w  = (const float*)d_in[1];
    const float* bn1_g  = (const float*)d_in[2];
    const float* bn1_b  = (const float*)d_in[3];
    const float* bn1_m  = (const float*)d_in[4];
    const float* bn1_v  = (const float*)d_in[5];
    const float* dw2_w  = (const float*)d_in[6];
    const float* bn2_g  = (const float*)d_in[7];
    const float* bn2_b  = (const float*)d_in[8];
    const float* bn2_m  = (const float*)d_in[9];
    const float* bn2_v  = (const float*)d_in[10];
    const float* ln_w   = (const float*)d_in[11];
    const float* ln_b   = (const float*)d_in[12];
    const float* bcdt_w = (const float*)d_in[13];
    const float* dws_w  = (const float*)d_in[14];
    const float* hproj_w= (const float*)d_in[15];
    // d_in[16] = A (cancels inside softmax over L)
    const float* gate_w = (const float*)d_in[17];
    const float* gate_b = (const float*)d_in[18];
    const float* w1     = (const float*)d_in[19];
    const float* b1     = (const float*)d_in[20];
    const float* w2     = (const float*)d_in[21];
    const float* b2     = (const float*)d_in[22];
    const float* w3     = (const float*)d_in[23];
    const float* b3     = (const float*)d_in[24];

    float* out_x = (float*)d_out;
    float* out_h = out_x + (size_t)Bsz * D * L;

    float* px1;    cudaGetSymbolAddress((void**)&px1, g_x1);
    float* pbcdt;  cudaGetSymbolAddress((void**)&pbcdt, g_bcdt);
    float* pbcdt2; cudaGetSymbolAddress((void**)&pbcdt2, g_bcdt2);
    float* px2;    cudaGetSymbolAddress((void**)&px2, g_x2);
    __nv_bfloat16 *pw1b, *pw3b, *pw2b;
    cudaGetSymbolAddress((void**)&pw1b, g_w1b);
    cudaGetSymbolAddress((void**)&pw3b, g_w3b);
    cudaGetSymbolAddress((void**)&pw2b, g_w2b);

    static bool attr_set = false;
    if (!attr_set) {
        cudaFuncSetAttribute(k_moe1, cudaFuncAttributeMaxDynamicSharedMemorySize, 61952);
        cudaFuncSetAttribute(k_moe2, cudaFuncAttributeMaxDynamicSharedMemorySize, 40960);
        attr_set = true;
    }

    k_init<<<1536, 256>>>();
    constexpr int WN = E * HID * D;
    k_cvt<<<WN / 1024, 256>>>(w1, pw1b, WN);
    k_cvt<<<WN / 1024, 256>>>(w3, pw3b, WN);
    k_cvt<<<WN / 1024, 256>>>(w2, pw2b, WN);

    // x1 = x + bn1(dw1(x))
    k_dwconv<<<Bsz * D, 256>>>(x, dw1_w, bn1_g, bn1_b, bn1_m, bn1_v, px1, D, 1);
    // xn = LN(x1)
    k_ln<<<NTOK / 256, 256>>>(ln_w, ln_b);
    // bcdt (tf32)
    k_gemm_bcdt<<<dim3(Bsz, 3, 8), 256>>>(bcdt_w);
    k_dwconv<<<Bsz * C3, 256>>>(pbcdt, dws_w, nullptr, nullptr, nullptr, nullptr, pbcdt2, C3, 0);
    k_softmax<<<Bsz * S, 256>>>();
    // h = xn @ (Am*Bm)^T (tf32, split-K=4)
    k_gemm_h<<<dim3(Bsz, 3, 4), 256>>>();
    // h2 = silu(hproj @ h) -> second output
    k_hproj<<<dim3(Bsz, 6, 1), 256>>>(hproj_w, out_h);
    // x2 = x1 + h2 @ Cm (tf32)
    k_gemm_y<<<dim3(Bsz, 3, 8), 256>>>(out_h);
    // x3 = x2 + bn2(dw2(x2)) -> first output (MoE adds on top)
    k_dwconv<<<Bsz * D, 256>>>(px2, dw2_w, bn2_g, bn2_b, bn2_m, bn2_v, out_x, D, 1);
    // tokens (fp32 + bf16)
    k_transpose<<<dim3(Bsz, 12, 32), 256>>>(out_x);
    // routing (warp per token)
    k_route<<<NTOK / 8, 256>>>(gate_w, gate_b);
    k_offsets<<<1, 1>>>();
    k_scatter<<<NTOK / 256, 256>>>();
    // MoE (bf16 tensor cores)
    k_moe1<<<dim3(E, 128, 6), 256, 61952>>>(b1, b3);
    k_moe2<<<dim3(E, 128, 3), 256, 40960>>>(b2, out_x);
}

// round 5
// speedup vs baseline: 3.6667x; 1.0660x over previous
#include <cuda_runtime.h>
#include <cuda_bf16.h>
#include <cstdint>

#define EPSV 1e-5f

constexpr int Bsz = 16, D = 384, L = 1024, S = 64, C3 = 192, E = 8, HID = 768;
constexpr int NTOK = Bsz * L;                    // 16384
constexpr int MAXSLOTS = 2 * NTOK + E * 128;     // 33792 (expert-padded)

// ------------------------- scratch (static device globals) -------------------------
__device__ float g_x1[Bsz * D * L];
__device__ float g_xn[Bsz * D * L];
__device__ float g_bcdt[Bsz * C3 * L];
__device__ float g_bcdt2[Bsz * C3 * L];
__device__ float g_ab[Bsz * S * L];
__device__ float g_h[Bsz * D * S];
__device__ float g_x2[Bsz * D * L];
__device__ float g_xT[NTOK * D];
__device__ __nv_bfloat16 g_xTb[NTOK * D];
__device__ __nv_bfloat16 g_heb[(size_t)MAXSLOTS * HID];
__device__ __nv_bfloat16 g_w1b[E * HID * D];
__device__ __nv_bfloat16 g_w3b[E * HID * D];
__device__ __nv_bfloat16 g_w2b[E * D * HID];
__device__ int   g_cnt[E];
__device__ int   g_cnt2[E];
__device__ int   g_off[E + 1];
__device__ int   g_topk_idx[NTOK * 2];
__device__ float g_topk_w[NTOK * 2];
__device__ int   g_perm[MAXSLOTS];
__device__ float g_wgt[MAXSLOTS];

// ------------------------- mma / async helpers --------------------------------------
__device__ __forceinline__ uint32_t f2tf32(float x) {
    uint32_t r;
    asm("cvt.rna.tf32.f32 %0, %1;" : "=r"(r) : "f"(x));
    return r;
}
__device__ __forceinline__ void mma_tf32(float c[4], uint32_t a0, uint32_t a1,
                                         uint32_t a2, uint32_t a3,
                                         uint32_t b0, uint32_t b1) {
    asm volatile(
        "mma.sync.aligned.m16n8k8.row.col.f32.tf32.tf32.f32 "
        "{%0,%1,%2,%3}, {%4,%5,%6,%7}, {%8,%9}, {%0,%1,%2,%3};"
        : "+f"(c[0]), "+f"(c[1]), "+f"(c[2]), "+f"(c[3])
        : "r"(a0), "r"(a1), "r"(a2), "r"(a3), "r"(b0), "r"(b1));
}
__device__ __forceinline__ void ldm_x4(uint32_t* r, uint32_t addr) {
    asm volatile("ldmatrix.sync.aligned.m8n8.x4.shared.b16 {%0,%1,%2,%3}, [%4];"
                 : "=r"(r[0]), "=r"(r[1]), "=r"(r[2]), "=r"(r[3]) : "r"(addr));
}
__device__ __forceinline__ void mma_bf16(float c[4], const uint32_t a[4],
                                         uint32_t b0, uint32_t b1) {
    asm volatile(
        "mma.sync.aligned.m16n8k16.row.col.f32.bf16.bf16.f32 "
        "{%0,%1,%2,%3}, {%4,%5,%6,%7}, {%8,%9}, {%0,%1,%2,%3};"
        : "+f"(c[0]), "+f"(c[1]), "+f"(c[2]), "+f"(c[3])
        : "r"(a[0]), "r"(a[1]), "r"(a[2]), "r"(a[3]), "r"(b0), "r"(b1));
}
__device__ __forceinline__ void cpa16(uint32_t dst, const void* src) {
    asm volatile("cp.async.cg.shared.global [%0], [%1], 16;" :: "r"(dst), "l"(src));
}
__device__ __forceinline__ void cp_commit() {
    asm volatile("cp.async.commit_group;");
}
__device__ __forceinline__ void cp_wait1() {
    asm volatile("cp.async.wait_group 1;");
}

// ---------------- prep: init counters/pads + fp32->bf16 weight convert ---------------
__global__ void k_prep(const float* __restrict__ w1, const float* __restrict__ w3,
                       const float* __restrict__ w2) {
    int t = blockIdx.x * 256 + threadIdx.x;
    if (t < MAXSLOTS) { g_wgt[t] = 0.f; g_perm[t] = 0; }
    if (t < E) g_cnt[t] = 0;
    if (t < Bsz * D * S) g_h[t] = 0.f;
    int i = t * 4;
    constexpr int WN = E * HID * D;
    if (i < WN) {
        float4 v1 = *(const float4*)(w1 + i);
        float4 v3 = *(const float4*)(w3 + i);
        float4 v2 = *(const float4*)(w2 + i);
        *(__nv_bfloat162*)(g_w1b + i)     = __float22bfloat162_rn(make_float2(v1.x, v1.y));
        *(__nv_bfloat162*)(g_w1b + i + 2) = __float22bfloat162_rn(make_float2(v1.z, v1.w));
        *(__nv_bfloat162*)(g_w3b + i)     = __float22bfloat162_rn(make_float2(v3.x, v3.y));
        *(__nv_bfloat162*)(g_w3b + i + 2) = __float22bfloat162_rn(make_float2(v3.z, v3.w));
        *(__nv_bfloat162*)(g_w2b + i)     = __float22bfloat162_rn(make_float2(v2.x, v2.y));
        *(__nv_bfloat162*)(g_w2b + i + 2) = __float22bfloat162_rn(make_float2(v2.z, v2.w));
    }
}

// ------------------------- depthwise 3x3 (+optional BN, +optional residual) ----------
__global__ void k_dwconv(const float* __restrict__ in, const float* __restrict__ w9,
                         const float* __restrict__ g, const float* __restrict__ bb,
                         const float* __restrict__ m, const float* __restrict__ v,
                         float* __restrict__ out, int C, int residual) {
    __shared__ float s[34 * 34];
    int b = blockIdx.x / C, c = blockIdx.x % C;
    const float* ip = in + (size_t)(b * C + c) * L;
    int tid = threadIdx.x;
    for (int idx = tid; idx < 34 * 34; idx += 256) {
        int r = idx / 34 - 1, cc = idx % 34 - 1;
        s[idx] = (r >= 0 && r < 32 && cc >= 0 && cc < 32) ? ip[r * 32 + cc] : 0.f;
    }
    __syncthreads();
    float w[9];
#pragma unroll
    for (int i = 0; i < 9; i++) w[i] = w9[c * 9 + i];
    float sc = 1.f, sh = 0.f;
    if (g) { sc = g[c] * rsqrtf(v[c] + EPSV); sh = bb[c] - m[c] * sc; }
    float* op = out + (size_t)(b * C + c) * L;
    for (int idx = tid; idx < 1024; idx += 256) {
        int r = idx >> 5, cc = idx & 31;
        float acc = 0.f;
#pragma unroll
        for (int kr = 0; kr < 3; kr++)
#pragma unroll
            for (int kc = 0; kc < 3; kc++)
                acc += w[kr * 3 + kc] * s[(r + kr) * 34 + cc + kc];
        float val = sc * acc + sh;
        if (residual) val += s[(r + 1) * 34 + cc + 1];
        op[idx] = val;
    }
}

// ------------------------- LayerNorm over channel dim --------------------------------
__global__ void k_ln(const float* __restrict__ lnw, const float* __restrict__ lnb) {
    int gi = blockIdx.x * 256 + threadIdx.x;
    int b = gi >> 10, l = gi & 1023;
    const float* p = g_x1 + (size_t)b * D * L + l;
    float sum = 0.f, sq = 0.f;
    for (int d = 0; d < D; d++) { float x = p[(size_t)d * L]; sum += x; sq += x * x; }
    float mu = sum * (1.f / D);
    float var = sq * (1.f / D) - mu * mu;
    float inv = rsqrtf(var + EPSV);
    float* o = g_xn + (size_t)b * D * L + l;
    for (int d = 0; d < D; d++)
        o[(size_t)d * L] = (p[(size_t)d * L] - mu) * inv * lnw[d] + lnb[d];
}

// --------------- bcdt = bcdt_w @ xn_b  (tf32 mma, 64x128 tiles, K=384) ---------------
__global__ __launch_bounds__(256) void k_gemm_bcdt(const float* __restrict__ Wm) {
    __shared__ uint32_t As[64][17];
    __shared__ uint32_t Bs[128][17];
    int b = blockIdx.x, m0 = blockIdx.y * 64, n0 = blockIdx.z * 128;
    int tid = threadIdx.x, lane = tid & 31, wid = tid >> 5;
    int wm = (wid & 1) * 32, wn = (wid >> 1) * 32;
    int g = lane >> 2, tg = lane & 3;
    const float* Bp = g_xn + (size_t)b * D * L;

    int mA = tid >> 2, kqA = tid & 3;
    int nB = (tid & 31) * 4, kB = tid >> 5;

    float acc[2][4][4] = {};
    float4 ra, rb0, rb1;
    ra  = *(const float4*)&Wm[(size_t)(m0 + mA) * 384 + kqA * 4];
    rb0 = *(const float4*)&Bp[(size_t)kB * L + n0 + nB];
    rb1 = *(const float4*)&Bp[(size_t)(kB + 8) * L + n0 + nB];

    for (int it = 0; it < 24; it++) {
        As[mA][kqA * 4 + 0] = f2tf32(ra.x); As[mA][kqA * 4 + 1] = f2tf32(ra.y);
        As[mA][kqA * 4 + 2] = f2tf32(ra.z); As[mA][kqA * 4 + 3] = f2tf32(ra.w);
        Bs[nB + 0][kB] = f2tf32(rb0.x); Bs[nB + 1][kB] = f2tf32(rb0.y);
        Bs[nB + 2][kB] = f2tf32(rb0.z); Bs[nB + 3][kB] = f2tf32(rb0.w);
        Bs[nB + 0][kB + 8] = f2tf32(rb1.x); Bs[nB + 1][kB + 8] = f2tf32(rb1.y);
        Bs[nB + 2][kB + 8] = f2tf32(rb1.z); Bs[nB + 3][kB + 8] = f2tf32(rb1.w);
        __syncthreads();
        if (it + 1 < 24) {
            int k0 = (it + 1) * 16;
            ra  = *(const float4*)&Wm[(size_t)(m0 + mA) * 384 + k0 + kqA * 4];
            rb0 = *(const float4*)&Bp[(size_t)(k0 + kB) * L + n0 + nB];
            rb1 = *(const float4*)&Bp[(size_t)(k0 + kB + 8) * L + n0 + nB];
        }
#pragma unroll
        for (int ks = 0; ks < 16; ks += 8) {
            uint32_t af[2][4], bf[4][2];
#pragma unroll
            for (int mt = 0; mt < 2; mt++) {
                int r = wm + mt * 16 + g;
                af[mt][0] = As[r][ks + tg];     af[mt][1] = As[r + 8][ks + tg];
                af[mt][2] = As[r][ks + 4 + tg]; af[mt][3] = As[r + 8][ks + 4 + tg];
            }
#pragma unroll
            for (int nt = 0; nt < 4; nt++) {
                int c = wn + nt * 8 + g;
                bf[nt][0] = Bs[c][ks + tg]; bf[nt][1] = Bs[c][ks + 4 + tg];
            }
#pragma unroll
            for (int mt = 0; mt < 2; mt++)
#pragma unroll
                for (int nt = 0; nt < 4; nt++)
                    mma_tf32(acc[mt][nt], af[mt][0], af[mt][1], af[mt][2], af[mt][3],
                             bf[nt][0], bf[nt][1]);
        }
        __syncthreads();
    }
    float* Cp = g_bcdt + (size_t)b * C3 * L;
#pragma unroll
    for (int mt = 0; mt < 2; mt++)
#pragma unroll
        for (int h = 0; h < 2; h++) {
            int row = m0 + wm + mt * 16 + g + h * 8;
#pragma unroll
            for (int nt = 0; nt < 4; nt++) {
                int col = n0 + wn + nt * 8 + tg * 2;
                Cp[(size_t)row * L + col]     = acc[mt][nt][h * 2];
                Cp[(size_t)row * L + col + 1] = acc[mt][nt][h * 2 + 1];
            }
        }
}

// ------------------------- softmax over L + *Bm --------------------------------------
__global__ void k_softmax() {
    int b = blockIdx.x >> 6, s = blockIdx.x & 63;
    const float* dt = g_bcdt2 + ((size_t)b * C3 + 2 * S + s) * L;
    const float* Bm = g_bcdt2 + ((size_t)b * C3 + s) * L;
    float* ab = g_ab + ((size_t)b * S + s) * L;
    int tid = threadIdx.x;
    __shared__ float red[256];
    float vals[4]; float mx = -1e30f;
#pragma unroll
    for (int i = 0; i < 4; i++) { vals[i] = dt[tid + i * 256]; mx = fmaxf(mx, vals[i]); }
    red[tid] = mx; __syncthreads();
    for (int o = 128; o > 0; o >>= 1) { if (tid < o) red[tid] = fmaxf(red[tid], red[tid + o]); __syncthreads(); }
    mx = red[0]; __syncthreads();
    float e[4]; float sum = 0.f;
#pragma unroll
    for (int i = 0; i < 4; i++) { e[i] = __expf(vals[i] - mx); sum += e[i]; }
    red[tid] = sum; __syncthreads();
    for (int o = 128; o > 0; o >>= 1) { if (tid < o) red[tid] += red[tid + o]; __syncthreads(); }
    float inv = 1.f / red[0];
#pragma unroll
    for (int i = 0; i < 4; i++) ab[tid + i * 256] = e[i] * inv * Bm[tid + i * 256];
}

// ----------- h[b,d,s] = sum_l xn*ab  (tf32 mma, 128x64 tile, split-K=4) --------------
__global__ __launch_bounds__(256) void k_gemm_h() {
    __shared__ uint32_t As[128][17];
    __shared__ uint32_t Bs[64][17];
    int b = blockIdx.x, m0 = blockIdx.y * 128, kc = blockIdx.z;
    int tid = threadIdx.x, lane = tid & 31, wid = tid >> 5;
    int wm = (wid & 3) * 32, wn = (wid >> 2) * 32;
    int g = lane >> 2, tg = lane & 3;
    const float* Ap = g_xn + (size_t)b * D * L;
    const float* Bp = g_ab + (size_t)b * S * L;

    int mA = tid >> 1, kqA = (tid & 1) * 2;
    int nB = tid >> 2, kqB = tid & 3;

    float acc[2][4][4] = {};
    float4 ra0, ra1, rb;
    int kbase = kc * 256;
    ra0 = *(const float4*)&Ap[(size_t)(m0 + mA) * L + kbase + kqA * 4];
    ra1 = *(const float4*)&Ap[(size_t)(m0 + mA) * L + kbase + kqA * 4 + 4];
    rb  = *(const float4*)&Bp[(size_t)nB * L + kbase + kqB * 4];

    for (int it = 0; it < 16; it++) {
        As[mA][kqA * 4 + 0] = f2tf32(ra0.x); As[mA][kqA * 4 + 1] = f2tf32(ra0.y);
        As[mA][kqA * 4 + 2] = f2tf32(ra0.z); As[mA][kqA * 4 + 3] = f2tf32(ra0.w);
        As[mA][kqA * 4 + 4] = f2tf32(ra1.x); As[mA][kqA * 4 + 5] = f2tf32(ra1.y);
        As[mA][kqA * 4 + 6] = f2tf32(ra1.z); As[mA][kqA * 4 + 7] = f2tf32(ra1.w);
        Bs[nB][kqB * 4 + 0] = f2tf32(rb.x); Bs[nB][kqB * 4 + 1] = f2tf32(rb.y);
        Bs[nB][kqB * 4 + 2] = f2tf32(rb.z); Bs[nB][kqB * 4 + 3] = f2tf32(rb.w);
        __syncthreads();
        if (it + 1 < 16) {
            int k0 = kbase + (it + 1) * 16;
            ra0 = *(const float4*)&Ap[(size_t)(m0 + mA) * L + k0 + kqA * 4];
            ra1 = *(const float4*)&Ap[(size_t)(m0 + mA) * L + k0 + kqA * 4 + 4];
            rb  = *(const float4*)&Bp[(size_t)nB * L + k0 + kqB * 4];
        }
#pragma unroll
        for (int ks = 0; ks < 16; ks += 8) {
            uint32_t af[2][4], bf[4][2];
#pragma unroll
            for (int mt = 0; mt < 2; mt++) {
                int r = wm + mt * 16 + g;
                af[mt][0] = As[r][ks + tg];     af[mt][1] = As[r + 8][ks + tg];
                af[mt][2] = As[r][ks + 4 + tg]; af[mt][3] = As[r + 8][ks + 4 + tg];
            }
#pragma unroll
            for (int nt = 0; nt < 4; nt++) {
                int c = wn + nt * 8 + g;
                bf[nt][0] = Bs[c][ks + tg]; bf[nt][1] = Bs[c][ks + 4 + tg];
            }
#pragma unroll
            for (int mt = 0; mt < 2; mt++)
#pragma unroll
                for (int nt = 0; nt < 4; nt++)
                    mma_tf32(acc[mt][nt], af[mt][0], af[mt][1], af[mt][2], af[mt][3],
                             bf[nt][0], bf[nt][1]);
        }
        __syncthreads();
    }
    float* Cp = g_h + (size_t)b * D * S;
#pragma unroll
    for (int mt = 0; mt < 2; mt++)
#pragma unroll
        for (int h = 0; h < 2; h++) {
            int row = m0 + wm + mt * 16 + g + h * 8;
#pragma unroll
            for (int nt = 0; nt < 4; nt++) {
                int col = wn + nt * 8 + tg * 2;
                atomicAdd(&Cp[(size_t)row * S + col],     acc[mt][nt][h * 2]);
                atomicAdd(&Cp[(size_t)row * S + col + 1], acc[mt][nt][h * 2 + 1]);
            }
        }
}

// ------------------------- h2 = silu(hproj @ h) -> out_h -----------------------------
__global__ void k_hproj(const float* __restrict__ Wp, float* __restrict__ outh) {
    __shared__ float As[8][68], Bs[8][68];
    int b = blockIdx.x, m0 = blockIdx.y * 64;
    int tid = threadIdx.x, tx = tid & 15, ty = tid >> 4;
    const float* Bp = g_h + (size_t)b * D * S;
    float acc[4][4] = {};
    for (int k0 = 0; k0 < 384; k0 += 8) {
        for (int p = 0; p < 2; p++) {
            int idx = tid + p * 256; int mm = idx >> 3, kk = idx & 7;
            As[kk][mm] = Wp[(size_t)(m0 + mm) * 384 + k0 + kk];
        }
        for (int p = 0; p < 2; p++) {
            int idx = tid + p * 256; int kk = idx >> 6, nn = idx & 63;
            Bs[kk][nn] = Bp[(size_t)(k0 + kk) * S + nn];
        }
        __syncthreads();
#pragma unroll
        for (int k = 0; k < 8; k++) {
            float a[4], bv[4];
#pragma unroll
            for (int i = 0; i < 4; i++) a[i] = As[k][ty + i * 16];
#pragma unroll
            for (int j = 0; j < 4; j++) bv[j] = Bs[k][tx + j * 16];
#pragma unroll
            for (int i = 0; i < 4; i++)
#pragma unroll
                for (int j = 0; j < 4; j++) acc[i][j] += a[i] * bv[j];
        }
        __syncthreads();
    }
    float* Cp = outh + (size_t)b * D * S;
    for (int i = 0; i < 4; i++)
        for (int j = 0; j < 4; j++) {
            float x = acc[i][j];
            Cp[(size_t)(m0 + ty + i * 16) * S + tx + j * 16] = x / (1.f + __expf(-x));
        }
}

// ------------- x2 = x1 + h2 @ Cm  (tf32 mma, 128x128 tiles, K=64) --------------------
__global__ __launch_bounds__(256) void k_gemm_y(const float* __restrict__ outh) {
    __shared__ uint32_t As[128][17];
    __shared__ uint32_t Bs[128][17];
    int b = blockIdx.x, m0 = blockIdx.y * 128, n0 = blockIdx.z * 128;
    int tid = threadIdx.x, lane = tid & 31, wid = tid >> 5;
    int wm = (wid & 1) * 64, wn = (wid >> 1) * 32;
    int g = lane >> 2, tg = lane & 3;
    const float* Ap = outh + (size_t)b * D * S;
    const float* Bp = g_bcdt2 + ((size_t)b * C3 + S) * L;

    int mA = tid >> 1, kqA = (tid & 1) * 2;
    int nB = (tid & 31) * 4, kB = tid >> 5;

    float acc[4][4][4] = {};
    float4 ra0, ra1, rb0, rb1;
    ra0 = *(const float4*)&Ap[(size_t)(m0 + mA) * S + kqA * 4];
    ra1 = *(const float4*)&Ap[(size_t)(m0 + mA) * S + kqA * 4 + 4];
    rb0 = *(const float4*)&Bp[(size_t)kB * L + n0 + nB];
    rb1 = *(const float4*)&Bp[(size_t)(kB + 8) * L + n0 + nB];

    for (int it = 0; it < 4; it++) {
        As[mA][kqA * 4 + 0] = f2tf32(ra0.x); As[mA][kqA * 4 + 1] = f2tf32(ra0.y);
        As[mA][kqA * 4 + 2] = f2tf32(ra0.z); As[mA][kqA * 4 + 3] = f2tf32(ra0.w);
        As[mA][kqA * 4 + 4] = f2tf32(ra1.x); As[mA][kqA * 4 + 5] = f2tf32(ra1.y);
        As[mA][kqA * 4 + 6] = f2tf32(ra1.z); As[mA][kqA * 4 + 7] = f2tf32(ra1.w);
        Bs[nB + 0][kB] = f2tf32(rb0.x); Bs[nB + 1][kB] = f2tf32(rb0.y);
        Bs[nB + 2][kB] = f2tf32(rb0.z); Bs[nB + 3][kB] = f2tf32(rb0.w);
        Bs[nB + 0][kB + 8] = f2tf32(rb1.x); Bs[nB + 1][kB + 8] = f2tf32(rb1.y);
        Bs[nB + 2][kB + 8] = f2tf32(rb1.z); Bs[nB + 3][kB + 8] = f2tf32(rb1.w);
        __syncthreads();
        if (it + 1 < 4) {
            int k0 = (it + 1) * 16;
            ra0 = *(const float4*)&Ap[(size_t)(m0 + mA) * S + k0 + kqA * 4];
            ra1 = *(const float4*)&Ap[(size_t)(m0 + mA) * S + k0 + kqA * 4 + 4];
            rb0 = *(const float4*)&Bp[(size_t)(k0 + kB) * L + n0 + nB];
            rb1 = *(const float4*)&Bp[(size_t)(k0 + kB + 8) * L + n0 + nB];
        }
#pragma unroll
        for (int ks = 0; ks < 16; ks += 8) {
            uint32_t af[4][4], bf[4][2];
#pragma unroll
            for (int mt = 0; mt < 4; mt++) {
                int r = wm + mt * 16 + g;
                af[mt][0] = As[r][ks + tg];     af[mt][1] = As[r + 8][ks + tg];
                af[mt][2] = As[r][ks + 4 + tg]; af[mt][3] = As[r + 8][ks + 4 + tg];
            }
#pragma unroll
            for (int nt = 0; nt < 4; nt++) {
                int c = wn + nt * 8 + g;
                bf[nt][0] = Bs[c][ks + tg]; bf[nt][1] = Bs[c][ks + 4 + tg];
            }
#pragma unroll
            for (int mt = 0; mt < 4; mt++)
#pragma unroll
                for (int nt = 0; nt < 4; nt++)
                    mma_tf32(acc[mt][nt], af[mt][0], af[mt][1], af[mt][2], af[mt][3],
                             bf[nt][0], bf[nt][1]);
        }
        __syncthreads();
    }
#pragma unroll
    for (int mt = 0; mt < 4; mt++)
#pragma unroll
        for (int h = 0; h < 2; h++) {
            int row = m0 + wm + mt * 16 + g + h * 8;
#pragma unroll
            for (int nt = 0; nt < 4; nt++) {
                int col = n0 + wn + nt * 8 + tg * 2;
                size_t o = (size_t)b * D * L + (size_t)row * L + col;
                g_x2[o]     = g_x1[o]     + acc[mt][nt][h * 2];
                g_x2[o + 1] = g_x1[o + 1] + acc[mt][nt][h * 2 + 1];
            }
        }
}

// ------------------------- NCHW -> token-major transpose (fp32 + bf16) ---------------
__global__ void k_transpose(const float* __restrict__ xin) {
    __shared__ float s[32][33];
    int b = blockIdx.x, d0 = blockIdx.y * 32, l0 = blockIdx.z * 32;
    int c = threadIdx.x & 31, r0 = threadIdx.x >> 5;
    for (int i = 0; i < 32; i += 8)
        s[r0 + i][c] = xin[((size_t)b * D + d0 + r0 + i) * L + l0 + c];
    __syncthreads();
    for (int i = 0; i < 32; i += 8) {
        float v = s[c][r0 + i];
        size_t o = ((size_t)b * L + l0 + r0 + i) * D + d0 + c;
        g_xT[o] = v;
        g_xTb[o] = __float2bfloat16(v);
    }
}

// ------------------------- router (warp per token, coalesced) ------------------------
__global__ void k_route(const float* __restrict__ gw, const float* __restrict__ gb) {
    __shared__ float sg[E * D];
    int tid = threadIdx.x, lane = tid & 31, wid = tid >> 5;
    for (int i = tid; i < E * D; i += 256) sg[i] = gw[i];
    __syncthreads();
    int n = blockIdx.x * 8 + wid;
    const float* t = g_xT + (size_t)n * D;
    float lg[E] = {};
#pragma unroll
    for (int j = 0; j < 12; j++) {
        float x = t[lane + j * 32];
        int d = lane + j * 32;
#pragma unroll
        for (int e = 0; e < E; e++) lg[e] += sg[e * D + d] * x;
    }
#pragma unroll
    for (int e = 0; e < E; e++) {
        float v = lg[e];
#pragma unroll
        for (int o = 16; o > 0; o >>= 1) v += __shfl_xor_sync(0xffffffff, v, o);
        lg[e] = v;
    }
    if (lane == 0) {
#pragma unroll
        for (int e = 0; e < E; e++) lg[e] += gb[e];
        int i0 = 0; float v0 = lg[0];
#pragma unroll
        for (int e = 1; e < E; e++) if (lg[e] > v0) { v0 = lg[e]; i0 = e; }
        int i1 = -1; float v1 = -1e30f;
#pragma unroll
        for (int e = 0; e < E; e++) if (e != i0 && lg[e] > v1) { v1 = lg[e]; i1 = e; }
        float p0 = 1.f / (1.f + __expf(v1 - v0));
        g_topk_idx[n * 2] = i0; g_topk_idx[n * 2 + 1] = i1;
        g_topk_w[n * 2] = p0;   g_topk_w[n * 2 + 1] = 1.f - p0;
        atomicAdd(&g_cnt[i0], 1); atomicAdd(&g_cnt[i1], 1);
    }
}

__global__ void k_offsets() {
    int off = 0;
    for (int e = 0; e < E; e++) {
        g_off[e] = off;
        off += (g_cnt[e] + 127) & ~127;
        g_cnt2[e] = 0;
    }
    g_off[E] = off;
}

__global__ void k_scatter() {
    int n = blockIdx.x * 256 + threadIdx.x;
#pragma unroll
    for (int k = 0; k < 2; k++) {
        int e = g_topk_idx[n * 2 + k];
        int pos = g_off[e] + atomicAdd(&g_cnt2[e], 1);
        g_perm[pos] = n;
        g_wgt[pos] = g_topk_w[n * 2 + k];
    }
}

// ------------------- MoE GEMM1 (bf16 mma + cp.async 3-stage) -------------------------
// smem bytes: A @0 (3*10240), B1 @30720, B3 @61440, perm @92160; total 92672
__global__ __launch_bounds__(256) void k_moe1(
        const float* __restrict__ B1, const float* __restrict__ B3) {
    extern __shared__ char sm[];
    int* sperm = (int*)(sm + 92160);

    int e = blockIdx.x;
    int cnt = g_cnt[e];
    int m0 = blockIdx.y * 128;
    if (m0 >= cnt) return;
    int base = g_off[e];
    int n0 = blockIdx.z * 128;

    int tid = threadIdx.x, lane = tid & 31, wid = tid >> 5;
    int wm = (wid & 1) * 64, wn = (wid >> 1) * 32;
    int g = lane >> 2, tg = lane & 3;

    if (tid < 128) sperm[tid] = g_perm[base + m0 + tid];
    __syncthreads();

    int lr = tid >> 1, lh = tid & 1;
    const __nv_bfloat16* aRow  = g_xTb + (size_t)sperm[lr] * D + lh * 16;
    const __nv_bfloat16* b1Row = g_w1b + ((size_t)e * HID + n0 + lr) * D + lh * 16;
    const __nv_bfloat16* b3Row = g_w3b + ((size_t)e * HID + n0 + lr) * D + lh * 16;

    uint32_t smBase = (uint32_t)__cvta_generic_to_shared(sm);
    uint32_t sdst = (uint32_t)(lr * 80 + lh * 32);
    uint32_t aFrag = (wm + (lane & 15)) * 80 + (lane >> 4) * 16;
    uint32_t bFrag = (wn + (lane >> 4) * 8 + (lane & 7)) * 80 + ((lane >> 3) & 1) * 16;

    constexpr int KT = D / 32;   // 12
    auto issue = [&](int t) {
        if (t < KT) {
            int k0 = t * 32;
            uint32_t off = (uint32_t)(t % 3) * 10240 + sdst;
            cpa16(smBase + off,              aRow + k0);
            cpa16(smBase + off + 16,         aRow + k0 + 8);
            cpa16(smBase + 30720 + off,      b1Row + k0);
            cpa16(smBase + 30720 + off + 16, b1Row + k0 + 8);
            cpa16(smBase + 61440 + off,      b3Row + k0);
            cpa16(smBase + 61440 + off + 16, b3Row + k0 + 8);
        }
        cp_commit();
    };

    float acc1[4][4][4] = {}, acc3[4][4][4] = {};
    issue(0); issue(1);

    for (int it = 0; it < KT; it++) {
        cp_wait1();
        __syncthreads();
        issue(it + 2);
        uint32_t st = (uint32_t)(it % 3) * 10240;
#pragma unroll
        for (int ks = 0; ks < 2; ks++) {
            uint32_t af[4][4], bf1[2][4], bf3[2][4];
#pragma unroll
            for (int mt = 0; mt < 4; mt++)
                ldm_x4(af[mt], smBase + st + aFrag + mt * 1280 + ks * 32);
#pragma unroll
            for (int np = 0; np < 2; np++) {
                ldm_x4(bf1[np], smBase + 30720 + st + bFrag + np * 1280 + ks * 32);
                ldm_x4(bf3[np], smBase + 61440 + st + bFrag + np * 1280 + ks * 32);
            }
#pragma unroll
            for (int mt = 0; mt < 4; mt++)
#pragma unroll
                for (int nt = 0; nt < 4; nt++) {
                    int np = nt >> 1, hf = (nt & 1) * 2;
                    mma_bf16(acc1[mt][nt], af[mt], bf1[np][hf], bf1[np][hf + 1]);
                    mma_bf16(acc3[mt][nt], af[mt], bf3[np][hf], bf3[np][hf + 1]);
                }
        }
    }

#pragma unroll
    for (int mt = 0; mt < 4; mt++) {
#pragma unroll
        for (int nt = 0; nt < 4; nt++) {
            int cl = n0 + wn + nt * 8 + tg * 2;
            float bb1a = B1[e * HID + cl], bb1b = B1[e * HID + cl + 1];
            float bb3a = B3[e * HID + cl], bb3b = B3[e * HID + cl + 1];
#pragma unroll
            for (int h = 0; h < 2; h++) {
                int rl = wm + mt * 16 + g + h * 8;
                float x1a = acc1[mt][nt][h * 2] + bb1a;
                float x1b = acc1[mt][nt][h * 2 + 1] + bb1b;
                float x3a = acc3[mt][nt][h * 2] + bb3a;
                float x3b = acc3[mt][nt][h * 2 + 1] + bb3b;
                float oa = (x1a / (1.f + __expf(-x1a))) * x3a;
                float ob = (x1b / (1.f + __expf(-x1b))) * x3b;
                *(__nv_bfloat162*)&g_heb[(size_t)(base + m0 + rl) * HID + cl] =
                    __float22bfloat162_rn(make_float2(oa, ob));
            }
        }
    }
}

// ------------------- MoE GEMM2 (bf16 mma + cp.async 3-stage, scatter) ----------------
// smem bytes: A @0 (3*10240), B @30720 (3*10240); total 61440
__global__ __launch_bounds__(256) void k_moe2(
        const float* __restrict__ b2v, float* __restrict__ outx) {
    extern __shared__ char sm[];

    int e = blockIdx.x;
    int cnt = g_cnt[e];
    int m0 = blockIdx.y * 128;
    if (m0 >= cnt) return;
    int base = g_off[e];
    int n0 = blockIdx.z * 128;

    int tid = threadIdx.x, lane = tid & 31, wid = tid >> 5;
    int wm = (wid & 1) * 64, wn = (wid >> 1) * 32;
    int g = lane >> 2, tg = lane & 3;

    int lr = tid >> 1, lh = tid & 1;
    const __nv_bfloat16* aRow = g_heb + (size_t)(base + m0 + lr) * HID + lh * 16;
    const __nv_bfloat16* bRow = g_w2b + ((size_t)e * D + n0 + lr) * HID + lh * 16;

    uint32_t smBase = (uint32_t)__cvta_generic_to_shared(sm);
    uint32_t sdst = (uint32_t)(lr * 80 + lh * 32);
    uint32_t aFrag = (wm + (lane & 15)) * 80 + (lane >> 4) * 16;
    uint32_t bFrag = (wn + (lane >> 4) * 8 + (lane & 7)) * 80 + ((lane >> 3) & 1) * 16;

    constexpr int KT = HID / 32;  // 24
    auto issue = [&](int t) {
        if (t < KT) {
            int k0 = t * 32;
            uint32_t off = (uint32_t)(t % 3) * 10240 + sdst;
            cpa16(smBase + off,              aRow + k0);
            cpa16(smBase + off + 16,         aRow + k0 + 8);
            cpa16(smBase + 30720 + off,      bRow + k0);
            cpa16(smBase + 30720 + off + 16, bRow + k0 + 8);
        }
        cp_commit();
    };

    float acc[4][4][4] = {};
    issue(0); issue(1);

    for (int it = 0; it < KT; it++) {
        cp_wait1();
        __syncthreads();
        issue(it + 2);
        uint32_t st = (uint32_t)(it % 3) * 10240;
#pragma unroll
        for (int ks = 0; ks < 2; ks++) {
            uint32_t af[4][4], bf[2][4];
#pragma unroll
            for (int mt = 0; mt < 4; mt++)
                ldm_x4(af[mt], smBase + st + aFrag + mt * 1280 + ks * 32);
#pragma unroll
            for (int np = 0; np < 2; np++)
                ldm_x4(bf[np], smBase + 30720 + st + bFrag + np * 1280 + ks * 32);
#pragma unroll
            for (int mt = 0; mt < 4; mt++)
#pragma unroll
                for (int nt = 0; nt < 4; nt++) {
                    int np = nt >> 1, hf = (nt & 1) * 2;
                    mma_bf16(acc[mt][nt], af[mt], bf[np][hf], bf[np][hf + 1]);
                }
        }
    }

#pragma unroll
    for (int mt = 0; mt < 4; mt++) {
#pragma unroll
        for (int h = 0; h < 2; h++) {
            int rl = wm + mt * 16 + g + h * 8;
            float w = g_wgt[base + m0 + rl];
            if (w == 0.f) continue;
            int n = g_perm[base + m0 + rl];
            int b = n >> 10, l = n & 1023;
#pragma unroll
            for (int nt = 0; nt < 4; nt++) {
                int cl = n0 + wn + nt * 8 + tg * 2;
                float v0 = (acc[mt][nt][h * 2] + b2v[e * D + cl]) * w;
                float v1 = (acc[mt][nt][h * 2 + 1] + b2v[e * D + cl + 1]) * w;
                atomicAdd(&outx[((size_t)b * D + cl) * L + l], v0);
                atomicAdd(&outx[((size_t)b * D + cl + 1) * L + l], v1);
            }
        }
    }
}

// ------------------------- launch ---------------------------------------------------
extern "C" void kernel_launch(void* const* d_in, const int* in_sizes, int n_in,
                              void* d_out, int out_size) {
    const float* x      = (const float*)d_in[0];
    const float* dw1_w  = (const float*)d_in[1];
    const float* bn1_g  = (const float*)d_in[2];
    const float* bn1_b  = (const float*)d_in[3];
    const float* bn1_m  = (const float*)d_in[4];
    const float* bn1_v  = (const float*)d_in[5];
    const float* dw2_w  = (const float*)d_in[6];
    const float* bn2_g  = (const float*)d_in[7];
    const float* bn2_b  = (const float*)d_in[8];
    const float* bn2_m  = (const float*)d_in[9];
    const float* bn2_v  = (const float*)d_in[10];
    const float* ln_w   = (const float*)d_in[11];
    const float* ln_b   = (const float*)d_in[12];
    const float* bcdt_w = (const float*)d_in[13];
    const float* dws_w  = (const float*)d_in[14];
    const float* hproj_w= (const float*)d_in[15];
    // d_in[16] = A (cancels inside softmax over L)
    const float* gate_w = (const float*)d_in[17];
    const float* gate_b = (const float*)d_in[18];
    const float* w1     = (const float*)d_in[19];
    const float* b1     = (const float*)d_in[20];
    const float* w2     = (const float*)d_in[21];
    const float* b2     = (const float*)d_in[22];
    const float* w3     = (const float*)d_in[23];
    const float* b3     = (const float*)d_in[24];

    float* out_x = (float*)d_out;
    float* out_h = out_x + (size_t)Bsz * D * L;

    float* px1;    cudaGetSymbolAddress((void**)&px1, g_x1);
    float* pbcdt;  cudaGetSymbolAddress((void**)&pbcdt, g_bcdt);
    float* pbcdt2; cudaGetSymbolAddress((void**)&pbcdt2, g_bcdt2);
    float* px2;    cudaGetSymbolAddress((void**)&px2, g_x2);

    static bool attr_set = false;
    if (!attr_set) {
        cudaFuncSetAttribute(k_moe1, cudaFuncAttributeMaxDynamicSharedMemorySize, 92672);
        cudaFuncSetAttribute(k_moe2, cudaFuncAttributeMaxDynamicSharedMemorySize, 61440);
        attr_set = true;
    }

    // init + weight conversions in one launch
    k_prep<<<2304, 256>>>(w1, w3, w2);

    // x1 = x + bn1(dw1(x))
    k_dwconv<<<Bsz * D, 256>>>(x, dw1_w, bn1_g, bn1_b, bn1_m, bn1_v, px1, D, 1);
    // xn = LN(x1)
    k_ln<<<NTOK / 256, 256>>>(ln_w, ln_b);
    // bcdt (tf32)
    k_gemm_bcdt<<<dim3(Bsz, 3, 8), 256>>>(bcdt_w);
    k_dwconv<<<Bsz * C3, 256>>>(pbcdt, dws_w, nullptr, nullptr, nullptr, nullptr, pbcdt2, C3, 0);
    k_softmax<<<Bsz * S, 256>>>();
    // h = xn @ (Am*Bm)^T (tf32, split-K=4)
    k_gemm_h<<<dim3(Bsz, 3, 4), 256>>>();
    // h2 = silu(hproj @ h) -> second output
    k_hproj<<<dim3(Bsz, 6, 1), 256>>>(hproj_w, out_h);
    // x2 = x1 + h2 @ Cm (tf32)
    k_gemm_y<<<dim3(Bsz, 3, 8), 256>>>(out_h);
    // x3 = x2 + bn2(dw2(x2)) -> first output (MoE adds on top)
    k_dwconv<<<Bsz * D, 256>>>(px2, dw2_w, bn2_g, bn2_b, bn2_m, bn2_v, out_x, D, 1);
    // tokens (fp32 + bf16)
    k_transpose<<<dim3(Bsz, 12, 32), 256>>>(out_x);
    // routing (warp per token)
    k_route<<<NTOK / 8, 256>>>(gate_w, gate_b);
    k_offsets<<<1, 1>>>();
    k_scatter<<<NTOK / 256, 256>>>();
    // MoE (bf16 tensor cores, cp.async pipelines)
    k_moe1<<<dim3(E, 128, 6), 256, 92672>>>(b1, b3);
    k_moe2<<<dim3(E, 128, 3), 256, 61440>>>(b2, out_x);
}

// round 7
// speedup vs baseline: 4.1359x; 1.1280x over previous
#include <cuda_runtime.h>
#include <cuda_bf16.h>
#include <cstdint>

#define EPSV 1e-5f

constexpr int Bsz = 16, D = 384, L = 1024, S = 64, C3 = 192, E = 8, HID = 768;
constexpr int NTOK = Bsz * L;                    // 16384
constexpr int MAXSLOTS = 2 * NTOK + E * 128;     // 33792 (expert-padded)

// ------------------------- scratch (static device globals) -------------------------
__device__ float g_x1[Bsz * D * L];
__device__ float g_xn[Bsz * D * L];
__device__ float g_bcdt[Bsz * C3 * L];
__device__ float g_bcdt2[Bsz * C3 * L];
__device__ float g_ab[Bsz * S * L];
__device__ float g_h[Bsz * D * S];
__device__ float g_x2[Bsz * D * L];
__device__ float g_xT[NTOK * D];
__device__ __nv_bfloat16 g_xTb[NTOK * D];
__device__ __nv_bfloat16 g_heb[(size_t)MAXSLOTS * HID];
__device__ __nv_bfloat16 g_w1b[E * HID * D];
__device__ __nv_bfloat16 g_w3b[E * HID * D];
__device__ __nv_bfloat16 g_w2b[E * D * HID];
__device__ int   g_cnt[E];
__device__ int   g_cnt2[E];
__device__ int   g_off[E + 1];
__device__ int   g_topk_idx[NTOK * 2];
__device__ float g_topk_w[NTOK * 2];
__device__ int   g_perm[MAXSLOTS];
__device__ float g_wgt[MAXSLOTS];

// ------------------------- mma / async helpers --------------------------------------
__device__ __forceinline__ uint32_t f2tf32(float x) {
    uint32_t r;
    asm("cvt.rna.tf32.f32 %0, %1;" : "=r"(r) : "f"(x));
    return r;
}
__device__ __forceinline__ void mma_tf32(float c[4], uint32_t a0, uint32_t a1,
                                         uint32_t a2, uint32_t a3,
                                         uint32_t b0, uint32_t b1) {
    asm volatile(
        "mma.sync.aligned.m16n8k8.row.col.f32.tf32.tf32.f32 "
        "{%0,%1,%2,%3}, {%4,%5,%6,%7}, {%8,%9}, {%0,%1,%2,%3};"
        : "+f"(c[0]), "+f"(c[1]), "+f"(c[2]), "+f"(c[3])
        : "r"(a0), "r"(a1), "r"(a2), "r"(a3), "r"(b0), "r"(b1));
}
__device__ __forceinline__ void ldm_x4(uint32_t* r, uint32_t addr) {
    asm volatile("ldmatrix.sync.aligned.m8n8.x4.shared.b16 {%0,%1,%2,%3}, [%4];"
                 : "=r"(r[0]), "=r"(r[1]), "=r"(r[2]), "=r"(r[3]) : "r"(addr));
}
__device__ __forceinline__ void mma_bf16(float c[4], const uint32_t a[4],
                                         uint32_t b0, uint32_t b1) {
    asm volatile(
        "mma.sync.aligned.m16n8k16.row.col.f32.bf16.bf16.f32 "
        "{%0,%1,%2,%3}, {%4,%5,%6,%7}, {%8,%9}, {%0,%1,%2,%3};"
        : "+f"(c[0]), "+f"(c[1]), "+f"(c[2]), "+f"(c[3])
        : "r"(a[0]), "r"(a[1]), "r"(a[2]), "r"(a[3]), "r"(b0), "r"(b1));
}
__device__ __forceinline__ void cpa16(uint32_t dst, const void* src) {
    asm volatile("cp.async.cg.shared.global [%0], [%1], 16;" :: "r"(dst), "l"(src));
}
__device__ __forceinline__ void cp_commit() {
    asm volatile("cp.async.commit_group;");
}
__device__ __forceinline__ void cp_wait1() {
    asm volatile("cp.async.wait_group 1;");
}

// ---------------- prep: init counters/pads + fp32->bf16 weight convert ---------------
__global__ void k_prep(const float* __restrict__ w1, const float* __restrict__ w3,
                       const float* __restrict__ w2) {
    int t = blockIdx.x * 256 + threadIdx.x;
    if (t < MAXSLOTS) { g_wgt[t] = 0.f; g_perm[t] = 0; }
    if (t < E) g_cnt[t] = 0;
    if (t < Bsz * D * S) g_h[t] = 0.f;
    int i = t * 4;
    constexpr int WN = E * HID * D;
    if (i < WN) {
        float4 v1 = *(const float4*)(w1 + i);
        float4 v3 = *(const float4*)(w3 + i);
        float4 v2 = *(const float4*)(w2 + i);
        *(__nv_bfloat162*)(g_w1b + i)     = __float22bfloat162_rn(make_float2(v1.x, v1.y));
        *(__nv_bfloat162*)(g_w1b + i + 2) = __float22bfloat162_rn(make_float2(v1.z, v1.w));
        *(__nv_bfloat162*)(g_w3b + i)     = __float22bfloat162_rn(make_float2(v3.x, v3.y));
        *(__nv_bfloat162*)(g_w3b + i + 2) = __float22bfloat162_rn(make_float2(v3.z, v3.w));
        *(__nv_bfloat162*)(g_w2b + i)     = __float22bfloat162_rn(make_float2(v2.x, v2.y));
        *(__nv_bfloat162*)(g_w2b + i + 2) = __float22bfloat162_rn(make_float2(v2.z, v2.w));
    }
}

// ------------------------- depthwise 3x3 (+optional BN, +optional residual) ----------
__global__ void k_dwconv(const float* __restrict__ in, const float* __restrict__ w9,
                         const float* __restrict__ g, const float* __restrict__ bb,
                         const float* __restrict__ m, const float* __restrict__ v,
                         float* __restrict__ out, int C, int residual) {
    __shared__ float s[34 * 34];
    int b = blockIdx.x / C, c = blockIdx.x % C;
    const float* ip = in + (size_t)(b * C + c) * L;
    int tid = threadIdx.x;
    for (int idx = tid; idx < 34 * 34; idx += 256) {
        int r = idx / 34 - 1, cc = idx % 34 - 1;
        s[idx] = (r >= 0 && r < 32 && cc >= 0 && cc < 32) ? ip[r * 32 + cc] : 0.f;
    }
    __syncthreads();
    float w[9];
#pragma unroll
    for (int i = 0; i < 9; i++) w[i] = w9[c * 9 + i];
    float sc = 1.f, sh = 0.f;
    if (g) { sc = g[c] * rsqrtf(v[c] + EPSV); sh = bb[c] - m[c] * sc; }
    float* op = out + (size_t)(b * C + c) * L;
    for (int idx = tid; idx < 1024; idx += 256) {
        int r = idx >> 5, cc = idx & 31;
        float acc = 0.f;
#pragma unroll
        for (int kr = 0; kr < 3; kr++)
#pragma unroll
            for (int kc = 0; kc < 3; kc++)
                acc += w[kr * 3 + kc] * s[(r + kr) * 34 + cc + kc];
        float val = sc * acc + sh;
        if (residual) val += s[(r + 1) * 34 + cc + 1];
        op[idx] = val;
    }
}

// ------------------------- LayerNorm over channel dim --------------------------------
__global__ void k_ln(const float* __restrict__ lnw, const float* __restrict__ lnb) {
    int gi = blockIdx.x * 256 + threadIdx.x;
    int b = gi >> 10, l = gi & 1023;
    const float* p = g_x1 + (size_t)b * D * L + l;
    float sum = 0.f, sq = 0.f;
    for (int d = 0; d < D; d++) { float x = p[(size_t)d * L]; sum += x; sq += x * x; }
    float mu = sum * (1.f / D);
    float var = sq * (1.f / D) - mu * mu;
    float inv = rsqrtf(var + EPSV);
    float* o = g_xn + (size_t)b * D * L + l;
    for (int d = 0; d < D; d++)
        o[(size_t)d * L] = (p[(size_t)d * L] - mu) * inv * lnw[d] + lnb[d];
}

// --------------- bcdt = bcdt_w @ xn_b  (tf32 mma, conflict-free smem) ----------------
__global__ __launch_bounds__(256) void k_gemm_bcdt(const float* __restrict__ Wm) {
    __shared__ uint32_t As[64][20];
    __shared__ uint32_t Bs[16][132];
    int b = blockIdx.x, m0 = blockIdx.y * 64, n0 = blockIdx.z * 128;
    int tid = threadIdx.x, lane = tid & 31, wid = tid >> 5;
    int wm = (wid & 1) * 32, wn = (wid >> 1) * 32;
    int g = lane >> 2, tg = lane & 3;
    const float* Bp = g_xn + (size_t)b * D * L;

    int mA = tid >> 2, kqA = tid & 3;
    int nB = (tid & 31) * 4, kB = tid >> 5;

    float acc[2][4][4] = {};
    float4 ra, rb0, rb1;
    ra  = *(const float4*)&Wm[(size_t)(m0 + mA) * 384 + kqA * 4];
    rb0 = *(const float4*)&Bp[(size_t)kB * L + n0 + nB];
    rb1 = *(const float4*)&Bp[(size_t)(kB + 8) * L + n0 + nB];

    for (int it = 0; it < 24; it++) {
        *(uint4*)&As[mA][kqA * 4] =
            make_uint4(f2tf32(ra.x), f2tf32(ra.y), f2tf32(ra.z), f2tf32(ra.w));
        *(uint4*)&Bs[kB][nB] =
            make_uint4(f2tf32(rb0.x), f2tf32(rb0.y), f2tf32(rb0.z), f2tf32(rb0.w));
        *(uint4*)&Bs[kB + 8][nB] =
            make_uint4(f2tf32(rb1.x), f2tf32(rb1.y), f2tf32(rb1.z), f2tf32(rb1.w));
        __syncthreads();
        if (it + 1 < 24) {
            int k0 = (it + 1) * 16;
            ra  = *(const float4*)&Wm[(size_t)(m0 + mA) * 384 + k0 + kqA * 4];
            rb0 = *(const float4*)&Bp[(size_t)(k0 + kB) * L + n0 + nB];
            rb1 = *(const float4*)&Bp[(size_t)(k0 + kB + 8) * L + n0 + nB];
        }
#pragma unroll
        for (int ks = 0; ks < 16; ks += 8) {
            uint32_t af[2][4], bf[4][2];
#pragma unroll
            for (int mt = 0; mt < 2; mt++) {
                int r = wm + mt * 16 + g;
                af[mt][0] = As[r][ks + tg];     af[mt][1] = As[r + 8][ks + tg];
                af[mt][2] = As[r][ks + 4 + tg]; af[mt][3] = As[r + 8][ks + 4 + tg];
            }
#pragma unroll
            for (int nt = 0; nt < 4; nt++) {
                int c = wn + nt * 8 + g;
                bf[nt][0] = Bs[ks + tg][c]; bf[nt][1] = Bs[ks + 4 + tg][c];
            }
#pragma unroll
            for (int mt = 0; mt < 2; mt++)
#pragma unroll
                for (int nt = 0; nt < 4; nt++)
                    mma_tf32(acc[mt][nt], af[mt][0], af[mt][1], af[mt][2], af[mt][3],
                             bf[nt][0], bf[nt][1]);
        }
        __syncthreads();
    }
    float* Cp = g_bcdt + (size_t)b * C3 * L;
#pragma unroll
    for (int mt = 0; mt < 2; mt++)
#pragma unroll
        for (int h = 0; h < 2; h++) {
            int row = m0 + wm + mt * 16 + g + h * 8;
#pragma unroll
            for (int nt = 0; nt < 4; nt++) {
                int col = n0 + wn + nt * 8 + tg * 2;
                Cp[(size_t)row * L + col]     = acc[mt][nt][h * 2];
                Cp[(size_t)row * L + col + 1] = acc[mt][nt][h * 2 + 1];
            }
        }
}

// ------------------------- softmax over L + *Bm --------------------------------------
__global__ void k_softmax() {
    int b = blockIdx.x >> 6, s = blockIdx.x & 63;
    const float* dt = g_bcdt2 + ((size_t)b * C3 + 2 * S + s) * L;
    const float* Bm = g_bcdt2 + ((size_t)b * C3 + s) * L;
    float* ab = g_ab + ((size_t)b * S + s) * L;
    int tid = threadIdx.x;
    __shared__ float red[256];
    float vals[4]; float mx = -1e30f;
#pragma unroll
    for (int i = 0; i < 4; i++) { vals[i] = dt[tid + i * 256]; mx = fmaxf(mx, vals[i]); }
    red[tid] = mx; __syncthreads();
    for (int o = 128; o > 0; o >>= 1) { if (tid < o) red[tid] = fmaxf(red[tid], red[tid + o]); __syncthreads(); }
    mx = red[0]; __syncthreads();
    float e[4]; float sum = 0.f;
#pragma unroll
    for (int i = 0; i < 4; i++) { e[i] = __expf(vals[i] - mx); sum += e[i]; }
    red[tid] = sum; __syncthreads();
    for (int o = 128; o > 0; o >>= 1) { if (tid < o) red[tid] += red[tid + o]; __syncthreads(); }
    float inv = 1.f / red[0];
#pragma unroll
    for (int i = 0; i < 4; i++) ab[tid + i * 256] = e[i] * inv * Bm[tid + i * 256];
}

// ----------- h[b,d,s] = sum_l xn*ab  (tf32 mma, 128x64 tile, split-K=4) --------------
__global__ __launch_bounds__(256) void k_gemm_h() {
    __shared__ uint32_t As[128][20];
    __shared__ uint32_t Bs[64][17];
    int b = blockIdx.x, m0 = blockIdx.y * 128, kc = blockIdx.z;
    int tid = threadIdx.x, lane = tid & 31, wid = tid >> 5;
    int wm = (wid & 3) * 32, wn = (wid >> 2) * 32;
    int g = lane >> 2, tg = lane & 3;
    const float* Ap = g_xn + (size_t)b * D * L;
    const float* Bp = g_ab + (size_t)b * S * L;

    int mA = tid >> 1, lhA = tid & 1;
    int nB = tid >> 2, kqB = tid & 3;

    float acc[2][4][4] = {};
    float4 ra0, ra1, rb;
    int kbase = kc * 256;
    ra0 = *(const float4*)&Ap[(size_t)(m0 + mA) * L + kbase + lhA * 8];
    ra1 = *(const float4*)&Ap[(size_t)(m0 + mA) * L + kbase + lhA * 8 + 4];
    rb  = *(const float4*)&Bp[(size_t)nB * L + kbase + kqB * 4];

    for (int it = 0; it < 16; it++) {
        *(uint4*)&As[mA][lhA * 8] =
            make_uint4(f2tf32(ra0.x), f2tf32(ra0.y), f2tf32(ra0.z), f2tf32(ra0.w));
        *(uint4*)&As[mA][lhA * 8 + 4] =
            make_uint4(f2tf32(ra1.x), f2tf32(ra1.y), f2tf32(ra1.z), f2tf32(ra1.w));
        Bs[nB][kqB * 4 + 0] = f2tf32(rb.x); Bs[nB][kqB * 4 + 1] = f2tf32(rb.y);
        Bs[nB][kqB * 4 + 2] = f2tf32(rb.z); Bs[nB][kqB * 4 + 3] = f2tf32(rb.w);
        __syncthreads();
        if (it + 1 < 16) {
            int k0 = kbase + (it + 1) * 16;
            ra0 = *(const float4*)&Ap[(size_t)(m0 + mA) * L + k0 + lhA * 8];
            ra1 = *(const float4*)&Ap[(size_t)(m0 + mA) * L + k0 + lhA * 8 + 4];
            rb  = *(const float4*)&Bp[(size_t)nB * L + k0 + kqB * 4];
        }
#pragma unroll
        for (int ks = 0; ks < 16; ks += 8) {
            uint32_t af[2][4], bf[4][2];
#pragma unroll
            for (int mt = 0; mt < 2; mt++) {
                int r = wm + mt * 16 + g;
                af[mt][0] = As[r][ks + tg];     af[mt][1] = As[r + 8][ks + tg];
                af[mt][2] = As[r][ks + 4 + tg]; af[mt][3] = As[r + 8][ks + 4 + tg];
            }
#pragma unroll
            for (int nt = 0; nt < 4; nt++) {
                int c = wn + nt * 8 + g;
                bf[nt][0] = Bs[c][ks + tg]; bf[nt][1] = Bs[c][ks + 4 + tg];
            }
#pragma unroll
            for (int mt = 0; mt < 2; mt++)
#pragma unroll
                for (int nt = 0; nt < 4; nt++)
                    mma_tf32(acc[mt][nt], af[mt][0], af[mt][1], af[mt][2], af[mt][3],
                             bf[nt][0], bf[nt][1]);
        }
        __syncthreads();
    }
    float* Cp = g_h + (size_t)b * D * S;
#pragma unroll
    for (int mt = 0; mt < 2; mt++)
#pragma unroll
        for (int h = 0; h < 2; h++) {
            int row = m0 + wm + mt * 16 + g + h * 8;
#pragma unroll
            for (int nt = 0; nt < 4; nt++) {
                int col = wn + nt * 8 + tg * 2;
                atomicAdd(&Cp[(size_t)row * S + col],     acc[mt][nt][h * 2]);
                atomicAdd(&Cp[(size_t)row * S + col + 1], acc[mt][nt][h * 2 + 1]);
            }
        }
}

// ------------------------- h2 = silu(hproj @ h) -> out_h -----------------------------
__global__ void k_hproj(const float* __restrict__ Wp, float* __restrict__ outh) {
    __shared__ float As[8][68], Bs[8][68];
    int b = blockIdx.x, m0 = blockIdx.y * 64;
    int tid = threadIdx.x, tx = tid & 15, ty = tid >> 4;
    const float* Bp = g_h + (size_t)b * D * S;
    float acc[4][4] = {};
    for (int k0 = 0; k0 < 384; k0 += 8) {
        for (int p = 0; p < 2; p++) {
            int idx = tid + p * 256; int mm = idx >> 3, kk = idx & 7;
            As[kk][mm] = Wp[(size_t)(m0 + mm) * 384 + k0 + kk];
        }
        for (int p = 0; p < 2; p++) {
            int idx = tid + p * 256; int kk = idx >> 6, nn = idx & 63;
            Bs[kk][nn] = Bp[(size_t)(k0 + kk) * S + nn];
        }
        __syncthreads();
#pragma unroll
        for (int k = 0; k < 8; k++) {
            float a[4], bv[4];
#pragma unroll
            for (int i = 0; i < 4; i++) a[i] = As[k][ty + i * 16];
#pragma unroll
            for (int j = 0; j < 4; j++) bv[j] = Bs[k][tx + j * 16];
#pragma unroll
            for (int i = 0; i < 4; i++)
#pragma unroll
                for (int j = 0; j < 4; j++) acc[i][j] += a[i] * bv[j];
        }
        __syncthreads();
    }
    float* Cp = outh + (size_t)b * D * S;
    for (int i = 0; i < 4; i++)
        for (int j = 0; j < 4; j++) {
            float x = acc[i][j];
            Cp[(size_t)(m0 + ty + i * 16) * S + tx + j * 16] = x / (1.f + __expf(-x));
        }
}

// ------------- x2 = x1 + h2 @ Cm  (tf32 mma, 128x128 tiles, K=64) --------------------
__global__ __launch_bounds__(256) void k_gemm_y(const float* __restrict__ outh) {
    __shared__ uint32_t As[128][20];
    __shared__ uint32_t Bs[16][132];
    int b = blockIdx.x, m0 = blockIdx.y * 128, n0 = blockIdx.z * 128;
    int tid = threadIdx.x, lane = tid & 31, wid = tid >> 5;
    int wm = (wid & 1) * 64, wn = (wid >> 1) * 32;
    int g = lane >> 2, tg = lane & 3;
    const float* Ap = outh + (size_t)b * D * S;
    const float* Bp = g_bcdt2 + ((size_t)b * C3 + S) * L;

    int mA = tid >> 1, lhA = tid & 1;
    int nB = (tid & 31) * 4, kB = tid >> 5;

    float acc[4][4][4] = {};
    float4 ra0, ra1, rb0, rb1;
    ra0 = *(const float4*)&Ap[(size_t)(m0 + mA) * S + lhA * 8];
    ra1 = *(const float4*)&Ap[(size_t)(m0 + mA) * S + lhA * 8 + 4];
    rb0 = *(const float4*)&Bp[(size_t)kB * L + n0 + nB];
    rb1 = *(const float4*)&Bp[(size_t)(kB + 8) * L + n0 + nB];

    for (int it = 0; it < 4; it++) {
        *(uint4*)&As[mA][lhA * 8] =
            make_uint4(f2tf32(ra0.x), f2tf32(ra0.y), f2tf32(ra0.z), f2tf32(ra0.w));
        *(uint4*)&As[mA][lhA * 8 + 4] =
            make_uint4(f2tf32(ra1.x), f2tf32(ra1.y), f2tf32(ra1.z), f2tf32(ra1.w));
        *(uint4*)&Bs[kB][nB] =
            make_uint4(f2tf32(rb0.x), f2tf32(rb0.y), f2tf32(rb0.z), f2tf32(rb0.w));
        *(uint4*)&Bs[kB + 8][nB] =
            make_uint4(f2tf32(rb1.x), f2tf32(rb1.y), f2tf32(rb1.z), f2tf32(rb1.w));
        __syncthreads();
        if (it + 1 < 4) {
            int k0 = (it + 1) * 16;
            ra0 = *(const float4*)&Ap[(size_t)(m0 + mA) * S + k0 + lhA * 8];
            ra1 = *(const float4*)&Ap[(size_t)(m0 + mA) * S + k0 + lhA * 8 + 4];
            rb0 = *(const float4*)&Bp[(size_t)(k0 + kB) * L + n0 + nB];
            rb1 = *(const float4*)&Bp[(size_t)(k0 + kB + 8) * L + n0 + nB];
        }
#pragma unroll
        for (int ks = 0; ks < 16; ks += 8) {
            uint32_t af[4][4], bf[4][2];
#pragma unroll
            for (int mt = 0; mt < 4; mt++) {
                int r = wm + mt * 16 + g;
                af[mt][0] = As[r][ks + tg];     af[mt][1] = As[r + 8][ks + tg];
                af[mt][2] = As[r][ks + 4 + tg]; af[mt][3] = As[r + 8][ks + 4 + tg];
            }
#pragma unroll
            for (int nt = 0; nt < 4; nt++) {
                int c = wn + nt * 8 + g;
                bf[nt][0] = Bs[ks + tg][c]; bf[nt][1] = Bs[ks + 4 + tg][c];
            }
#pragma unroll
            for (int mt = 0; mt < 4; mt++)
#pragma unroll
                for (int nt = 0; nt < 4; nt++)
                    mma_tf32(acc[mt][nt], af[mt][0], af[mt][1], af[mt][2], af[mt][3],
                             bf[nt][0], bf[nt][1]);
        }
        __syncthreads();
    }
#pragma unroll
    for (int mt = 0; mt < 4; mt++)
#pragma unroll
        for (int h = 0; h < 2; h++) {
            int row = m0 + wm + mt * 16 + g + h * 8;
#pragma unroll
            for (int nt = 0; nt < 4; nt++) {
                int col = n0 + wn + nt * 8 + tg * 2;
                size_t o = (size_t)b * D * L + (size_t)row * L + col;
                g_x2[o]     = g_x1[o]     + acc[mt][nt][h * 2];
                g_x2[o + 1] = g_x1[o + 1] + acc[mt][nt][h * 2 + 1];
            }
        }
}

// ------------------------- NCHW -> token-major transpose (fp32 + bf16) ---------------
__global__ void k_transpose(const float* __restrict__ xin) {
    __shared__ float s[32][33];
    int b = blockIdx.x, d0 = blockIdx.y * 32, l0 = blockIdx.z * 32;
    int c = threadIdx.x & 31, r0 = threadIdx.x >> 5;
    for (int i = 0; i < 32; i += 8)
        s[r0 + i][c] = xin[((size_t)b * D + d0 + r0 + i) * L + l0 + c];
    __syncthreads();
    for (int i = 0; i < 32; i += 8) {
        float v = s[c][r0 + i];
        size_t o = ((size_t)b * L + l0 + r0 + i) * D + d0 + c;
        g_xT[o] = v;
        g_xTb[o] = __float2bfloat16(v);
    }
}

// ------------------------- router (warp per token, coalesced) ------------------------
__global__ void k_route(const float* __restrict__ gw, const float* __restrict__ gb) {
    __shared__ float sg[E * D];
    int tid = threadIdx.x, lane = tid & 31, wid = tid >> 5;
    for (int i = tid; i < E * D; i += 256) sg[i] = gw[i];
    __syncthreads();
    int n = blockIdx.x * 8 + wid;
    const float* t = g_xT + (size_t)n * D;
    float lg[E] = {};
#pragma unroll
    for (int j = 0; j < 12; j++) {
        float x = t[lane + j * 32];
        int d = lane + j * 32;
#pragma unroll
        for (int e = 0; e < E; e++) lg[e] += sg[e * D + d] * x;
    }
#pragma unroll
    for (int e = 0; e < E; e++) {
        float v = lg[e];
#pragma unroll
        for (int o = 16; o > 0; o >>= 1) v += __shfl_xor_sync(0xffffffff, v, o);
        lg[e] = v;
    }
    if (lane == 0) {
#pragma unroll
        for (int e = 0; e < E; e++) lg[e] += gb[e];
        int i0 = 0; float v0 = lg[0];
#pragma unroll
        for (int e = 1; e < E; e++) if (lg[e] > v0) { v0 = lg[e]; i0 = e; }
        int i1 = -1; float v1 = -1e30f;
#pragma unroll
        for (int e = 0; e < E; e++) if (e != i0 && lg[e] > v1) { v1 = lg[e]; i1 = e; }
        float p0 = 1.f / (1.f + __expf(v1 - v0));
        g_topk_idx[n * 2] = i0; g_topk_idx[n * 2 + 1] = i1;
        g_topk_w[n * 2] = p0;   g_topk_w[n * 2 + 1] = 1.f - p0;
        atomicAdd(&g_cnt[i0], 1); atomicAdd(&g_cnt[i1], 1);
    }
}

__global__ void k_offsets() {
    int off = 0;
    for (int e = 0; e < E; e++) {
        g_off[e] = off;
        off += (g_cnt[e] + 127) & ~127;
        g_cnt2[e] = 0;
    }
    g_off[E] = off;
}

__global__ void k_scatter() {
    int n = blockIdx.x * 256 + threadIdx.x;
#pragma unroll
    for (int k = 0; k < 2; k++) {
        int e = g_topk_idx[n * 2 + k];
        int pos = g_off[e] + atomicAdd(&g_cnt2[e], 1);
        g_perm[pos] = n;
        g_wgt[pos] = g_topk_w[n * 2 + k];
    }
}

// ------------------- MoE GEMM1 (bf16 mma + cp.async 3-stage, k-tile 64) --------------
// Tile rows pitch = 72 elems (144B) -> ldmatrix + cp.async conflict-free.
// smem bytes: A @0 (3*18432), B1 @55296 (3*18432), B3 @110592 (3*18432), perm @165888.
constexpr int MT_BYTES = 18432;       // 128 rows * 144B
constexpr int MOE1_SMEM = 166400;
constexpr int MOE2_SMEM = 110592;

__global__ __launch_bounds__(256) void k_moe1(
        const float* __restrict__ B1, const float* __restrict__ B3) {
    extern __shared__ char sm[];
    int* sperm = (int*)(sm + 165888);

    int e = blockIdx.x;
    int cnt = g_cnt[e];
    int m0 = blockIdx.y * 128;
    if (m0 >= cnt) return;
    int base = g_off[e];
    int n0 = blockIdx.z * 128;

    int tid = threadIdx.x, lane = tid & 31, wid = tid >> 5;
    int wm = (wid & 1) * 64, wn = (wid >> 1) * 32;
    int g = lane >> 2, tg = lane & 3;

    if (tid < 128) sperm[tid] = g_perm[base + m0 + tid];
    __syncthreads();

    uint32_t smBase = (uint32_t)__cvta_generic_to_shared(sm);
    uint32_t aFrag = (wm + (lane & 15)) * 144 + (lane >> 4) * 16;
    uint32_t bFrag = (wn + (lane >> 4) * 8 + (lane & 7)) * 144 + ((lane >> 3) & 1) * 16;

    constexpr int KT = D / 64;   // 6
    auto issue = [&](int t) {
        if (t < KT) {
            int k0 = t * 64;
            uint32_t off = (uint32_t)(t % 3) * MT_BYTES;
#pragma unroll
            for (int j = 0; j < 4; j++) {
                int li = tid + j * 256;          // 0..1023: row = li>>3, lc = li&7
                int row = li >> 3, lc = li & 7;
                uint32_t so = off + row * 144 + lc * 16;
                cpa16(smBase + so, g_xTb + (size_t)sperm[row] * D + k0 + lc * 8);
                size_t wgo = ((size_t)e * HID + n0 + row) * D + k0 + lc * 8;
                cpa16(smBase + 55296 + so,  g_w1b + wgo);
                cpa16(smBase + 110592 + so, g_w3b + wgo);
            }
        }
        cp_commit();
    };

    float acc1[4][4][4] = {}, acc3[4][4][4] = {};
    issue(0); issue(1);

    for (int it = 0; it < KT; it++) {
        cp_wait1();
        __syncthreads();
        issue(it + 2);
        uint32_t st = (uint32_t)(it % 3) * MT_BYTES;
#pragma unroll
        for (int ks = 0; ks < 4; ks++) {
            uint32_t af[4][4], bf1[2][4], bf3[2][4];
#pragma unroll
            for (int mt = 0; mt < 4; mt++)
                ldm_x4(af[mt], smBase + st + aFrag + mt * 2304 + ks * 32);
#pragma unroll
            for (int np = 0; np < 2; np++) {
                ldm_x4(bf1[np], smBase + 55296 + st + bFrag + np * 2304 + ks * 32);
                ldm_x4(bf3[np], smBase + 110592 + st + bFrag + np * 2304 + ks * 32);
            }
#pragma unroll
            for (int mt = 0; mt < 4; mt++)
#pragma unroll
                for (int nt = 0; nt < 4; nt++) {
                    int np = nt >> 1, hf = (nt & 1) * 2;
                    mma_bf16(acc1[mt][nt], af[mt], bf1[np][hf], bf1[np][hf + 1]);
                    mma_bf16(acc3[mt][nt], af[mt], bf3[np][hf], bf3[np][hf + 1]);
                }
        }
    }

#pragma unroll
    for (int mt = 0; mt < 4; mt++) {
#pragma unroll
        for (int nt = 0; nt < 4; nt++) {
            int cl = n0 + wn + nt * 8 + tg * 2;
            float bb1a = B1[e * HID + cl], bb1b = B1[e * HID + cl + 1];
            float bb3a = B3[e * HID + cl], bb3b = B3[e * HID + cl + 1];
#pragma unroll
            for (int h = 0; h < 2; h++) {
                int rl = wm + mt * 16 + g + h * 8;
                float x1a = acc1[mt][nt][h * 2] + bb1a;
                float x1b = acc1[mt][nt][h * 2 + 1] + bb1b;
                float x3a = acc3[mt][nt][h * 2] + bb3a;
                float x3b = acc3[mt][nt][h * 2 + 1] + bb3b;
                float oa = (x1a / (1.f + __expf(-x1a))) * x3a;
                float ob = (x1b / (1.f + __expf(-x1b))) * x3b;
                *(__nv_bfloat162*)&g_heb[(size_t)(base + m0 + rl) * HID + cl] =
                    __float22bfloat162_rn(make_float2(oa, ob));
            }
        }
    }
}

// ------------------- MoE GEMM2 (bf16 mma + cp.async 3-stage, k-tile 64) --------------
// smem bytes: A @0 (3*18432), B @55296 (3*18432)
__global__ __launch_bounds__(256) void k_moe2(
        const float* __restrict__ b2v, float* __restrict__ outx) {
    extern __shared__ char sm[];

    int e = blockIdx.x;
    int cnt = g_cnt[e];
    int m0 = blockIdx.y * 128;
    if (m0 >= cnt) return;
    int base = g_off[e];
    int n0 = blockIdx.z * 128;

    int tid = threadIdx.x, lane = tid & 31, wid = tid >> 5;
    int wm = (wid & 1) * 64, wn = (wid >> 1) * 32;
    int g = lane >> 2, tg = lane & 3;

    uint32_t smBase = (uint32_t)__cvta_generic_to_shared(sm);
    uint32_t aFrag = (wm + (lane & 15)) * 144 + (lane >> 4) * 16;
    uint32_t bFrag = (wn + (lane >> 4) * 8 + (lane & 7)) * 144 + ((lane >> 3) & 1) * 16;

    constexpr int KT = HID / 64;  // 12
    auto issue = [&](int t) {
        if (t < KT) {
            int k0 = t * 64;
            uint32_t off = (uint32_t)(t % 3) * MT_BYTES;
#pragma unroll
            for (int j = 0; j < 4; j++) {
                int li = tid + j * 256;
                int row = li >> 3, lc = li & 7;
                uint32_t so = off + row * 144 + lc * 16;
                cpa16(smBase + so,
                      g_heb + (size_t)(base + m0 + row) * HID + k0 + lc * 8);
                cpa16(smBase + 55296 + so,
                      g_w2b + ((size_t)e * D + n0 + row) * HID + k0 + lc * 8);
            }
        }
        cp_commit();
    };

    float acc[4][4][4] = {};
    issue(0); issue(1);

    for (int it = 0; it < KT; it++) {
        cp_wait1();
        __syncthreads();
        issue(it + 2);
        uint32_t st = (uint32_t)(it % 3) * MT_BYTES;
#pragma unroll
        for (int ks = 0; ks < 4; ks++) {
            uint32_t af[4][4], bf[2][4];
#pragma unroll
            for (int mt = 0; mt < 4; mt++)
                ldm_x4(af[mt], smBase + st + aFrag + mt * 2304 + ks * 32);
#pragma unroll
            for (int np = 0; np < 2; np++)
                ldm_x4(bf[np], smBase + 55296 + st + bFrag + np * 2304 + ks * 32);
#pragma unroll
            for (int mt = 0; mt < 4; mt++)
#pragma unroll
                for (int nt = 0; nt < 4; nt++) {
                    int np = nt >> 1, hf = (nt & 1) * 2;
                    mma_bf16(acc[mt][nt], af[mt], bf[np][hf], bf[np][hf + 1]);
                }
        }
    }

#pragma unroll
    for (int mt = 0; mt < 4; mt++) {
#pragma unroll
        for (int h = 0; h < 2; h++) {
            int rl = wm + mt * 16 + g + h * 8;
            float w = g_wgt[base + m0 + rl];
            if (w == 0.f) continue;
            int n = g_perm[base + m0 + rl];
            int b = n >> 10, l = n & 1023;
#pragma unroll
            for (int nt = 0; nt < 4; nt++) {
                int cl = n0 + wn + nt * 8 + tg * 2;
                float v0 = (acc[mt][nt][h * 2] + b2v[e * D + cl]) * w;
                float v1 = (acc[mt][nt][h * 2 + 1] + b2v[e * D + cl + 1]) * w;
                atomicAdd(&outx[((size_t)b * D + cl) * L + l], v0);
                atomicAdd(&outx[((size_t)b * D + cl + 1) * L + l], v1);
            }
        }
    }
}

// ------------------------- launch ---------------------------------------------------
extern "C" void kernel_launch(void* const* d_in, const int* in_sizes, int n_in,
                              void* d_out, int out_size) {
    const float* x      = (const float*)d_in[0];
    const float* dw1_w  = (const float*)d_in[1];
    const float* bn1_g  = (const float*)d_in[2];
    const float* bn1_b  = (const float*)d_in[3];
    const float* bn1_m  = (const float*)d_in[4];
    const float* bn1_v  = (const float*)d_in[5];
    const float* dw2_w  = (const float*)d_in[6];
    const float* bn2_g  = (const float*)d_in[7];
    const float* bn2_b  = (const float*)d_in[8];
    const float* bn2_m  = (const float*)d_in[9];
    const float* bn2_v  = (const float*)d_in[10];
    const float* ln_w   = (const float*)d_in[11];
    const float* ln_b   = (const float*)d_in[12];
    const float* bcdt_w = (const float*)d_in[13];
    const float* dws_w  = (const float*)d_in[14];
    const float* hproj_w= (const float*)d_in[15];
    // d_in[16] = A (cancels inside softmax over L)
    const float* gate_w = (const float*)d_in[17];
    const float* gate_b = (const float*)d_in[18];
    const float* w1     = (const float*)d_in[19];
    const float* b1     = (const float*)d_in[20];
    const float* w2     = (const float*)d_in[21];
    const float* b2     = (const float*)d_in[22];
    const float* w3     = (const float*)d_in[23];
    const float* b3     = (const float*)d_in[24];

    float* out_x = (float*)d_out;
    float* out_h = out_x + (size_t)Bsz * D * L;

    float* px1;    cudaGetSymbolAddress((void**)&px1, g_x1);
    float* pbcdt;  cudaGetSymbolAddress((void**)&pbcdt, g_bcdt);
    float* pbcdt2; cudaGetSymbolAddress((void**)&pbcdt2, g_bcdt2);
    float* px2;    cudaGetSymbolAddress((void**)&px2, g_x2);

    static bool attr_set = false;
    if (!attr_set) {
        cudaFuncSetAttribute(k_moe1, cudaFuncAttributeMaxDynamicSharedMemorySize, MOE1_SMEM);
        cudaFuncSetAttribute(k_moe2, cudaFuncAttributeMaxDynamicSharedMemorySize, MOE2_SMEM);
        attr_set = true;
    }

    // init + weight conversions in one launch
    k_prep<<<2304, 256>>>(w1, w3, w2);

    // x1 = x + bn1(dw1(x))
    k_dwconv<<<Bsz * D, 256>>>(x, dw1_w, bn1_g, bn1_b, bn1_m, bn1_v, px1, D, 1);
    // xn = LN(x1)
    k_ln<<<NTOK / 256, 256>>>(ln_w, ln_b);
    // bcdt (tf32, conflict-free smem)
    k_gemm_bcdt<<<dim3(Bsz, 3, 8), 256>>>(bcdt_w);
    k_dwconv<<<Bsz * C3, 256>>>(pbcdt, dws_w, nullptr, nullptr, nullptr, nullptr, pbcdt2, C3, 0);
    k_softmax<<<Bsz * S, 256>>>();
    // h = xn @ (Am*Bm)^T (tf32, split-K=4)
    k_gemm_h<<<dim3(Bsz, 3, 4), 256>>>();
    // h2 = silu(hproj @ h) -> second output
    k_hproj<<<dim3(Bsz, 6, 1), 256>>>(hproj_w, out_h);
    // x2 = x1 + h2 @ Cm (tf32)
    k_gemm_y<<<dim3(Bsz, 3, 8), 256>>>(out_h);
    // x3 = x2 + bn2(dw2(x2)) -> first output (MoE adds on top)
    k_dwconv<<<Bsz * D, 256>>>(px2, dw2_w, bn2_g, bn2_b, bn2_m, bn2_v, out_x, D, 1);
    // tokens (fp32 + bf16)
    k_transpose<<<dim3(Bsz, 12, 32), 256>>>(out_x);
    // routing (warp per token)
    k_route<<<NTOK / 8, 256>>>(gate_w, gate_b);
    k_offsets<<<1, 1>>>();
    k_scatter<<<NTOK / 256, 256>>>();
    // MoE (bf16 mma.sync, cp.async 3-stage, k-tile 64)
    k_moe1<<<dim3(E, 128, 6), 256, MOE1_SMEM>>>(b1, b3);
    k_moe2<<<dim3(E, 128, 3), 256, MOE2_SMEM>>>(b2, out_x);
}